// round 2
// baseline (speedup 1.0000x reference)
#include <cuda_runtime.h>
#include <cuda_bf16.h>
#include <math.h>

#define BATCH 2
#define SEQ   2048
#define DIN   2048
#define NHEAD 16
#define HDIM  128
#define HPAIR (HDIM/2)          // 64 rope pairs per head
#define MROWS (BATCH*SEQ)       // 4096
#define QKVN  (3*DIN)           // 6144

// ---------------- scratch (device globals; no allocs allowed) ----------------
__device__ float g_qkv[(size_t)MROWS * QKVN];   // 96 MB
__device__ float g_att[(size_t)MROWS * DIN];    // 32 MB
__device__ float g_cos[SEQ * HPAIR];
__device__ float g_sin[SEQ * HPAIR];

// ---------------- rope freq table ----------------
__global__ void freq_kernel() {
    int t = blockIdx.x * blockDim.x + threadIdx.x;
    if (t >= SEQ * HPAIR) return;
    int s = t >> 6;          // seq pos
    int p = t & 63;          // pair index
    float inv = (float)(1.0 / pow(10000.0, (double)(2 * p) / (double)HDIM));
    float ang = (float)s * inv;
    float sn, cs;
    sincosf(ang, &sn, &cs);
    g_cos[t] = cs;
    g_sin[t] = sn;
}

// ---------------- rope applied to q and k in qkv buffer ----------------
__global__ void rope_kernel(float* __restrict__ qkv) {
    int t = blockIdx.x * blockDim.x + threadIdx.x;
    if (t >= BATCH * SEQ * NHEAD * HPAIR) return;
    int p = t & 63;
    int h = (t >> 6) & (NHEAD - 1);
    int s = (t >> 10) & (SEQ - 1);
    int b = t >> 21;
    int row = b * SEQ + s;
    float c  = g_cos[s * HPAIR + p];
    float sn = g_sin[s * HPAIR + p];
    size_t base = (size_t)row * QKVN + h * HDIM + 2 * p;
    // q
    float q1 = qkv[base], q2 = qkv[base + 1];
    qkv[base]     = q1 * c - q2 * sn;
    qkv[base + 1] = q1 * sn + q2 * c;
    // k
    size_t kb = base + DIN;
    float k1 = qkv[kb], k2 = qkv[kb + 1];
    qkv[kb]     = k1 * c - k2 * sn;
    qkv[kb + 1] = k1 * sn + k2 * c;
}

// ---------------- fp32 tiled GEMM: C[M,N] = A[M,K] * B[K,N], row-major ----------------
// 128x128 tile, BK=16, 256 threads, 8x8 per-thread micro-tile.
__global__ __launch_bounds__(256) void sgemm128(
    const float* __restrict__ A, const float* __restrict__ B,
    float* __restrict__ C, int M, int N, int K)
{
    __shared__ float As[16][128];
    __shared__ float Bs[16][128];

    int t  = threadIdx.x;
    int tx = t & 15;          // n direction
    int ty = t >> 4;          // m direction
    int tn0 = tx * 8;
    int tm0 = ty * 8;

    const float* Ab = A + (size_t)blockIdx.y * 128 * K;
    const float* Bb = B + (size_t)blockIdx.x * 128;

    float acc[8][8];
    #pragma unroll
    for (int i = 0; i < 8; ++i)
        #pragma unroll
        for (int j = 0; j < 8; ++j) acc[i][j] = 0.f;

    for (int k0 = 0; k0 < K; k0 += 16) {
        // A tile: 128 rows x 16 cols -> store transposed As[k][m]
        #pragma unroll
        for (int i = 0; i < 2; ++i) {
            int f   = t * 2 + i;          // 0..511 float4s
            int row = f >> 2;
            int c4  = f & 3;
            float4 v = *(const float4*)(Ab + (size_t)row * K + k0 + c4 * 4);
            As[c4 * 4 + 0][row] = v.x;
            As[c4 * 4 + 1][row] = v.y;
            As[c4 * 4 + 2][row] = v.z;
            As[c4 * 4 + 3][row] = v.w;
        }
        // B tile: 16 rows x 128 cols -> direct
        #pragma unroll
        for (int i = 0; i < 2; ++i) {
            int f   = t * 2 + i;
            int row = f >> 5;
            int c4  = f & 31;
            *(float4*)(&Bs[row][c4 * 4]) =
                *(const float4*)(Bb + (size_t)(k0 + row) * N + c4 * 4);
        }
        __syncthreads();

        #pragma unroll
        for (int k = 0; k < 16; ++k) {
            float a[8], b[8];
            *(float4*)(a)     = *(float4*)(&As[k][tm0]);
            *(float4*)(a + 4) = *(float4*)(&As[k][tm0 + 4]);
            *(float4*)(b)     = *(float4*)(&Bs[k][tn0]);
            *(float4*)(b + 4) = *(float4*)(&Bs[k][tn0 + 4]);
            #pragma unroll
            for (int i = 0; i < 8; ++i)
                #pragma unroll
                for (int j = 0; j < 8; ++j)
                    acc[i][j] = fmaf(a[i], b[j], acc[i][j]);
        }
        __syncthreads();
    }

    float* Cb = C + (size_t)(blockIdx.y * 128 + tm0) * N + blockIdx.x * 128 + tn0;
    #pragma unroll
    for (int i = 0; i < 8; ++i) {
        *(float4*)(Cb + (size_t)i * N)     = make_float4(acc[i][0], acc[i][1], acc[i][2], acc[i][3]);
        *(float4*)(Cb + (size_t)i * N + 4) = make_float4(acc[i][4], acc[i][5], acc[i][6], acc[i][7]);
    }
}

// ---------------- causal flash attention, fp32 ----------------
// grid: (SEQ/64, NHEAD, BATCH), 256 threads (16x16).
// Q tile 64x128, K tile 64x128, online softmax, O accum in registers.
// smem: Qs[128][64] Ks[128][64] Vs[64][128] Ps[64][68]
__global__ __launch_bounds__(256) void attn_kernel(
    const float* __restrict__ qkv, float* __restrict__ out)
{
    extern __shared__ float smem[];
    float* Qs = smem;                 // [d][q]  128*64
    float* Ks = Qs + 128 * 64;        // [d][k]  128*64
    float* Vs = Ks + 128 * 64;        // [k][d]  64*128
    float* Ps = Vs + 64 * 128;        // [k][q]  64*68 (padded)

    const int qt = blockIdx.x;
    const int h  = blockIdx.y;
    const int b  = blockIdx.z;
    const int t  = threadIdx.x;
    const int tx = t & 15;            // k (for S) / d-group (for O)
    const int ty = t >> 4;            // q

    const float* base = qkv + (size_t)b * SEQ * QKVN + h * HDIM;

    // load Q tile transposed: Qs[d][q]
    for (int i = t; i < 64 * 32; i += 256) {        // 2048 float4
        int r  = i >> 5;                            // q row 0..63
        int c4 = i & 31;                            // d float4 0..31
        float4 v = *(const float4*)(base + (size_t)(qt * 64 + r) * QKVN + c4 * 4);
        Qs[(c4 * 4 + 0) * 64 + r] = v.x;
        Qs[(c4 * 4 + 1) * 64 + r] = v.y;
        Qs[(c4 * 4 + 2) * 64 + r] = v.z;
        Qs[(c4 * 4 + 3) * 64 + r] = v.w;
    }

    float o[4][8];
    float m[4], l[4];
    #pragma unroll
    for (int qi = 0; qi < 4; ++qi) {
        m[qi] = -INFINITY; l[qi] = 0.f;
        #pragma unroll
        for (int dj = 0; dj < 8; ++dj) o[qi][dj] = 0.f;
    }

    const float scale = 0.08838834764831845f;   // 1/sqrt(128)

    for (int kt = 0; kt <= qt; ++kt) {
        __syncthreads();   // prior PV reads done before K/V overwrite (also covers Q load)
        // load K (transposed) and V (direct)
        for (int i = t; i < 64 * 32; i += 256) {
            int r  = i >> 5;
            int c4 = i & 31;
            const float* kp = base + DIN + (size_t)(kt * 64 + r) * QKVN + c4 * 4;
            float4 kv = *(const float4*)kp;
            Ks[(c4 * 4 + 0) * 64 + r] = kv.x;
            Ks[(c4 * 4 + 1) * 64 + r] = kv.y;
            Ks[(c4 * 4 + 2) * 64 + r] = kv.z;
            Ks[(c4 * 4 + 3) * 64 + r] = kv.w;
            float4 vv = *(const float4*)(kp + DIN);
            *(float4*)(&Vs[r * 128 + c4 * 4]) = vv;
        }
        __syncthreads();

        // S = Q K^T  (each thread: 4q x 4k)
        float s[4][4];
        #pragma unroll
        for (int qi = 0; qi < 4; ++qi)
            #pragma unroll
            for (int kj = 0; kj < 4; ++kj) s[qi][kj] = 0.f;

        #pragma unroll 4
        for (int d = 0; d < 128; ++d) {
            float qv[4], kv[4];
            *(float4*)qv = *(float4*)(&Qs[d * 64 + ty * 4]);
            *(float4*)kv = *(float4*)(&Ks[d * 64 + tx * 4]);
            #pragma unroll
            for (int qi = 0; qi < 4; ++qi)
                #pragma unroll
                for (int kj = 0; kj < 4; ++kj)
                    s[qi][kj] = fmaf(qv[qi], kv[kj], s[qi][kj]);
        }

        // scale + causal mask
        #pragma unroll
        for (int qi = 0; qi < 4; ++qi)
            #pragma unroll
            for (int kj = 0; kj < 4; ++kj) {
                float v = s[qi][kj] * scale;
                if (kt == qt && (tx * 4 + kj) > (ty * 4 + qi)) v = -INFINITY;
                s[qi][kj] = v;
            }

        // online softmax
        #pragma unroll
        for (int qi = 0; qi < 4; ++qi) {
            float rm = fmaxf(fmaxf(s[qi][0], s[qi][1]), fmaxf(s[qi][2], s[qi][3]));
            #pragma unroll
            for (int w = 1; w < 16; w <<= 1)
                rm = fmaxf(rm, __shfl_xor_sync(0xffffffffu, rm, w));
            float mn   = fmaxf(m[qi], rm);
            float corr = expf(m[qi] - mn);
            float rs = 0.f;
            #pragma unroll
            for (int kj = 0; kj < 4; ++kj) {
                float p = expf(s[qi][kj] - mn);
                s[qi][kj] = p;
                rs += p;
            }
            #pragma unroll
            for (int w = 1; w < 16; w <<= 1)
                rs += __shfl_xor_sync(0xffffffffu, rs, w);
            l[qi] = l[qi] * corr + rs;
            m[qi] = mn;
            #pragma unroll
            for (int dj = 0; dj < 8; ++dj) o[qi][dj] *= corr;
        }

        // write P transposed: Ps[k][q]
        #pragma unroll
        for (int kj = 0; kj < 4; ++kj)
            *(float4*)(&Ps[(tx * 4 + kj) * 68 + ty * 4]) =
                make_float4(s[0][kj], s[1][kj], s[2][kj], s[3][kj]);
        __syncthreads();

        // O += P V   (each thread: 4q x 8d, d0 = tx*8)
        #pragma unroll 4
        for (int kk = 0; kk < 64; ++kk) {
            float pv[4], vv[8];
            *(float4*)pv       = *(float4*)(&Ps[kk * 68 + ty * 4]);
            *(float4*)vv       = *(float4*)(&Vs[kk * 128 + tx * 8]);
            *(float4*)(vv + 4) = *(float4*)(&Vs[kk * 128 + tx * 8 + 4]);
            #pragma unroll
            for (int qi = 0; qi < 4; ++qi)
                #pragma unroll
                for (int dj = 0; dj < 8; ++dj)
                    o[qi][dj] = fmaf(pv[qi], vv[dj], o[qi][dj]);
        }
    }

    // epilogue: normalize and write
    #pragma unroll
    for (int qi = 0; qi < 4; ++qi) {
        float inv = 1.f / l[qi];
        size_t row = (size_t)b * SEQ + qt * 64 + ty * 4 + qi;
        float* op = out + row * DIN + h * HDIM + tx * 8;
        *(float4*)(op)     = make_float4(o[qi][0] * inv, o[qi][1] * inv, o[qi][2] * inv, o[qi][3] * inv);
        *(float4*)(op + 4) = make_float4(o[qi][4] * inv, o[qi][5] * inv, o[qi][6] * inv, o[qi][7] * inv);
    }
}

// ---------------- launch ----------------
extern "C" void kernel_launch(void* const* d_in, const int* in_sizes, int n_in,
                              void* d_out, int out_size)
{
    const float* x     = (const float*)d_in[0];   // [2,2048,2048]
    const float* Wqkv  = (const float*)d_in[1];   // [2048,6144]
    const float* Wproj = (const float*)d_in[2];   // [2048,2048]
    float* out = (float*)d_out;                    // [2,2048,2048]

    float *qkv_ptr, *att_ptr;
    cudaGetSymbolAddress((void**)&qkv_ptr, g_qkv);
    cudaGetSymbolAddress((void**)&att_ptr, g_att);

    // rope tables
    freq_kernel<<<(SEQ * HPAIR + 255) / 256, 256>>>();

    // qkv = x @ Wqkv : [4096,2048]x[2048,6144]
    {
        dim3 grid(QKVN / 128, MROWS / 128);
        sgemm128<<<grid, 256>>>(x, Wqkv, qkv_ptr, MROWS, QKVN, DIN);
    }

    // rope on q,k
    {
        int total = BATCH * SEQ * NHEAD * HPAIR;
        rope_kernel<<<(total + 255) / 256, 256>>>(qkv_ptr);
    }

    // attention
    {
        int smem_bytes = (128 * 64 + 128 * 64 + 64 * 128 + 64 * 68) * sizeof(float);
        cudaFuncSetAttribute(attn_kernel, cudaFuncAttributeMaxDynamicSharedMemorySize, smem_bytes);
        dim3 grid(SEQ / 64, NHEAD, BATCH);
        attn_kernel<<<grid, 256, smem_bytes>>>(qkv_ptr, att_ptr);
    }

    // out = att @ Wproj : [4096,2048]x[2048,2048]
    {
        dim3 grid(DIN / 128, MROWS / 128);
        sgemm128<<<grid, 256>>>(att_ptr, Wproj, out, MROWS, DIN, DIN);
    }
}

// round 3
// speedup vs baseline: 1.0065x; 1.0065x over previous
#include <cuda_runtime.h>
#include <cuda_bf16.h>
#include <math.h>

#define BATCH 2
#define SEQ   2048
#define DIN   2048
#define NHEAD 16
#define HDIM  128
#define HPAIR (HDIM/2)          // 64 rope pairs per head
#define MROWS (BATCH*SEQ)       // 4096
#define QKVN  (3*DIN)           // 6144

// ---------------- scratch (device globals; no allocs allowed) ----------------
__device__ float g_qkv[(size_t)MROWS * QKVN];   // 96 MB
__device__ float g_att[(size_t)MROWS * DIN];    // 32 MB
__device__ float g_cos[SEQ * HPAIR];
__device__ float g_sin[SEQ * HPAIR];

// ---------------- rope freq table ----------------
__global__ void freq_kernel() {
    int t = blockIdx.x * blockDim.x + threadIdx.x;
    if (t >= SEQ * HPAIR) return;
    int s = t >> 6;          // seq pos
    int p = t & 63;          // pair index
    float inv = (float)(1.0 / pow(10000.0, (double)(2 * p) / (double)HDIM));
    float ang = (float)s * inv;
    float sn, cs;
    sincosf(ang, &sn, &cs);
    g_cos[t] = cs;
    g_sin[t] = sn;
}

// ---------------- rope applied to q and k in qkv buffer ----------------
__global__ void rope_kernel(float* __restrict__ qkv) {
    int t = blockIdx.x * blockDim.x + threadIdx.x;
    if (t >= BATCH * SEQ * NHEAD * HPAIR) return;
    int p = t & 63;
    int h = (t >> 6) & (NHEAD - 1);
    int s = (t >> 10) & (SEQ - 1);
    int b = t >> 21;
    int row = b * SEQ + s;
    float c  = g_cos[s * HPAIR + p];
    float sn = g_sin[s * HPAIR + p];
    size_t base = (size_t)row * QKVN + h * HDIM + 2 * p;
    // q
    float q1 = qkv[base], q2 = qkv[base + 1];
    qkv[base]     = q1 * c - q2 * sn;
    qkv[base + 1] = q1 * sn + q2 * c;
    // k
    size_t kb = base + DIN;
    float k1 = qkv[kb], k2 = qkv[kb + 1];
    qkv[kb]     = k1 * c - k2 * sn;
    qkv[kb + 1] = k1 * sn + k2 * c;
}

// ---------------- fp32 tiled GEMM: C[M,N] = A[M,K] * B[K,N], row-major ----------------
// 128x128 tile, BK=16, 256 threads, 8x8 per-thread micro-tile.
__global__ __launch_bounds__(256) void sgemm128(
    const float* __restrict__ A, const float* __restrict__ B,
    float* __restrict__ C, int M, int N, int K)
{
    __shared__ float As[16][128];
    __shared__ float Bs[16][128];

    int t  = threadIdx.x;
    int tx = t & 15;          // n direction
    int ty = t >> 4;          // m direction
    int tn0 = tx * 8;
    int tm0 = ty * 8;

    const float* Ab = A + (size_t)blockIdx.y * 128 * K;
    const float* Bb = B + (size_t)blockIdx.x * 128;

    float acc[8][8];
    #pragma unroll
    for (int i = 0; i < 8; ++i)
        #pragma unroll
        for (int j = 0; j < 8; ++j) acc[i][j] = 0.f;

    for (int k0 = 0; k0 < K; k0 += 16) {
        // A tile: 128 rows x 16 cols -> store transposed As[k][m]
        #pragma unroll
        for (int i = 0; i < 2; ++i) {
            int f   = t * 2 + i;          // 0..511 float4s
            int row = f >> 2;
            int c4  = f & 3;
            float4 v = *(const float4*)(Ab + (size_t)row * K + k0 + c4 * 4);
            As[c4 * 4 + 0][row] = v.x;
            As[c4 * 4 + 1][row] = v.y;
            As[c4 * 4 + 2][row] = v.z;
            As[c4 * 4 + 3][row] = v.w;
        }
        // B tile: 16 rows x 128 cols -> direct
        #pragma unroll
        for (int i = 0; i < 2; ++i) {
            int f   = t * 2 + i;
            int row = f >> 5;
            int c4  = f & 31;
            *(float4*)(&Bs[row][c4 * 4]) =
                *(const float4*)(Bb + (size_t)(k0 + row) * N + c4 * 4);
        }
        __syncthreads();

        #pragma unroll
        for (int k = 0; k < 16; ++k) {
            float a[8], b[8];
            *(float4*)(a)     = *(float4*)(&As[k][tm0]);
            *(float4*)(a + 4) = *(float4*)(&As[k][tm0 + 4]);
            *(float4*)(b)     = *(float4*)(&Bs[k][tn0]);
            *(float4*)(b + 4) = *(float4*)(&Bs[k][tn0 + 4]);
            #pragma unroll
            for (int i = 0; i < 8; ++i)
                #pragma unroll
                for (int j = 0; j < 8; ++j)
                    acc[i][j] = fmaf(a[i], b[j], acc[i][j]);
        }
        __syncthreads();
    }

    float* Cb = C + (size_t)(blockIdx.y * 128 + tm0) * N + blockIdx.x * 128 + tn0;
    #pragma unroll
    for (int i = 0; i < 8; ++i) {
        *(float4*)(Cb + (size_t)i * N)     = make_float4(acc[i][0], acc[i][1], acc[i][2], acc[i][3]);
        *(float4*)(Cb + (size_t)i * N + 4) = make_float4(acc[i][4], acc[i][5], acc[i][6], acc[i][7]);
    }
}

// ---------------- causal flash attention, fp32 ----------------
// grid: (SEQ/64, NHEAD, BATCH), 256 threads (16x16).
// Q tile 64x128, K tile 64x128, online softmax, O accum in registers.
// smem: Qs[128][64] Ks[128][64] Vs[64][128] Ps[64][68]
__global__ __launch_bounds__(256) void attn_kernel(
    const float* __restrict__ qkv, float* __restrict__ out)
{
    extern __shared__ float smem[];
    float* Qs = smem;                 // [d][q]  128*64
    float* Ks = Qs + 128 * 64;        // [d][k]  128*64
    float* Vs = Ks + 128 * 64;        // [k][d]  64*128
    float* Ps = Vs + 64 * 128;        // [k][q]  64*68 (padded)

    const int qt = blockIdx.x;
    const int h  = blockIdx.y;
    const int b  = blockIdx.z;
    const int t  = threadIdx.x;
    const int tx = t & 15;            // k (for S) / d-group (for O)
    const int ty = t >> 4;            // q

    const float* base = qkv + (size_t)b * SEQ * QKVN + h * HDIM;

    // load Q tile transposed: Qs[d][q]
    for (int i = t; i < 64 * 32; i += 256) {        // 2048 float4
        int r  = i >> 5;                            // q row 0..63
        int c4 = i & 31;                            // d float4 0..31
        float4 v = *(const float4*)(base + (size_t)(qt * 64 + r) * QKVN + c4 * 4);
        Qs[(c4 * 4 + 0) * 64 + r] = v.x;
        Qs[(c4 * 4 + 1) * 64 + r] = v.y;
        Qs[(c4 * 4 + 2) * 64 + r] = v.z;
        Qs[(c4 * 4 + 3) * 64 + r] = v.w;
    }

    float o[4][8];
    float m[4], l[4];
    #pragma unroll
    for (int qi = 0; qi < 4; ++qi) {
        m[qi] = -INFINITY; l[qi] = 0.f;
        #pragma unroll
        for (int dj = 0; dj < 8; ++dj) o[qi][dj] = 0.f;
    }

    const float scale = 0.08838834764831845f;   // 1/sqrt(128)

    for (int kt = 0; kt <= qt; ++kt) {
        __syncthreads();   // prior PV reads done before K/V overwrite (also covers Q load)
        // load K (transposed) and V (direct)
        for (int i = t; i < 64 * 32; i += 256) {
            int r  = i >> 5;
            int c4 = i & 31;
            const float* kp = base + DIN + (size_t)(kt * 64 + r) * QKVN + c4 * 4;
            float4 kv = *(const float4*)kp;
            Ks[(c4 * 4 + 0) * 64 + r] = kv.x;
            Ks[(c4 * 4 + 1) * 64 + r] = kv.y;
            Ks[(c4 * 4 + 2) * 64 + r] = kv.z;
            Ks[(c4 * 4 + 3) * 64 + r] = kv.w;
            float4 vv = *(const float4*)(kp + DIN);
            *(float4*)(&Vs[r * 128 + c4 * 4]) = vv;
        }
        __syncthreads();

        // S = Q K^T  (each thread: 4q x 4k)
        float s[4][4];
        #pragma unroll
        for (int qi = 0; qi < 4; ++qi)
            #pragma unroll
            for (int kj = 0; kj < 4; ++kj) s[qi][kj] = 0.f;

        #pragma unroll 4
        for (int d = 0; d < 128; ++d) {
            float qv[4], kv[4];
            *(float4*)qv = *(float4*)(&Qs[d * 64 + ty * 4]);
            *(float4*)kv = *(float4*)(&Ks[d * 64 + tx * 4]);
            #pragma unroll
            for (int qi = 0; qi < 4; ++qi)
                #pragma unroll
                for (int kj = 0; kj < 4; ++kj)
                    s[qi][kj] = fmaf(qv[qi], kv[kj], s[qi][kj]);
        }

        // scale + causal mask
        #pragma unroll
        for (int qi = 0; qi < 4; ++qi)
            #pragma unroll
            for (int kj = 0; kj < 4; ++kj) {
                float v = s[qi][kj] * scale;
                if (kt == qt && (tx * 4 + kj) > (ty * 4 + qi)) v = -INFINITY;
                s[qi][kj] = v;
            }

        // online softmax
        #pragma unroll
        for (int qi = 0; qi < 4; ++qi) {
            float rm = fmaxf(fmaxf(s[qi][0], s[qi][1]), fmaxf(s[qi][2], s[qi][3]));
            #pragma unroll
            for (int w = 1; w < 16; w <<= 1)
                rm = fmaxf(rm, __shfl_xor_sync(0xffffffffu, rm, w));
            float mn   = fmaxf(m[qi], rm);
            float corr = expf(m[qi] - mn);
            float rs = 0.f;
            #pragma unroll
            for (int kj = 0; kj < 4; ++kj) {
                float p = expf(s[qi][kj] - mn);
                s[qi][kj] = p;
                rs += p;
            }
            #pragma unroll
            for (int w = 1; w < 16; w <<= 1)
                rs += __shfl_xor_sync(0xffffffffu, rs, w);
            l[qi] = l[qi] * corr + rs;
            m[qi] = mn;
            #pragma unroll
            for (int dj = 0; dj < 8; ++dj) o[qi][dj] *= corr;
        }

        // write P transposed: Ps[k][q]
        #pragma unroll
        for (int kj = 0; kj < 4; ++kj)
            *(float4*)(&Ps[(tx * 4 + kj) * 68 + ty * 4]) =
                make_float4(s[0][kj], s[1][kj], s[2][kj], s[3][kj]);
        __syncthreads();

        // O += P V   (each thread: 4q x 8d, d0 = tx*8)
        #pragma unroll 4
        for (int kk = 0; kk < 64; ++kk) {
            float pv[4], vv[8];
            *(float4*)pv       = *(float4*)(&Ps[kk * 68 + ty * 4]);
            *(float4*)vv       = *(float4*)(&Vs[kk * 128 + tx * 8]);
            *(float4*)(vv + 4) = *(float4*)(&Vs[kk * 128 + tx * 8 + 4]);
            #pragma unroll
            for (int qi = 0; qi < 4; ++qi)
                #pragma unroll
                for (int dj = 0; dj < 8; ++dj)
                    o[qi][dj] = fmaf(pv[qi], vv[dj], o[qi][dj]);
        }
    }

    // epilogue: normalize and write
    #pragma unroll
    for (int qi = 0; qi < 4; ++qi) {
        float inv = 1.f / l[qi];
        size_t row = (size_t)b * SEQ + qt * 64 + ty * 4 + qi;
        float* op = out + row * DIN + h * HDIM + tx * 8;
        *(float4*)(op)     = make_float4(o[qi][0] * inv, o[qi][1] * inv, o[qi][2] * inv, o[qi][3] * inv);
        *(float4*)(op + 4) = make_float4(o[qi][4] * inv, o[qi][5] * inv, o[qi][6] * inv, o[qi][7] * inv);
    }
}

// ---------------- launch ----------------
extern "C" void kernel_launch(void* const* d_in, const int* in_sizes, int n_in,
                              void* d_out, int out_size)
{
    const float* x     = (const float*)d_in[0];   // [2,2048,2048]
    const float* Wqkv  = (const float*)d_in[1];   // [2048,6144]
    const float* Wproj = (const float*)d_in[2];   // [2048,2048]
    float* out = (float*)d_out;                    // [2,2048,2048]

    float *qkv_ptr, *att_ptr;
    cudaGetSymbolAddress((void**)&qkv_ptr, g_qkv);
    cudaGetSymbolAddress((void**)&att_ptr, g_att);

    // rope tables
    freq_kernel<<<(SEQ * HPAIR + 255) / 256, 256>>>();

    // qkv = x @ Wqkv : [4096,2048]x[2048,6144]
    {
        dim3 grid(QKVN / 128, MROWS / 128);
        sgemm128<<<grid, 256>>>(x, Wqkv, qkv_ptr, MROWS, QKVN, DIN);
    }

    // rope on q,k
    {
        int total = BATCH * SEQ * NHEAD * HPAIR;
        rope_kernel<<<(total + 255) / 256, 256>>>(qkv_ptr);
    }

    // attention
    {
        int smem_bytes = (128 * 64 + 128 * 64 + 64 * 128 + 64 * 68) * sizeof(float);
        cudaFuncSetAttribute(attn_kernel, cudaFuncAttributeMaxDynamicSharedMemorySize, smem_bytes);
        dim3 grid(SEQ / 64, NHEAD, BATCH);
        attn_kernel<<<grid, 256, smem_bytes>>>(qkv_ptr, att_ptr);
    }

    // out = att @ Wproj : [4096,2048]x[2048,2048]
    {
        dim3 grid(DIN / 128, MROWS / 128);
        sgemm128<<<grid, 256>>>(att_ptr, Wproj, out, MROWS, DIN, DIN);
    }
}

// round 5
// speedup vs baseline: 1.5445x; 1.5345x over previous
#include <cuda_runtime.h>
#include <cuda_bf16.h>
#include <math.h>
#include <stdint.h>

#define BATCH 2
#define SEQ   2048
#define DIN   2048
#define NHEAD 16
#define HDIM  128
#define HPAIR (HDIM/2)
#define MROWS (BATCH*SEQ)       // 4096
#define QKVN  (3*DIN)           // 6144
#define KDIM  2048

// ---------------- scratch (device globals; no allocs allowed) ----------------
__device__ float g_qkv[(size_t)MROWS * QKVN];   // 96 MB
__device__ float g_att[(size_t)MROWS * DIN];    // 32 MB
__device__ float g_cos[SEQ * HPAIR];
__device__ float g_sin[SEQ * HPAIR];

__device__ __align__(128) __nv_bfloat16 g_ahi[(size_t)MROWS * KDIM];
__device__ __align__(128) __nv_bfloat16 g_alo[(size_t)MROWS * KDIM];
__device__ __align__(128) __nv_bfloat16 g_bqkv_hi[(size_t)QKVN * KDIM];    // Wqkv^T [6144][2048]
__device__ __align__(128) __nv_bfloat16 g_bqkv_lo[(size_t)QKVN * KDIM];
__device__ __align__(128) __nv_bfloat16 g_bproj_hi[(size_t)DIN * KDIM];    // Wproj^T [2048][2048]
__device__ __align__(128) __nv_bfloat16 g_bproj_lo[(size_t)DIN * KDIM];

// ---------------- PTX helpers (all base-ISA, no 'a' features) ----------------
__device__ __forceinline__ uint32_t smem_u32(const void* p) {
    uint32_t a;
    asm("{ .reg .u64 t; cvta.to.shared.u64 t, %1; cvt.u32.u64 %0, t; }" : "=r"(a) : "l"(p));
    return a;
}
__device__ __forceinline__ void cpa16(uint32_t s, const void* g) {
    asm volatile("cp.async.cg.shared.global [%0], [%1], 16;" :: "r"(s), "l"(g));
}
#define CP_COMMIT() asm volatile("cp.async.commit_group;" ::: "memory")
#define CP_WAIT1()  asm volatile("cp.async.wait_group 1;" ::: "memory")

__device__ __forceinline__ void ldsm4(uint32_t* r, uint32_t addr) {
    asm volatile("ldmatrix.sync.aligned.m8n8.x4.shared.b16 {%0,%1,%2,%3}, [%4];"
                 : "=r"(r[0]), "=r"(r[1]), "=r"(r[2]), "=r"(r[3]) : "r"(addr));
}
__device__ __forceinline__ void mma16816(float* c, const uint32_t* a, const uint32_t* b) {
    asm volatile(
        "mma.sync.aligned.m16n8k16.row.col.f32.bf16.bf16.f32 "
        "{%0,%1,%2,%3}, {%4,%5,%6,%7}, {%8,%9}, {%0,%1,%2,%3};"
        : "+f"(c[0]), "+f"(c[1]), "+f"(c[2]), "+f"(c[3])
        : "r"(a[0]), "r"(a[1]), "r"(a[2]), "r"(a[3]), "r"(b[0]), "r"(b[1]));
}

// ============================================================================
// prep kernels
// ============================================================================
__global__ void freq_kernel() {
    int t = blockIdx.x * blockDim.x + threadIdx.x;
    if (t >= SEQ * HPAIR) return;
    int s = t >> 6;
    int p = t & 63;
    float inv = (float)(1.0 / pow(10000.0, (double)(2 * p) / (double)HDIM));
    float ang = (float)s * inv;
    float sn, cs;
    sincosf(ang, &sn, &cs);
    g_cos[t] = cs;
    g_sin[t] = sn;
}

__global__ void rope_kernel(float* __restrict__ qkv) {
    int t = blockIdx.x * blockDim.x + threadIdx.x;
    if (t >= BATCH * SEQ * NHEAD * HPAIR) return;
    int p = t & 63;
    int h = (t >> 6) & (NHEAD - 1);
    int s = (t >> 10) & (SEQ - 1);
    int b = t >> 21;
    int row = b * SEQ + s;
    float c  = g_cos[s * HPAIR + p];
    float sn = g_sin[s * HPAIR + p];
    size_t base = (size_t)row * QKVN + h * HDIM + 2 * p;
    float q1 = qkv[base], q2 = qkv[base + 1];
    qkv[base]     = q1 * c - q2 * sn;
    qkv[base + 1] = q1 * sn + q2 * c;
    size_t kb = base + DIN;
    float k1 = qkv[kb], k2 = qkv[kb + 1];
    qkv[kb]     = k1 * c - k2 * sn;
    qkv[kb + 1] = k1 * sn + k2 * c;
}

__global__ void split_kernel(const float* __restrict__ src,
                             __nv_bfloat16* __restrict__ hi,
                             __nv_bfloat16* __restrict__ lo, int n4) {
    int i = blockIdx.x * blockDim.x + threadIdx.x;
    if (i >= n4) return;
    float4 v = ((const float4*)src)[i];
    __nv_bfloat16 h0 = __float2bfloat16(v.x), h1 = __float2bfloat16(v.y);
    __nv_bfloat16 h2 = __float2bfloat16(v.z), h3 = __float2bfloat16(v.w);
    ((__nv_bfloat162*)hi)[2*i]   = __nv_bfloat162(h0, h1);
    ((__nv_bfloat162*)hi)[2*i+1] = __nv_bfloat162(h2, h3);
    ((__nv_bfloat162*)lo)[2*i]   = __nv_bfloat162(__float2bfloat16(v.x - __bfloat162float(h0)),
                                                  __float2bfloat16(v.y - __bfloat162float(h1)));
    ((__nv_bfloat162*)lo)[2*i+1] = __nv_bfloat162(__float2bfloat16(v.z - __bfloat162float(h2)),
                                                  __float2bfloat16(v.w - __bfloat162float(h3)));
}

// transpose fp32 [K][N] -> bf16 hi/lo [N][K]
__global__ void transpose_split(const float* __restrict__ in,
                                __nv_bfloat16* __restrict__ hi,
                                __nv_bfloat16* __restrict__ lo, int K, int N) {
    __shared__ float t[32][33];
    int n0 = blockIdx.x * 32, k0 = blockIdx.y * 32;
    int tx = threadIdx.x, ty = threadIdx.y;   // block (32, 8)
    #pragma unroll
    for (int j = 0; j < 4; ++j)
        t[ty + j*8][tx] = in[(size_t)(k0 + ty + j*8) * N + n0 + tx];
    __syncthreads();
    #pragma unroll
    for (int j = 0; j < 4; ++j) {
        int n = ty + j*8;
        float v = t[tx][n];
        __nv_bfloat16 h = __float2bfloat16(v);
        size_t o = (size_t)(n0 + n) * K + k0 + tx;
        hi[o] = h;
        lo[o] = __float2bfloat16(v - __bfloat162float(h));
    }
}

// ============================================================================
// HMMA GEMM: C[M,N] = A[M,K] x B[K,N]; A hi/lo row-major [M][K], Bt hi/lo [N][K].
// BM=128 BN=128 BK=32, 256 thr (8 warps: 4m x 2n), 3-stage cp.async pipeline.
// 3-term bf16 split: AhBh + AhBl + AlBh into fp32 accumulators.
// ============================================================================
#define SSTRIDE 80                   // bytes per smem row (32 bf16 data + pad)
#define OFF_ALO 10240
#define OFF_BHI 20480
#define OFF_BLO 30720
#define STAGE_B 40960
#define NSTAGE  3
#define GEMM_SMEM (NSTAGE * STAGE_B)   // 122880
#define KT_TOT (KDIM / 32)             // 64

__global__ __launch_bounds__(256) void gemm_mma(
    const __nv_bfloat16* __restrict__ Ahi, const __nv_bfloat16* __restrict__ Alo,
    const __nv_bfloat16* __restrict__ Bhi, const __nv_bfloat16* __restrict__ Blo,
    float* __restrict__ C, int Ntot)
{
    extern __shared__ char smem_raw[];
    uint32_t sb = smem_u32(smem_raw);
    const int t = threadIdx.x, lane = t & 31, wid = t >> 5;
    const int m0 = blockIdx.y * 128, n0 = blockIdx.x * 128;
    const int mW = (wid & 3) * 32, nW = (wid >> 2) * 64;

    // cp.async thread mapping: 512 16B-chunks per operand tile, 2 per thread
    const int rowL = t >> 2, ch = t & 3;
    const uint32_t soff = (uint32_t)rowL * SSTRIDE + ch * 16;
    const __nv_bfloat16* gAhi = Ahi + (size_t)(m0 + rowL) * KDIM + ch * 8;
    const __nv_bfloat16* gAlo = Alo + (size_t)(m0 + rowL) * KDIM + ch * 8;
    const __nv_bfloat16* gBhi = Bhi + (size_t)(n0 + rowL) * KDIM + ch * 8;
    const __nv_bfloat16* gBlo = Blo + (size_t)(n0 + rowL) * KDIM + ch * 8;

    float acc[2][8][4];
    #pragma unroll
    for (int i = 0; i < 2; ++i)
        #pragma unroll
        for (int j = 0; j < 8; ++j)
            #pragma unroll
            for (int q = 0; q < 4; ++q) acc[i][j][q] = 0.f;

    auto load_stage = [&](int slot, int kt) {
        uint32_t s = sb + slot * STAGE_B + soff;
        int g = kt * 32;
        cpa16(s,                          gAhi + g);
        cpa16(s + 64u * SSTRIDE,          gAhi + g + (size_t)64 * KDIM);
        cpa16(s + OFF_ALO,                gAlo + g);
        cpa16(s + OFF_ALO + 64u * SSTRIDE, gAlo + g + (size_t)64 * KDIM);
        cpa16(s + OFF_BHI,                gBhi + g);
        cpa16(s + OFF_BHI + 64u * SSTRIDE, gBhi + g + (size_t)64 * KDIM);
        cpa16(s + OFF_BLO,                gBlo + g);
        cpa16(s + OFF_BLO + 64u * SSTRIDE, gBlo + g + (size_t)64 * KDIM);
    };

    // ldmatrix lane addressing (bytes)
    // A x4 (16x16): lanes 0-15 rows 0-15 @k-lo16B, lanes 16-31 same rows @k-hi16B
    const uint32_t aLane = (uint32_t)(mW + (lane & 15)) * SSTRIDE + ((lane >> 4) * 16);
    // B x4 (two 8n x 16k tiles): lanes 0-7 n0-7 klo, 8-15 n0-7 khi, 16-23 n8-15 klo, 24-31 khi
    const uint32_t bLane = (uint32_t)(nW + (lane & 7) + ((lane >> 4) << 3)) * SSTRIDE
                         + (((lane >> 3) & 1) * 16);

    auto compute_stage = [&](int slot) {
        uint32_t base = sb + slot * STAGE_B;
        #pragma unroll
        for (int kk = 0; kk < 2; ++kk) {
            uint32_t koff = kk * 32;   // 16 bf16 = 32 bytes
            uint32_t aH[2][4], aL[2][4], bH[8][2], bL[8][2];
            #pragma unroll
            for (int mt = 0; mt < 2; ++mt) {
                uint32_t ad = base + aLane + mt * (16u * SSTRIDE) + koff;
                ldsm4(aH[mt], ad);
                ldsm4(aL[mt], ad + OFF_ALO);
            }
            #pragma unroll
            for (int p = 0; p < 4; ++p) {
                uint32_t bd = base + OFF_BHI + bLane + p * (16u * SSTRIDE) + koff;
                uint32_t r[4];
                ldsm4(r, bd);
                bH[2*p][0] = r[0]; bH[2*p][1] = r[1];
                bH[2*p+1][0] = r[2]; bH[2*p+1][1] = r[3];
                ldsm4(r, bd + (OFF_BLO - OFF_BHI));
                bL[2*p][0] = r[0]; bL[2*p][1] = r[1];
                bL[2*p+1][0] = r[2]; bL[2*p+1][1] = r[3];
            }
            #pragma unroll
            for (int mt = 0; mt < 2; ++mt)
                #pragma unroll
                for (int nt = 0; nt < 8; ++nt) {
                    mma16816(acc[mt][nt], aH[mt], bH[nt]);
                    mma16816(acc[mt][nt], aH[mt], bL[nt]);
                    mma16816(acc[mt][nt], aL[mt], bH[nt]);
                }
        }
    };

    // pipeline
    load_stage(0, 0); CP_COMMIT();
    load_stage(1, 1); CP_COMMIT();
    #pragma unroll 1
    for (int kt = 0; kt < KT_TOT; ++kt) {
        CP_WAIT1();
        __syncthreads();
        if (kt + 2 < KT_TOT) load_stage((kt + 2) % NSTAGE, kt + 2);
        CP_COMMIT();
        compute_stage(kt % NSTAGE);
    }

    // epilogue
    #pragma unroll
    for (int mt = 0; mt < 2; ++mt)
        #pragma unroll
        for (int nt = 0; nt < 8; ++nt) {
            int r = m0 + mW + mt * 16 + (lane >> 2);
            int c = n0 + nW + nt * 8 + (lane & 3) * 2;
            float2 v0 = make_float2(acc[mt][nt][0], acc[mt][nt][1]);
            float2 v1 = make_float2(acc[mt][nt][2], acc[mt][nt][3]);
            *(float2*)(C + (size_t)r * Ntot + c)       = v0;
            *(float2*)(C + (size_t)(r + 8) * Ntot + c) = v1;
        }
}

// ============================================================================
// causal flash attention, fp32 (unchanged, proven)
// ============================================================================
__global__ __launch_bounds__(256) void attn_kernel(
    const float* __restrict__ qkv, float* __restrict__ out)
{
    extern __shared__ float fsm[];
    float* Qs = fsm;
    float* Ks = Qs + 128 * 64;
    float* Vs = Ks + 128 * 64;
    float* Ps = Vs + 64 * 128;

    const int qt = blockIdx.x;
    const int h  = blockIdx.y;
    const int b  = blockIdx.z;
    const int t  = threadIdx.x;
    const int tx = t & 15;
    const int ty = t >> 4;

    const float* base = qkv + (size_t)b * SEQ * QKVN + h * HDIM;

    for (int i = t; i < 64 * 32; i += 256) {
        int r  = i >> 5;
        int c4 = i & 31;
        float4 v = *(const float4*)(base + (size_t)(qt * 64 + r) * QKVN + c4 * 4);
        Qs[(c4 * 4 + 0) * 64 + r] = v.x;
        Qs[(c4 * 4 + 1) * 64 + r] = v.y;
        Qs[(c4 * 4 + 2) * 64 + r] = v.z;
        Qs[(c4 * 4 + 3) * 64 + r] = v.w;
    }

    float o[4][8];
    float m[4], l[4];
    #pragma unroll
    for (int qi = 0; qi < 4; ++qi) {
        m[qi] = -INFINITY; l[qi] = 0.f;
        #pragma unroll
        for (int dj = 0; dj < 8; ++dj) o[qi][dj] = 0.f;
    }

    const float scale = 0.08838834764831845f;

    for (int kt = 0; kt <= qt; ++kt) {
        __syncthreads();
        for (int i = t; i < 64 * 32; i += 256) {
            int r  = i >> 5;
            int c4 = i & 31;
            const float* kp = base + DIN + (size_t)(kt * 64 + r) * QKVN + c4 * 4;
            float4 kv = *(const float4*)kp;
            Ks[(c4 * 4 + 0) * 64 + r] = kv.x;
            Ks[(c4 * 4 + 1) * 64 + r] = kv.y;
            Ks[(c4 * 4 + 2) * 64 + r] = kv.z;
            Ks[(c4 * 4 + 3) * 64 + r] = kv.w;
            float4 vv = *(const float4*)(kp + DIN);
            *(float4*)(&Vs[r * 128 + c4 * 4]) = vv;
        }
        __syncthreads();

        float s[4][4];
        #pragma unroll
        for (int qi = 0; qi < 4; ++qi)
            #pragma unroll
            for (int kj = 0; kj < 4; ++kj) s[qi][kj] = 0.f;

        #pragma unroll 4
        for (int d = 0; d < 128; ++d) {
            float qv[4], kv[4];
            *(float4*)qv = *(float4*)(&Qs[d * 64 + ty * 4]);
            *(float4*)kv = *(float4*)(&Ks[d * 64 + tx * 4]);
            #pragma unroll
            for (int qi = 0; qi < 4; ++qi)
                #pragma unroll
                for (int kj = 0; kj < 4; ++kj)
                    s[qi][kj] = fmaf(qv[qi], kv[kj], s[qi][kj]);
        }

        #pragma unroll
        for (int qi = 0; qi < 4; ++qi)
            #pragma unroll
            for (int kj = 0; kj < 4; ++kj) {
                float v = s[qi][kj] * scale;
                if (kt == qt && (tx * 4 + kj) > (ty * 4 + qi)) v = -INFINITY;
                s[qi][kj] = v;
            }

        #pragma unroll
        for (int qi = 0; qi < 4; ++qi) {
            float rm = fmaxf(fmaxf(s[qi][0], s[qi][1]), fmaxf(s[qi][2], s[qi][3]));
            #pragma unroll
            for (int w = 1; w < 16; w <<= 1)
                rm = fmaxf(rm, __shfl_xor_sync(0xffffffffu, rm, w));
            float mn   = fmaxf(m[qi], rm);
            float corr = expf(m[qi] - mn);
            float rs = 0.f;
            #pragma unroll
            for (int kj = 0; kj < 4; ++kj) {
                float p = expf(s[qi][kj] - mn);
                s[qi][kj] = p;
                rs += p;
            }
            #pragma unroll
            for (int w = 1; w < 16; w <<= 1)
                rs += __shfl_xor_sync(0xffffffffu, rs, w);
            l[qi] = l[qi] * corr + rs;
            m[qi] = mn;
            #pragma unroll
            for (int dj = 0; dj < 8; ++dj) o[qi][dj] *= corr;
        }

        #pragma unroll
        for (int kj = 0; kj < 4; ++kj)
            *(float4*)(&Ps[(tx * 4 + kj) * 68 + ty * 4]) =
                make_float4(s[0][kj], s[1][kj], s[2][kj], s[3][kj]);
        __syncthreads();

        #pragma unroll 4
        for (int kk = 0; kk < 64; ++kk) {
            float pv[4], vv[8];
            *(float4*)pv       = *(float4*)(&Ps[kk * 68 + ty * 4]);
            *(float4*)vv       = *(float4*)(&Vs[kk * 128 + tx * 8]);
            *(float4*)(vv + 4) = *(float4*)(&Vs[kk * 128 + tx * 8 + 4]);
            #pragma unroll
            for (int qi = 0; qi < 4; ++qi)
                #pragma unroll
                for (int dj = 0; dj < 8; ++dj)
                    o[qi][dj] = fmaf(pv[qi], vv[dj], o[qi][dj]);
        }
    }

    #pragma unroll
    for (int qi = 0; qi < 4; ++qi) {
        float inv = 1.f / l[qi];
        size_t row = (size_t)b * SEQ + qt * 64 + ty * 4 + qi;
        float* op = out + row * DIN + h * HDIM + tx * 8;
        *(float4*)(op)     = make_float4(o[qi][0] * inv, o[qi][1] * inv, o[qi][2] * inv, o[qi][3] * inv);
        *(float4*)(op + 4) = make_float4(o[qi][4] * inv, o[qi][5] * inv, o[qi][6] * inv, o[qi][7] * inv);
    }
}

// ============================================================================
// launch
// ============================================================================
extern "C" void kernel_launch(void* const* d_in, const int* in_sizes, int n_in,
                              void* d_out, int out_size)
{
    const float* x     = (const float*)d_in[0];   // [2,2048,2048]
    const float* Wqkv  = (const float*)d_in[1];   // [2048,6144]
    const float* Wproj = (const float*)d_in[2];   // [2048,2048]
    float* out = (float*)d_out;

    float *qkv_ptr, *att_ptr;
    cudaGetSymbolAddress((void**)&qkv_ptr, g_qkv);
    cudaGetSymbolAddress((void**)&att_ptr, g_att);
    void *ahi, *alo, *bqh, *bql, *bph, *bpl;
    cudaGetSymbolAddress(&ahi, g_ahi);
    cudaGetSymbolAddress(&alo, g_alo);
    cudaGetSymbolAddress(&bqh, g_bqkv_hi);
    cudaGetSymbolAddress(&bql, g_bqkv_lo);
    cudaGetSymbolAddress(&bph, g_bproj_hi);
    cudaGetSymbolAddress(&bpl, g_bproj_lo);

    static bool attr_done = false;
    if (!attr_done) {
        cudaFuncSetAttribute(gemm_mma, cudaFuncAttributeMaxDynamicSharedMemorySize, GEMM_SMEM);
        int attn_smem = (128 * 64 + 128 * 64 + 64 * 128 + 64 * 68) * sizeof(float);
        cudaFuncSetAttribute(attn_kernel, cudaFuncAttributeMaxDynamicSharedMemorySize, attn_smem);
        attr_done = true;
    }

    // rope tables
    freq_kernel<<<(SEQ * HPAIR + 255) / 256, 256>>>();

    // weight transposes + splits
    {
        dim3 blk(32, 8);
        transpose_split<<<dim3(QKVN / 32, KDIM / 32), blk>>>(Wqkv, (__nv_bfloat16*)bqh, (__nv_bfloat16*)bql, KDIM, QKVN);
        transpose_split<<<dim3(DIN / 32, KDIM / 32), blk>>>(Wproj, (__nv_bfloat16*)bph, (__nv_bfloat16*)bpl, KDIM, DIN);
    }

    // split x -> a_hi/a_lo
    {
        int n4 = MROWS * KDIM / 4;
        split_kernel<<<(n4 + 255) / 256, 256>>>(x, (__nv_bfloat16*)ahi, (__nv_bfloat16*)alo, n4);
    }

    // GEMM1: qkv = x @ Wqkv
    {
        dim3 grid(QKVN / 128, MROWS / 128);
        gemm_mma<<<grid, 256, GEMM_SMEM>>>((const __nv_bfloat16*)ahi, (const __nv_bfloat16*)alo,
                                           (const __nv_bfloat16*)bqh, (const __nv_bfloat16*)bql,
                                           qkv_ptr, QKVN);
    }

    // rope
    {
        int total = BATCH * SEQ * NHEAD * HPAIR;
        rope_kernel<<<(total + 255) / 256, 256>>>(qkv_ptr);
    }

    // attention (fp32)
    {
        int attn_smem = (128 * 64 + 128 * 64 + 64 * 128 + 64 * 68) * sizeof(float);
        dim3 grid(SEQ / 64, NHEAD, BATCH);
        attn_kernel<<<grid, 256, attn_smem>>>(qkv_ptr, att_ptr);
    }

    // split att -> a_hi/a_lo
    {
        int n4 = MROWS * KDIM / 4;
        split_kernel<<<(n4 + 255) / 256, 256>>>(att_ptr, (__nv_bfloat16*)ahi, (__nv_bfloat16*)alo, n4);
    }

    // GEMM2: out = att @ Wproj
    {
        dim3 grid(DIN / 128, MROWS / 128);
        gemm_mma<<<grid, 256, GEMM_SMEM>>>((const __nv_bfloat16*)ahi, (const __nv_bfloat16*)alo,
                                           (const __nv_bfloat16*)bph, (const __nv_bfloat16*)bpl,
                                           out, DIN);
    }
}

// round 6
// speedup vs baseline: 2.8763x; 1.8624x over previous
#include <cuda_runtime.h>
#include <cuda_bf16.h>
#include <math.h>
#include <stdint.h>

#define BATCH 2
#define SEQ   2048
#define DIN   2048
#define NHEAD 16
#define HDIM  128
#define HPAIR (HDIM/2)
#define MROWS (BATCH*SEQ)       // 4096
#define QKVN  (3*DIN)           // 6144
#define KDIM  2048

// ---------------- scratch (device globals; no allocs allowed) ----------------
__device__ float g_qkv[(size_t)MROWS * QKVN];   // 96 MB
__device__ float g_cos[SEQ * HPAIR];
__device__ float g_sin[SEQ * HPAIR];

__device__ __align__(128) __nv_bfloat16 g_ahi[(size_t)MROWS * KDIM];
__device__ __align__(128) __nv_bfloat16 g_alo[(size_t)MROWS * KDIM];
__device__ __align__(128) __nv_bfloat16 g_bqkv_hi[(size_t)QKVN * KDIM];
__device__ __align__(128) __nv_bfloat16 g_bqkv_lo[(size_t)QKVN * KDIM];
__device__ __align__(128) __nv_bfloat16 g_bproj_hi[(size_t)DIN * KDIM];
__device__ __align__(128) __nv_bfloat16 g_bproj_lo[(size_t)DIN * KDIM];

// attention operands, bf16 hi/lo, rope applied
__device__ __align__(128) __nv_bfloat16 g_Qh[(size_t)BATCH*NHEAD*SEQ*HDIM];
__device__ __align__(128) __nv_bfloat16 g_Ql[(size_t)BATCH*NHEAD*SEQ*HDIM];
__device__ __align__(128) __nv_bfloat16 g_Kh[(size_t)BATCH*NHEAD*SEQ*HDIM];
__device__ __align__(128) __nv_bfloat16 g_Kl[(size_t)BATCH*NHEAD*SEQ*HDIM];
__device__ __align__(128) __nv_bfloat16 g_Vth[(size_t)BATCH*NHEAD*HDIM*SEQ];  // [b,h,d,s]
__device__ __align__(128) __nv_bfloat16 g_Vtl[(size_t)BATCH*NHEAD*HDIM*SEQ];

// ---------------- PTX helpers (all base-ISA, no 'a' features) ----------------
__device__ __forceinline__ uint32_t smem_u32(const void* p) {
    uint32_t a;
    asm("{ .reg .u64 t; cvta.to.shared.u64 t, %1; cvt.u32.u64 %0, t; }" : "=r"(a) : "l"(p));
    return a;
}
__device__ __forceinline__ void cpa16(uint32_t s, const void* g) {
    asm volatile("cp.async.cg.shared.global [%0], [%1], 16;" :: "r"(s), "l"(g));
}
#define CP_COMMIT() asm volatile("cp.async.commit_group;" ::: "memory")
#define CP_WAIT1()  asm volatile("cp.async.wait_group 1;" ::: "memory")
#define CP_WAIT0()  asm volatile("cp.async.wait_group 0;" ::: "memory")

__device__ __forceinline__ void ldsm4(uint32_t* r, uint32_t addr) {
    asm volatile("ldmatrix.sync.aligned.m8n8.x4.shared.b16 {%0,%1,%2,%3}, [%4];"
                 : "=r"(r[0]), "=r"(r[1]), "=r"(r[2]), "=r"(r[3]) : "r"(addr));
}
__device__ __forceinline__ void mma16816(float* c, const uint32_t* a, const uint32_t* b) {
    asm volatile(
        "mma.sync.aligned.m16n8k16.row.col.f32.bf16.bf16.f32 "
        "{%0,%1,%2,%3}, {%4,%5,%6,%7}, {%8,%9}, {%0,%1,%2,%3};"
        : "+f"(c[0]), "+f"(c[1]), "+f"(c[2]), "+f"(c[3])
        : "r"(a[0]), "r"(a[1]), "r"(a[2]), "r"(a[3]), "r"(b[0]), "r"(b[1]));
}
__device__ __forceinline__ float ex2f(float x) {
    float y;
    asm("ex2.approx.f32 %0, %1;" : "=f"(y) : "f"(x));
    return y;
}
__device__ __forceinline__ uint32_t pk2(float a, float b) {
    __nv_bfloat162 t = __floats2bfloat162_rn(a, b);
    return *(uint32_t*)&t;
}

// ============================================================================
// prep kernels
// ============================================================================
__global__ void freq_kernel() {
    int t = blockIdx.x * blockDim.x + threadIdx.x;
    if (t >= SEQ * HPAIR) return;
    int s = t >> 6;
    int p = t & 63;
    float inv = (float)(1.0 / pow(10000.0, (double)(2 * p) / (double)HDIM));
    float ang = (float)s * inv;
    float sn, cs;
    sincosf(ang, &sn, &cs);
    g_cos[t] = cs;
    g_sin[t] = sn;
}

// rope + hi/lo split of Q,K into per-head layouts
__global__ void ropesplit_kernel(const float* __restrict__ qkv) {
    int t = blockIdx.x * blockDim.x + threadIdx.x;
    if (t >= BATCH * SEQ * NHEAD * HPAIR) return;
    int p = t & 63;
    int h = (t >> 6) & (NHEAD - 1);
    int s = (t >> 10) & (SEQ - 1);
    int b = t >> 21;
    float c  = g_cos[s * HPAIR + p];
    float sn = g_sin[s * HPAIR + p];
    size_t src = (size_t)(b * SEQ + s) * QKVN + h * HDIM + 2 * p;
    size_t dst = ((size_t)(b * NHEAD + h) * SEQ + s) * HDIM + 2 * p;
    // q
    float q1 = qkv[src], q2 = qkv[src + 1];
    float r1 = q1 * c - q2 * sn;
    float r2 = q1 * sn + q2 * c;
    __nv_bfloat16 h1 = __float2bfloat16(r1), h2 = __float2bfloat16(r2);
    *(__nv_bfloat162*)(g_Qh + dst) = __nv_bfloat162(h1, h2);
    *(__nv_bfloat162*)(g_Ql + dst) = __nv_bfloat162(
        __float2bfloat16(r1 - __bfloat162float(h1)),
        __float2bfloat16(r2 - __bfloat162float(h2)));
    // k
    float k1 = qkv[src + DIN], k2 = qkv[src + DIN + 1];
    r1 = k1 * c - k2 * sn;
    r2 = k1 * sn + k2 * c;
    h1 = __float2bfloat16(r1); h2 = __float2bfloat16(r2);
    *(__nv_bfloat162*)(g_Kh + dst) = __nv_bfloat162(h1, h2);
    *(__nv_bfloat162*)(g_Kl + dst) = __nv_bfloat162(
        __float2bfloat16(r1 - __bfloat162float(h1)),
        __float2bfloat16(r2 - __bfloat162float(h2)));
}

// V: per-head transpose [s][d] -> [d][s] with hi/lo split
__global__ void vsplit_kernel(const float* __restrict__ qkv) {
    __shared__ float tile[32][33];
    int s0 = blockIdx.x * 32, d0 = blockIdx.y * 32, bh = blockIdx.z;
    int b = bh >> 4, h = bh & 15;
    int tx = threadIdx.x, ty = threadIdx.y;     // (32,8)
    #pragma unroll
    for (int j = 0; j < 4; ++j)
        tile[ty + j*8][tx] = qkv[(size_t)(b * SEQ + s0 + ty + j*8) * QKVN + 2*DIN + h * HDIM + d0 + tx];
    __syncthreads();
    #pragma unroll
    for (int j = 0; j < 4; ++j) {
        int dl = ty + j*8;
        float v = tile[tx][dl];
        __nv_bfloat16 hh = __float2bfloat16(v);
        size_t o = ((size_t)bh * HDIM + d0 + dl) * SEQ + s0 + tx;
        g_Vth[o] = hh;
        g_Vtl[o] = __float2bfloat16(v - __bfloat162float(hh));
    }
}

__global__ void split_kernel(const float* __restrict__ src,
                             __nv_bfloat16* __restrict__ hi,
                             __nv_bfloat16* __restrict__ lo, int n4) {
    int i = blockIdx.x * blockDim.x + threadIdx.x;
    if (i >= n4) return;
    float4 v = ((const float4*)src)[i];
    __nv_bfloat16 h0 = __float2bfloat16(v.x), h1 = __float2bfloat16(v.y);
    __nv_bfloat16 h2 = __float2bfloat16(v.z), h3 = __float2bfloat16(v.w);
    ((__nv_bfloat162*)hi)[2*i]   = __nv_bfloat162(h0, h1);
    ((__nv_bfloat162*)hi)[2*i+1] = __nv_bfloat162(h2, h3);
    ((__nv_bfloat162*)lo)[2*i]   = __nv_bfloat162(__float2bfloat16(v.x - __bfloat162float(h0)),
                                                  __float2bfloat16(v.y - __bfloat162float(h1)));
    ((__nv_bfloat162*)lo)[2*i+1] = __nv_bfloat162(__float2bfloat16(v.z - __bfloat162float(h2)),
                                                  __float2bfloat16(v.w - __bfloat162float(h3)));
}

__global__ void transpose_split(const float* __restrict__ in,
                                __nv_bfloat16* __restrict__ hi,
                                __nv_bfloat16* __restrict__ lo, int K, int N) {
    __shared__ float t[32][33];
    int n0 = blockIdx.x * 32, k0 = blockIdx.y * 32;
    int tx = threadIdx.x, ty = threadIdx.y;
    #pragma unroll
    for (int j = 0; j < 4; ++j)
        t[ty + j*8][tx] = in[(size_t)(k0 + ty + j*8) * N + n0 + tx];
    __syncthreads();
    #pragma unroll
    for (int j = 0; j < 4; ++j) {
        int n = ty + j*8;
        float v = t[tx][n];
        __nv_bfloat16 h = __float2bfloat16(v);
        size_t o = (size_t)(n0 + n) * K + k0 + tx;
        hi[o] = h;
        lo[o] = __float2bfloat16(v - __bfloat162float(h));
    }
}

// ============================================================================
// HMMA GEMM (unchanged from R4, proven)
// ============================================================================
#define SSTRIDE 80
#define OFF_ALO 10240
#define OFF_BHI 20480
#define OFF_BLO 30720
#define STAGE_B 40960
#define NSTAGE  3
#define GEMM_SMEM (NSTAGE * STAGE_B)
#define KT_TOT (KDIM / 32)

__global__ __launch_bounds__(256) void gemm_mma(
    const __nv_bfloat16* __restrict__ Ahi, const __nv_bfloat16* __restrict__ Alo,
    const __nv_bfloat16* __restrict__ Bhi, const __nv_bfloat16* __restrict__ Blo,
    float* __restrict__ C, int Ntot)
{
    extern __shared__ char smem_raw[];
    uint32_t sb = smem_u32(smem_raw);
    const int t = threadIdx.x, lane = t & 31, wid = t >> 5;
    const int m0 = blockIdx.y * 128, n0 = blockIdx.x * 128;
    const int mW = (wid & 3) * 32, nW = (wid >> 2) * 64;

    const int rowL = t >> 2, ch = t & 3;
    const uint32_t soff = (uint32_t)rowL * SSTRIDE + ch * 16;
    const __nv_bfloat16* gAhi = Ahi + (size_t)(m0 + rowL) * KDIM + ch * 8;
    const __nv_bfloat16* gAlo = Alo + (size_t)(m0 + rowL) * KDIM + ch * 8;
    const __nv_bfloat16* gBhi = Bhi + (size_t)(n0 + rowL) * KDIM + ch * 8;
    const __nv_bfloat16* gBlo = Blo + (size_t)(n0 + rowL) * KDIM + ch * 8;

    float acc[2][8][4];
    #pragma unroll
    for (int i = 0; i < 2; ++i)
        #pragma unroll
        for (int j = 0; j < 8; ++j)
            #pragma unroll
            for (int q = 0; q < 4; ++q) acc[i][j][q] = 0.f;

    auto load_stage = [&](int slot, int kt) {
        uint32_t s = sb + slot * STAGE_B + soff;
        int g = kt * 32;
        cpa16(s,                           gAhi + g);
        cpa16(s + 64u * SSTRIDE,           gAhi + g + (size_t)64 * KDIM);
        cpa16(s + OFF_ALO,                 gAlo + g);
        cpa16(s + OFF_ALO + 64u * SSTRIDE, gAlo + g + (size_t)64 * KDIM);
        cpa16(s + OFF_BHI,                 gBhi + g);
        cpa16(s + OFF_BHI + 64u * SSTRIDE, gBhi + g + (size_t)64 * KDIM);
        cpa16(s + OFF_BLO,                 gBlo + g);
        cpa16(s + OFF_BLO + 64u * SSTRIDE, gBlo + g + (size_t)64 * KDIM);
    };

    const uint32_t aLane = (uint32_t)(mW + (lane & 15)) * SSTRIDE + ((lane >> 4) * 16);
    const uint32_t bLane = (uint32_t)(nW + (lane & 7) + ((lane >> 4) << 3)) * SSTRIDE
                         + (((lane >> 3) & 1) * 16);

    auto compute_stage = [&](int slot) {
        uint32_t base = sb + slot * STAGE_B;
        #pragma unroll
        for (int kk = 0; kk < 2; ++kk) {
            uint32_t koff = kk * 32;
            uint32_t aH[2][4], aL[2][4], bH[8][2], bL[8][2];
            #pragma unroll
            for (int mt = 0; mt < 2; ++mt) {
                uint32_t ad = base + aLane + mt * (16u * SSTRIDE) + koff;
                ldsm4(aH[mt], ad);
                ldsm4(aL[mt], ad + OFF_ALO);
            }
            #pragma unroll
            for (int p = 0; p < 4; ++p) {
                uint32_t bd = base + OFF_BHI + bLane + p * (16u * SSTRIDE) + koff;
                uint32_t r[4];
                ldsm4(r, bd);
                bH[2*p][0] = r[0]; bH[2*p][1] = r[1];
                bH[2*p+1][0] = r[2]; bH[2*p+1][1] = r[3];
                ldsm4(r, bd + (OFF_BLO - OFF_BHI));
                bL[2*p][0] = r[0]; bL[2*p][1] = r[1];
                bL[2*p+1][0] = r[2]; bL[2*p+1][1] = r[3];
            }
            #pragma unroll
            for (int mt = 0; mt < 2; ++mt)
                #pragma unroll
                for (int nt = 0; nt < 8; ++nt) {
                    mma16816(acc[mt][nt], aH[mt], bH[nt]);
                    mma16816(acc[mt][nt], aH[mt], bL[nt]);
                    mma16816(acc[mt][nt], aL[mt], bH[nt]);
                }
        }
    };

    load_stage(0, 0); CP_COMMIT();
    load_stage(1, 1); CP_COMMIT();
    #pragma unroll 1
    for (int kt = 0; kt < KT_TOT; ++kt) {
        CP_WAIT1();
        __syncthreads();
        if (kt + 2 < KT_TOT) load_stage((kt + 2) % NSTAGE, kt + 2);
        CP_COMMIT();
        compute_stage(kt % NSTAGE);
    }

    #pragma unroll
    for (int mt = 0; mt < 2; ++mt)
        #pragma unroll
        for (int nt = 0; nt < 8; ++nt) {
            int r = m0 + mW + mt * 16 + (lane >> 2);
            int c = n0 + nW + nt * 8 + (lane & 3) * 2;
            *(float2*)(C + (size_t)r * Ntot + c)       = make_float2(acc[mt][nt][0], acc[mt][nt][1]);
            *(float2*)(C + (size_t)(r + 8) * Ntot + c) = make_float2(acc[mt][nt][2], acc[mt][nt][3]);
        }
}

// ============================================================================
// HMMA flash attention: 128q x 64k tiles, bf16 hi/lo 3-term, double-buffered.
// 8 warps x 16 q-rows. Output: bf16 hi/lo directly into GEMM2 A buffers.
// ============================================================================
#define AQSTR   272                   // Q/K smem row stride (128 bf16 + pad)
#define AVSTR   144                   // Vt smem row stride (64 bf16 + pad)
#define AQ_B    (128 * AQSTR)         // 34816
#define AK_B    (64 * AQSTR)          // 17408
#define AV_B    (128 * AVSTR)         // 18432
#define ASTG_B  (2*AK_B + 2*AV_B)     // 71680
#define ASTG0   (2 * AQ_B)            // 69632
#define ATT_SMEM (ASTG0 + 2 * ASTG_B) // 212992

__global__ __launch_bounds__(256, 1) void attn_mma(
    const __nv_bfloat16* __restrict__ Qh, const __nv_bfloat16* __restrict__ Ql,
    const __nv_bfloat16* __restrict__ Kh, const __nv_bfloat16* __restrict__ Kl,
    const __nv_bfloat16* __restrict__ Vth, const __nv_bfloat16* __restrict__ Vtl,
    __nv_bfloat16* __restrict__ Ohi, __nv_bfloat16* __restrict__ Olo)
{
    extern __shared__ char smr[];
    uint32_t sb = smem_u32(smr);
    const int qt = (gridDim.x - 1) - blockIdx.x;   // heavy tiles first
    const int h = blockIdx.y, b = blockIdx.z;
    const int t = threadIdx.x, lane = t & 31, wid = t >> 5;
    const int bh = b * NHEAD + h;
    const size_t headQK = (size_t)bh * SEQ * HDIM;
    const size_t headV  = (size_t)bh * HDIM * SEQ;
    const float SC2 = 0.08838834764831845f * 1.4426950408889634f;

    // ---- load Q tile (hi/lo) ----
    #pragma unroll
    for (int i = 0; i < 8; ++i) {
        int idx = t + i * 256;
        int r = idx >> 4, c = idx & 15;
        uint32_t s = sb + (uint32_t)r * AQSTR + c * 16;
        size_t g = headQK + (size_t)(qt * 128 + r) * HDIM + c * 8;
        cpa16(s, Qh + g);
        cpa16(s + AQ_B, Ql + g);
    }

    auto load_kv = [&](int slot, int kt) {
        uint32_t st = sb + ASTG0 + slot * ASTG_B;
        #pragma unroll
        for (int i = 0; i < 4; ++i) {           // K: 64 rows x 16 chunks
            int idx = t + i * 256;
            int r = idx >> 4, c = idx & 15;
            uint32_t s = st + (uint32_t)r * AQSTR + c * 16;
            size_t g = headQK + (size_t)(kt * 64 + r) * HDIM + c * 8;
            cpa16(s, Kh + g);
            cpa16(s + AK_B, Kl + g);
        }
        #pragma unroll
        for (int i = 0; i < 4; ++i) {           // Vt: 128 rows x 8 chunks
            int idx = t + i * 256;
            int r = idx >> 3, c = idx & 7;
            uint32_t s = st + 2*AK_B + (uint32_t)r * AVSTR + c * 16;
            size_t g = headV + (size_t)r * SEQ + kt * 64 + c * 8;
            cpa16(s, Vth + g);
            cpa16(s + AV_B, Vtl + g);
        }
    };

    const uint32_t aLane  = (uint32_t)(wid * 16 + (lane & 15)) * AQSTR + ((lane >> 4) * 16);
    const uint32_t bLaneK = (uint32_t)((lane & 7) + ((lane >> 4) << 3)) * AQSTR
                          + (((lane >> 3) & 1) * 16);
    const uint32_t bLaneV = (uint32_t)((lane & 7) + ((lane >> 4) << 3)) * AVSTR
                          + (((lane >> 3) & 1) * 16);

    float oacc[16][4];
    #pragma unroll
    for (int i = 0; i < 16; ++i)
        #pragma unroll
        for (int j = 0; j < 4; ++j) oacc[i][j] = 0.f;
    float mrow0 = -1e30f, mrow1 = -1e30f, lrow0 = 0.f, lrow1 = 0.f;

    const int last = 2 * qt + 1;
    load_kv(0, 0); CP_COMMIT();

    #pragma unroll 1
    for (int kt = 0; kt <= last; ++kt) {
        if (kt < last) { load_kv((kt + 1) & 1, kt + 1); CP_COMMIT(); CP_WAIT1(); }
        else           { CP_WAIT0(); }
        __syncthreads();
        uint32_t st = sb + ASTG0 + (kt & 1) * ASTG_B;

        // ---- S = Q K^T (3-term) ----
        float sacc[8][4];
        #pragma unroll
        for (int i = 0; i < 8; ++i)
            #pragma unroll
            for (int j = 0; j < 4; ++j) sacc[i][j] = 0.f;

        #pragma unroll
        for (int j = 0; j < 8; ++j) {           // d k-steps
            uint32_t aH[4], aL[4];
            ldsm4(aH, sb + aLane + j * 32);
            ldsm4(aL, sb + AQ_B + aLane + j * 32);
            #pragma unroll
            for (int g = 0; g < 4; ++g) {       // s n-groups of 16
                uint32_t rH[4], rL[4];
                uint32_t bd = st + bLaneK + g * (16u * AQSTR) + j * 32;
                ldsm4(rH, bd);
                ldsm4(rL, bd + AK_B);
                mma16816(sacc[2*g],   aH, rH);
                mma16816(sacc[2*g],   aH, rL);
                mma16816(sacc[2*g],   aL, rH);
                mma16816(sacc[2*g+1], aH, rH + 2);
                mma16816(sacc[2*g+1], aH, rL + 2);
                mma16816(sacc[2*g+1], aL, rH + 2);
            }
        }

        // ---- causal mask (only near diagonal) ----
        if (kt >= 2 * qt) {
            int qlo = qt * 128 + wid * 16 + (lane >> 2);
            int c0 = kt * 64 + (lane & 3) * 2;
            #pragma unroll
            for (int nt = 0; nt < 8; ++nt)
                #pragma unroll
                for (int e = 0; e < 2; ++e) {
                    int col = c0 + nt * 8 + e;
                    if (col > qlo)     sacc[nt][e]     = -1e30f;
                    if (col > qlo + 8) sacc[nt][2 + e] = -1e30f;
                }
        }

        // ---- online softmax ----
        float mx0 = -1e30f, mx1 = -1e30f;
        #pragma unroll
        for (int nt = 0; nt < 8; ++nt) {
            mx0 = fmaxf(mx0, fmaxf(sacc[nt][0], sacc[nt][1]));
            mx1 = fmaxf(mx1, fmaxf(sacc[nt][2], sacc[nt][3]));
        }
        mx0 = fmaxf(mx0, __shfl_xor_sync(0xffffffffu, mx0, 1));
        mx0 = fmaxf(mx0, __shfl_xor_sync(0xffffffffu, mx0, 2));
        mx1 = fmaxf(mx1, __shfl_xor_sync(0xffffffffu, mx1, 1));
        mx1 = fmaxf(mx1, __shfl_xor_sync(0xffffffffu, mx1, 2));
        float mn0 = fmaxf(mrow0, mx0), mn1 = fmaxf(mrow1, mx1);
        float corr0 = ex2f((mrow0 - mn0) * SC2);
        float corr1 = ex2f((mrow1 - mn1) * SC2);

        float sum0 = 0.f, sum1 = 0.f;
        #pragma unroll
        for (int nt = 0; nt < 8; ++nt) {
            float p0 = ex2f((sacc[nt][0] - mn0) * SC2);
            float p1 = ex2f((sacc[nt][1] - mn0) * SC2);
            float p2 = ex2f((sacc[nt][2] - mn1) * SC2);
            float p3 = ex2f((sacc[nt][3] - mn1) * SC2);
            sum0 += p0 + p1; sum1 += p2 + p3;
            sacc[nt][0] = p0; sacc[nt][1] = p1; sacc[nt][2] = p2; sacc[nt][3] = p3;
        }
        sum0 += __shfl_xor_sync(0xffffffffu, sum0, 1);
        sum0 += __shfl_xor_sync(0xffffffffu, sum0, 2);
        sum1 += __shfl_xor_sync(0xffffffffu, sum1, 1);
        sum1 += __shfl_xor_sync(0xffffffffu, sum1, 2);
        lrow0 = lrow0 * corr0 + sum0;
        lrow1 = lrow1 * corr1 + sum1;
        mrow0 = mn0; mrow1 = mn1;

        #pragma unroll
        for (int nt = 0; nt < 16; ++nt) {
            oacc[nt][0] *= corr0; oacc[nt][1] *= corr0;
            oacc[nt][2] *= corr1; oacc[nt][3] *= corr1;
        }

        // ---- pack P into hi/lo A-fragments ----
        uint32_t pH[4][4], pL[4][4];
        #pragma unroll
        for (int j = 0; j < 4; ++j) {
            #pragma unroll
            for (int half = 0; half < 2; ++half) {
                int nt = 2*j + half;
                float v0 = sacc[nt][0], v1 = sacc[nt][1];
                float v2 = sacc[nt][2], v3 = sacc[nt][3];
                __nv_bfloat16 b0 = __float2bfloat16(v0), b1 = __float2bfloat16(v1);
                __nv_bfloat16 b2 = __float2bfloat16(v2), b3 = __float2bfloat16(v3);
                pH[j][2*half]   = pk2(__bfloat162float(b0), __bfloat162float(b1)) ;
                pH[j][2*half+1] = pk2(__bfloat162float(b2), __bfloat162float(b3));
                pL[j][2*half]   = pk2(v0 - __bfloat162float(b0), v1 - __bfloat162float(b1));
                pL[j][2*half+1] = pk2(v2 - __bfloat162float(b2), v3 - __bfloat162float(b3));
            }
        }

        // ---- O += P V (3-term) ----
        #pragma unroll
        for (int j = 0; j < 4; ++j) {           // s k-steps
            // rebuild fragment order: {a0,a1,a2,a3} = {ntile2j(c01), ntile2j(c23), ntile2j+1(c01), ntile2j+1(c23)}
            uint32_t aH[4] = {pH[j][0], pH[j][1], pH[j][2], pH[j][3]};
            uint32_t aL[4] = {pL[j][0], pL[j][1], pL[j][2], pL[j][3]};
            #pragma unroll
            for (int g = 0; g < 8; ++g) {       // d n-groups of 16
                uint32_t rH[4], rL[4];
                uint32_t bd = st + 2*AK_B + bLaneV + g * (16u * AVSTR) + j * 32;
                ldsm4(rH, bd);
                ldsm4(rL, bd + AV_B);
                mma16816(oacc[2*g],   aH, rH);
                mma16816(oacc[2*g],   aH, rL);
                mma16816(oacc[2*g],   aL, rH);
                mma16816(oacc[2*g+1], aH, rH + 2);
                mma16816(oacc[2*g+1], aH, rL + 2);
                mma16816(oacc[2*g+1], aL, rH + 2);
            }
        }
        __syncthreads();
    }

    // ---- epilogue: normalize, split hi/lo, store bf16 ----
    float inv0 = 1.f / lrow0, inv1 = 1.f / lrow1;
    size_t row0 = (size_t)b * SEQ + qt * 128 + wid * 16 + (lane >> 2);
    int colb = h * HDIM + (lane & 3) * 2;
    #pragma unroll
    for (int nt = 0; nt < 16; ++nt) {
        size_t o0 = row0 * DIN + colb + nt * 8;
        size_t o1 = (row0 + 8) * DIN + colb + nt * 8;
        float v0 = oacc[nt][0] * inv0, v1 = oacc[nt][1] * inv0;
        float v2 = oacc[nt][2] * inv1, v3 = oacc[nt][3] * inv1;
        __nv_bfloat16 h0 = __float2bfloat16(v0), h1 = __float2bfloat16(v1);
        __nv_bfloat16 h2 = __float2bfloat16(v2), h3 = __float2bfloat16(v3);
        *(__nv_bfloat162*)(Ohi + o0) = __nv_bfloat162(h0, h1);
        *(__nv_bfloat162*)(Ohi + o1) = __nv_bfloat162(h2, h3);
        *(__nv_bfloat162*)(Olo + o0) = __nv_bfloat162(
            __float2bfloat16(v0 - __bfloat162float(h0)),
            __float2bfloat16(v1 - __bfloat162float(h1)));
        *(__nv_bfloat162*)(Olo + o1) = __nv_bfloat162(
            __float2bfloat16(v2 - __bfloat162float(h2)),
            __float2bfloat16(v3 - __bfloat162float(h3)));
    }
}

// ============================================================================
// launch
// ============================================================================
extern "C" void kernel_launch(void* const* d_in, const int* in_sizes, int n_in,
                              void* d_out, int out_size)
{
    const float* x     = (const float*)d_in[0];
    const float* Wqkv  = (const float*)d_in[1];
    const float* Wproj = (const float*)d_in[2];
    float* out = (float*)d_out;

    float* qkv_ptr;
    cudaGetSymbolAddress((void**)&qkv_ptr, g_qkv);
    void *ahi, *alo, *bqh, *bql, *bph, *bpl;
    void *qh, *ql, *kh, *kl, *vth, *vtl;
    cudaGetSymbolAddress(&ahi, g_ahi);
    cudaGetSymbolAddress(&alo, g_alo);
    cudaGetSymbolAddress(&bqh, g_bqkv_hi);
    cudaGetSymbolAddress(&bql, g_bqkv_lo);
    cudaGetSymbolAddress(&bph, g_bproj_hi);
    cudaGetSymbolAddress(&bpl, g_bproj_lo);
    cudaGetSymbolAddress(&qh, g_Qh);
    cudaGetSymbolAddress(&ql, g_Ql);
    cudaGetSymbolAddress(&kh, g_Kh);
    cudaGetSymbolAddress(&kl, g_Kl);
    cudaGetSymbolAddress(&vth, g_Vth);
    cudaGetSymbolAddress(&vtl, g_Vtl);

    static bool attr_done = false;
    if (!attr_done) {
        cudaFuncSetAttribute(gemm_mma, cudaFuncAttributeMaxDynamicSharedMemorySize, GEMM_SMEM);
        cudaFuncSetAttribute(attn_mma, cudaFuncAttributeMaxDynamicSharedMemorySize, ATT_SMEM);
        attr_done = true;
    }

    freq_kernel<<<(SEQ * HPAIR + 255) / 256, 256>>>();

    {
        dim3 blk(32, 8);
        transpose_split<<<dim3(QKVN / 32, KDIM / 32), blk>>>(Wqkv, (__nv_bfloat16*)bqh, (__nv_bfloat16*)bql, KDIM, QKVN);
        transpose_split<<<dim3(DIN / 32, KDIM / 32), blk>>>(Wproj, (__nv_bfloat16*)bph, (__nv_bfloat16*)bpl, KDIM, DIN);
    }

    {
        int n4 = MROWS * KDIM / 4;
        split_kernel<<<(n4 + 255) / 256, 256>>>(x, (__nv_bfloat16*)ahi, (__nv_bfloat16*)alo, n4);
    }

    // GEMM1: qkv = x @ Wqkv
    {
        dim3 grid(QKVN / 128, MROWS / 128);
        gemm_mma<<<grid, 256, GEMM_SMEM>>>((const __nv_bfloat16*)ahi, (const __nv_bfloat16*)alo,
                                           (const __nv_bfloat16*)bqh, (const __nv_bfloat16*)bql,
                                           qkv_ptr, QKVN);
    }

    // rope + split Q/K, transpose+split V
    {
        int total = BATCH * SEQ * NHEAD * HPAIR;
        ropesplit_kernel<<<(total + 255) / 256, 256>>>(qkv_ptr);
        dim3 blk(32, 8);
        vsplit_kernel<<<dim3(SEQ / 32, HDIM / 32, BATCH * NHEAD), blk>>>(qkv_ptr);
    }

    // attention (HMMA) -> writes bf16 hi/lo straight into GEMM2 A buffers
    {
        dim3 grid(SEQ / 128, NHEAD, BATCH);
        attn_mma<<<grid, 256, ATT_SMEM>>>(
            (const __nv_bfloat16*)qh, (const __nv_bfloat16*)ql,
            (const __nv_bfloat16*)kh, (const __nv_bfloat16*)kl,
            (const __nv_bfloat16*)vth, (const __nv_bfloat16*)vtl,
            (__nv_bfloat16*)ahi, (__nv_bfloat16*)alo);
    }

    // GEMM2: out = att @ Wproj
    {
        dim3 grid(DIN / 128, MROWS / 128);
        gemm_mma<<<grid, 256, GEMM_SMEM>>>((const __nv_bfloat16*)ahi, (const __nv_bfloat16*)alo,
                                           (const __nv_bfloat16*)bph, (const __nv_bfloat16*)bpl,
                                           out, DIN);
    }
}

// round 7
// speedup vs baseline: 2.8985x; 1.0077x over previous
#include <cuda_runtime.h>
#include <cuda_bf16.h>
#include <math.h>
#include <stdint.h>

#define BATCH 2
#define SEQ   2048
#define DIN   2048
#define NHEAD 16
#define HDIM  128
#define HPAIR (HDIM/2)
#define MROWS (BATCH*SEQ)       // 4096
#define QKVN  (3*DIN)           // 6144
#define KDIM  2048

// ---------------- scratch (device globals; no allocs allowed) ----------------
__device__ float g_qkv[(size_t)MROWS * QKVN];   // 96 MB
__device__ float g_cos[SEQ * HPAIR];
__device__ float g_sin[SEQ * HPAIR];

__device__ __align__(128) __nv_bfloat16 g_ahi[(size_t)MROWS * KDIM];
__device__ __align__(128) __nv_bfloat16 g_alo[(size_t)MROWS * KDIM];
__device__ __align__(128) __nv_bfloat16 g_bqkv_hi[(size_t)QKVN * KDIM];
__device__ __align__(128) __nv_bfloat16 g_bqkv_lo[(size_t)QKVN * KDIM];
__device__ __align__(128) __nv_bfloat16 g_bproj_hi[(size_t)DIN * KDIM];
__device__ __align__(128) __nv_bfloat16 g_bproj_lo[(size_t)DIN * KDIM];

// attention operands, bf16 hi/lo, rope applied
__device__ __align__(128) __nv_bfloat16 g_Qh[(size_t)BATCH*NHEAD*SEQ*HDIM];
__device__ __align__(128) __nv_bfloat16 g_Ql[(size_t)BATCH*NHEAD*SEQ*HDIM];
__device__ __align__(128) __nv_bfloat16 g_Kh[(size_t)BATCH*NHEAD*SEQ*HDIM];
__device__ __align__(128) __nv_bfloat16 g_Kl[(size_t)BATCH*NHEAD*SEQ*HDIM];
__device__ __align__(128) __nv_bfloat16 g_Vth[(size_t)BATCH*NHEAD*HDIM*SEQ];  // [b,h,d,s]
__device__ __align__(128) __nv_bfloat16 g_Vtl[(size_t)BATCH*NHEAD*HDIM*SEQ];

// ---------------- PTX helpers (all base-ISA, no 'a' features) ----------------
__device__ __forceinline__ uint32_t smem_u32(const void* p) {
    uint32_t a;
    asm("{ .reg .u64 t; cvta.to.shared.u64 t, %1; cvt.u32.u64 %0, t; }" : "=r"(a) : "l"(p));
    return a;
}
__device__ __forceinline__ void cpa16(uint32_t s, const void* g) {
    asm volatile("cp.async.cg.shared.global [%0], [%1], 16;" :: "r"(s), "l"(g));
}
#define CP_COMMIT() asm volatile("cp.async.commit_group;" ::: "memory")
#define CP_WAIT1()  asm volatile("cp.async.wait_group 1;" ::: "memory")
#define CP_WAIT0()  asm volatile("cp.async.wait_group 0;" ::: "memory")

__device__ __forceinline__ void ldsm4(uint32_t* r, uint32_t addr) {
    asm volatile("ldmatrix.sync.aligned.m8n8.x4.shared.b16 {%0,%1,%2,%3}, [%4];"
                 : "=r"(r[0]), "=r"(r[1]), "=r"(r[2]), "=r"(r[3]) : "r"(addr));
}
__device__ __forceinline__ void mma16816(float* c, const uint32_t* a, const uint32_t* b) {
    asm volatile(
        "mma.sync.aligned.m16n8k16.row.col.f32.bf16.bf16.f32 "
        "{%0,%1,%2,%3}, {%4,%5,%6,%7}, {%8,%9}, {%0,%1,%2,%3};"
        : "+f"(c[0]), "+f"(c[1]), "+f"(c[2]), "+f"(c[3])
        : "r"(a[0]), "r"(a[1]), "r"(a[2]), "r"(a[3]), "r"(b[0]), "r"(b[1]));
}
__device__ __forceinline__ float ex2f(float x) {
    float y;
    asm("ex2.approx.f32 %0, %1;" : "=f"(y) : "f"(x));
    return y;
}
__device__ __forceinline__ uint32_t pk2(float a, float b) {
    __nv_bfloat162 t = __floats2bfloat162_rn(a, b);
    return *(uint32_t*)&t;
}

// ============================================================================
// prep kernels
// ============================================================================
__global__ void freq_kernel() {
    int t = blockIdx.x * blockDim.x + threadIdx.x;
    if (t >= SEQ * HPAIR) return;
    int s = t >> 6;
    int p = t & 63;
    float inv = (float)(1.0 / pow(10000.0, (double)(2 * p) / (double)HDIM));
    float ang = (float)s * inv;
    float sn, cs;
    sincosf(ang, &sn, &cs);
    g_cos[t] = cs;
    g_sin[t] = sn;
}

// rope + hi/lo split of Q,K into per-head layouts
__global__ void ropesplit_kernel(const float* __restrict__ qkv) {
    int t = blockIdx.x * blockDim.x + threadIdx.x;
    if (t >= BATCH * SEQ * NHEAD * HPAIR) return;
    int p = t & 63;
    int h = (t >> 6) & (NHEAD - 1);
    int s = (t >> 10) & (SEQ - 1);
    int b = t >> 21;
    float c  = g_cos[s * HPAIR + p];
    float sn = g_sin[s * HPAIR + p];
    size_t src = (size_t)(b * SEQ + s) * QKVN + h * HDIM + 2 * p;
    size_t dst = ((size_t)(b * NHEAD + h) * SEQ + s) * HDIM + 2 * p;
    // q
    float q1 = qkv[src], q2 = qkv[src + 1];
    float r1 = q1 * c - q2 * sn;
    float r2 = q1 * sn + q2 * c;
    __nv_bfloat16 h1 = __float2bfloat16(r1), h2 = __float2bfloat16(r2);
    *(__nv_bfloat162*)(g_Qh + dst) = __nv_bfloat162(h1, h2);
    *(__nv_bfloat162*)(g_Ql + dst) = __nv_bfloat162(
        __float2bfloat16(r1 - __bfloat162float(h1)),
        __float2bfloat16(r2 - __bfloat162float(h2)));
    // k
    float k1 = qkv[src + DIN], k2 = qkv[src + DIN + 1];
    r1 = k1 * c - k2 * sn;
    r2 = k1 * sn + k2 * c;
    h1 = __float2bfloat16(r1); h2 = __float2bfloat16(r2);
    *(__nv_bfloat162*)(g_Kh + dst) = __nv_bfloat162(h1, h2);
    *(__nv_bfloat162*)(g_Kl + dst) = __nv_bfloat162(
        __float2bfloat16(r1 - __bfloat162float(h1)),
        __float2bfloat16(r2 - __bfloat162float(h2)));
}

// V: per-head transpose [s][d] -> [d][s] with hi/lo split
__global__ void vsplit_kernel(const float* __restrict__ qkv) {
    __shared__ float tile[32][33];
    int s0 = blockIdx.x * 32, d0 = blockIdx.y * 32, bh = blockIdx.z;
    int b = bh >> 4, h = bh & 15;
    int tx = threadIdx.x, ty = threadIdx.y;     // (32,8)
    #pragma unroll
    for (int j = 0; j < 4; ++j)
        tile[ty + j*8][tx] = qkv[(size_t)(b * SEQ + s0 + ty + j*8) * QKVN + 2*DIN + h * HDIM + d0 + tx];
    __syncthreads();
    #pragma unroll
    for (int j = 0; j < 4; ++j) {
        int dl = ty + j*8;
        float v = tile[tx][dl];
        __nv_bfloat16 hh = __float2bfloat16(v);
        size_t o = ((size_t)bh * HDIM + d0 + dl) * SEQ + s0 + tx;
        g_Vth[o] = hh;
        g_Vtl[o] = __float2bfloat16(v - __bfloat162float(hh));
    }
}

__global__ void split_kernel(const float* __restrict__ src,
                             __nv_bfloat16* __restrict__ hi,
                             __nv_bfloat16* __restrict__ lo, int n4) {
    int i = blockIdx.x * blockDim.x + threadIdx.x;
    if (i >= n4) return;
    float4 v = ((const float4*)src)[i];
    __nv_bfloat16 h0 = __float2bfloat16(v.x), h1 = __float2bfloat16(v.y);
    __nv_bfloat16 h2 = __float2bfloat16(v.z), h3 = __float2bfloat16(v.w);
    ((__nv_bfloat162*)hi)[2*i]   = __nv_bfloat162(h0, h1);
    ((__nv_bfloat162*)hi)[2*i+1] = __nv_bfloat162(h2, h3);
    ((__nv_bfloat162*)lo)[2*i]   = __nv_bfloat162(__float2bfloat16(v.x - __bfloat162float(h0)),
                                                  __float2bfloat16(v.y - __bfloat162float(h1)));
    ((__nv_bfloat162*)lo)[2*i+1] = __nv_bfloat162(__float2bfloat16(v.z - __bfloat162float(h2)),
                                                  __float2bfloat16(v.w - __bfloat162float(h3)));
}

__global__ void transpose_split(const float* __restrict__ in,
                                __nv_bfloat16* __restrict__ hi,
                                __nv_bfloat16* __restrict__ lo, int K, int N) {
    __shared__ float t[32][33];
    int n0 = blockIdx.x * 32, k0 = blockIdx.y * 32;
    int tx = threadIdx.x, ty = threadIdx.y;
    #pragma unroll
    for (int j = 0; j < 4; ++j)
        t[ty + j*8][tx] = in[(size_t)(k0 + ty + j*8) * N + n0 + tx];
    __syncthreads();
    #pragma unroll
    for (int j = 0; j < 4; ++j) {
        int n = ty + j*8;
        float v = t[tx][n];
        __nv_bfloat16 h = __float2bfloat16(v);
        size_t o = (size_t)(n0 + n) * K + k0 + tx;
        hi[o] = h;
        lo[o] = __float2bfloat16(v - __bfloat162float(h));
    }
}

// ============================================================================
// HMMA GEMM v2: BM=256, BN=128, BK=32, 512 threads (16 warps, 64x32 per warp).
// 3-stage cp.async pipeline; 3-term bf16 hi/lo split.
// Stage: Ahi/Alo 256x32 + Bhi/Blo 128x32 (80B rows) = 61440 B; 131 FLOP/B.
// ============================================================================
#define G2STR    80
#define G2_ALO   20480
#define G2_BHI   40960
#define G2_BLO   51200
#define G2_STAGE 61440
#define G2_NST   3
#define GEMM_SMEM (G2_NST * G2_STAGE)   // 184320
#define KT_TOT (KDIM / 32)              // 64

__global__ __launch_bounds__(512) void gemm_mma(
    const __nv_bfloat16* __restrict__ Ahi, const __nv_bfloat16* __restrict__ Alo,
    const __nv_bfloat16* __restrict__ Bhi, const __nv_bfloat16* __restrict__ Blo,
    float* __restrict__ C, int Ntot)
{
    extern __shared__ char smem_raw[];
    uint32_t sb = smem_u32(smem_raw);
    const int t = threadIdx.x, lane = t & 31, wid = t >> 5;
    const int m0 = blockIdx.y * 256, n0 = blockIdx.x * 128;
    const int mW = (wid & 3) * 64, nW = (wid >> 2) * 32;

    // cp.async mapping: row r = t>>2 (0..127), chunk ch = t&3 (16B each)
    const int rL = t >> 2, ch = t & 3;
    const uint32_t soff = (uint32_t)rL * G2STR + ch * 16;
    const __nv_bfloat16* gAhi = Ahi + (size_t)(m0 + rL) * KDIM + ch * 8;
    const __nv_bfloat16* gAlo = Alo + (size_t)(m0 + rL) * KDIM + ch * 8;
    const __nv_bfloat16* gBhi = Bhi + (size_t)(n0 + rL) * KDIM + ch * 8;
    const __nv_bfloat16* gBlo = Blo + (size_t)(n0 + rL) * KDIM + ch * 8;

    float acc[4][4][4];
    #pragma unroll
    for (int i = 0; i < 4; ++i)
        #pragma unroll
        for (int j = 0; j < 4; ++j)
            #pragma unroll
            for (int q = 0; q < 4; ++q) acc[i][j][q] = 0.f;

    auto load_stage = [&](int slot, int kt) {
        uint32_t s = sb + slot * G2_STAGE + soff;
        int g = kt * 32;
        cpa16(s,                            gAhi + g);
        cpa16(s + 128u * G2STR,             gAhi + g + (size_t)128 * KDIM);
        cpa16(s + G2_ALO,                   gAlo + g);
        cpa16(s + G2_ALO + 128u * G2STR,    gAlo + g + (size_t)128 * KDIM);
        cpa16(s + G2_BHI,                   gBhi + g);
        cpa16(s + G2_BLO,                   gBlo + g);
    };

    const uint32_t aLane = (uint32_t)(mW + (lane & 15)) * G2STR + ((lane >> 4) * 16);
    const uint32_t bLane = (uint32_t)(nW + (lane & 7) + ((lane >> 4) << 3)) * G2STR
                         + (((lane >> 3) & 1) * 16);

    auto compute_stage = [&](int slot) {
        uint32_t base = sb + slot * G2_STAGE;
        #pragma unroll
        for (int kk = 0; kk < 2; ++kk) {
            uint32_t koff = kk * 32;
            uint32_t aH[4][4], aL[4][4];
            #pragma unroll
            for (int mt = 0; mt < 4; ++mt) {
                uint32_t ad = base + aLane + mt * (16u * G2STR) + koff;
                ldsm4(aH[mt], ad);
                ldsm4(aL[mt], ad + G2_ALO);
            }
            #pragma unroll
            for (int p = 0; p < 2; ++p) {
                uint32_t rH[4], rL4[4];
                uint32_t bd = base + G2_BHI + bLane + p * (16u * G2STR) + koff;
                ldsm4(rH, bd);
                ldsm4(rL4, bd + (G2_BLO - G2_BHI));
                #pragma unroll
                for (int mt = 0; mt < 4; ++mt) {
                    mma16816(acc[mt][2*p],   aH[mt], rH);
                    mma16816(acc[mt][2*p],   aH[mt], rL4);
                    mma16816(acc[mt][2*p],   aL[mt], rH);
                    mma16816(acc[mt][2*p+1], aH[mt], rH + 2);
                    mma16816(acc[mt][2*p+1], aH[mt], rL4 + 2);
                    mma16816(acc[mt][2*p+1], aL[mt], rH + 2);
                }
            }
        }
    };

    load_stage(0, 0); CP_COMMIT();
    load_stage(1, 1); CP_COMMIT();
    #pragma unroll 1
    for (int kt = 0; kt < KT_TOT; ++kt) {
        CP_WAIT1();
        __syncthreads();
        if (kt + 2 < KT_TOT) load_stage((kt + 2) % G2_NST, kt + 2);
        CP_COMMIT();
        compute_stage(kt % G2_NST);
        __syncthreads();
    }

    #pragma unroll
    for (int mt = 0; mt < 4; ++mt)
        #pragma unroll
        for (int nt = 0; nt < 4; ++nt) {
            int r = m0 + mW + mt * 16 + (lane >> 2);
            int c = n0 + nW + nt * 8 + (lane & 3) * 2;
            *(float2*)(C + (size_t)r * Ntot + c)       = make_float2(acc[mt][nt][0], acc[mt][nt][1]);
            *(float2*)(C + (size_t)(r + 8) * Ntot + c) = make_float2(acc[mt][nt][2], acc[mt][nt][3]);
        }
}

// ============================================================================
// HMMA flash attention (unchanged from R5, proven: ~644 TF/s effective)
// ============================================================================
#define AQSTR   272
#define AVSTR   144
#define AQ_B    (128 * AQSTR)
#define AK_B    (64 * AQSTR)
#define AV_B    (128 * AVSTR)
#define ASTG_B  (2*AK_B + 2*AV_B)
#define ASTG0   (2 * AQ_B)
#define ATT_SMEM (ASTG0 + 2 * ASTG_B)

__global__ __launch_bounds__(256, 1) void attn_mma(
    const __nv_bfloat16* __restrict__ Qh, const __nv_bfloat16* __restrict__ Ql,
    const __nv_bfloat16* __restrict__ Kh, const __nv_bfloat16* __restrict__ Kl,
    const __nv_bfloat16* __restrict__ Vth, const __nv_bfloat16* __restrict__ Vtl,
    __nv_bfloat16* __restrict__ Ohi, __nv_bfloat16* __restrict__ Olo)
{
    extern __shared__ char smr[];
    uint32_t sb = smem_u32(smr);
    const int qt = (gridDim.x - 1) - blockIdx.x;
    const int h = blockIdx.y, b = blockIdx.z;
    const int t = threadIdx.x, lane = t & 31, wid = t >> 5;
    const int bh = b * NHEAD + h;
    const size_t headQK = (size_t)bh * SEQ * HDIM;
    const size_t headV  = (size_t)bh * HDIM * SEQ;
    const float SC2 = 0.08838834764831845f * 1.4426950408889634f;

    #pragma unroll
    for (int i = 0; i < 8; ++i) {
        int idx = t + i * 256;
        int r = idx >> 4, c = idx & 15;
        uint32_t s = sb + (uint32_t)r * AQSTR + c * 16;
        size_t g = headQK + (size_t)(qt * 128 + r) * HDIM + c * 8;
        cpa16(s, Qh + g);
        cpa16(s + AQ_B, Ql + g);
    }

    auto load_kv = [&](int slot, int kt) {
        uint32_t st = sb + ASTG0 + slot * ASTG_B;
        #pragma unroll
        for (int i = 0; i < 4; ++i) {
            int idx = t + i * 256;
            int r = idx >> 4, c = idx & 15;
            uint32_t s = st + (uint32_t)r * AQSTR + c * 16;
            size_t g = headQK + (size_t)(kt * 64 + r) * HDIM + c * 8;
            cpa16(s, Kh + g);
            cpa16(s + AK_B, Kl + g);
        }
        #pragma unroll
        for (int i = 0; i < 4; ++i) {
            int idx = t + i * 256;
            int r = idx >> 3, c = idx & 7;
            uint32_t s = st + 2*AK_B + (uint32_t)r * AVSTR + c * 16;
            size_t g = headV + (size_t)r * SEQ + kt * 64 + c * 8;
            cpa16(s, Vth + g);
            cpa16(s + AV_B, Vtl + g);
        }
    };

    const uint32_t aLane  = (uint32_t)(wid * 16 + (lane & 15)) * AQSTR + ((lane >> 4) * 16);
    const uint32_t bLaneK = (uint32_t)((lane & 7) + ((lane >> 4) << 3)) * AQSTR
                          + (((lane >> 3) & 1) * 16);
    const uint32_t bLaneV = (uint32_t)((lane & 7) + ((lane >> 4) << 3)) * AVSTR
                          + (((lane >> 3) & 1) * 16);

    float oacc[16][4];
    #pragma unroll
    for (int i = 0; i < 16; ++i)
        #pragma unroll
        for (int j = 0; j < 4; ++j) oacc[i][j] = 0.f;
    float mrow0 = -1e30f, mrow1 = -1e30f, lrow0 = 0.f, lrow1 = 0.f;

    const int last = 2 * qt + 1;
    load_kv(0, 0); CP_COMMIT();

    #pragma unroll 1
    for (int kt = 0; kt <= last; ++kt) {
        if (kt < last) { load_kv((kt + 1) & 1, kt + 1); CP_COMMIT(); CP_WAIT1(); }
        else           { CP_WAIT0(); }
        __syncthreads();
        uint32_t st = sb + ASTG0 + (kt & 1) * ASTG_B;

        float sacc[8][4];
        #pragma unroll
        for (int i = 0; i < 8; ++i)
            #pragma unroll
            for (int j = 0; j < 4; ++j) sacc[i][j] = 0.f;

        #pragma unroll
        for (int j = 0; j < 8; ++j) {
            uint32_t aH[4], aL[4];
            ldsm4(aH, sb + aLane + j * 32);
            ldsm4(aL, sb + AQ_B + aLane + j * 32);
            #pragma unroll
            for (int g = 0; g < 4; ++g) {
                uint32_t rH[4], rL[4];
                uint32_t bd = st + bLaneK + g * (16u * AQSTR) + j * 32;
                ldsm4(rH, bd);
                ldsm4(rL, bd + AK_B);
                mma16816(sacc[2*g],   aH, rH);
                mma16816(sacc[2*g],   aH, rL);
                mma16816(sacc[2*g],   aL, rH);
                mma16816(sacc[2*g+1], aH, rH + 2);
                mma16816(sacc[2*g+1], aH, rL + 2);
                mma16816(sacc[2*g+1], aL, rH + 2);
            }
        }

        if (kt >= 2 * qt) {
            int qlo = qt * 128 + wid * 16 + (lane >> 2);
            int c0 = kt * 64 + (lane & 3) * 2;
            #pragma unroll
            for (int nt = 0; nt < 8; ++nt)
                #pragma unroll
                for (int e = 0; e < 2; ++e) {
                    int col = c0 + nt * 8 + e;
                    if (col > qlo)     sacc[nt][e]     = -1e30f;
                    if (col > qlo + 8) sacc[nt][2 + e] = -1e30f;
                }
        }

        float mx0 = -1e30f, mx1 = -1e30f;
        #pragma unroll
        for (int nt = 0; nt < 8; ++nt) {
            mx0 = fmaxf(mx0, fmaxf(sacc[nt][0], sacc[nt][1]));
            mx1 = fmaxf(mx1, fmaxf(sacc[nt][2], sacc[nt][3]));
        }
        mx0 = fmaxf(mx0, __shfl_xor_sync(0xffffffffu, mx0, 1));
        mx0 = fmaxf(mx0, __shfl_xor_sync(0xffffffffu, mx0, 2));
        mx1 = fmaxf(mx1, __shfl_xor_sync(0xffffffffu, mx1, 1));
        mx1 = fmaxf(mx1, __shfl_xor_sync(0xffffffffu, mx1, 2));
        float mn0 = fmaxf(mrow0, mx0), mn1 = fmaxf(mrow1, mx1);
        float corr0 = ex2f((mrow0 - mn0) * SC2);
        float corr1 = ex2f((mrow1 - mn1) * SC2);

        float sum0 = 0.f, sum1 = 0.f;
        #pragma unroll
        for (int nt = 0; nt < 8; ++nt) {
            float p0 = ex2f((sacc[nt][0] - mn0) * SC2);
            float p1 = ex2f((sacc[nt][1] - mn0) * SC2);
            float p2 = ex2f((sacc[nt][2] - mn1) * SC2);
            float p3 = ex2f((sacc[nt][3] - mn1) * SC2);
            sum0 += p0 + p1; sum1 += p2 + p3;
            sacc[nt][0] = p0; sacc[nt][1] = p1; sacc[nt][2] = p2; sacc[nt][3] = p3;
        }
        sum0 += __shfl_xor_sync(0xffffffffu, sum0, 1);
        sum0 += __shfl_xor_sync(0xffffffffu, sum0, 2);
        sum1 += __shfl_xor_sync(0xffffffffu, sum1, 1);
        sum1 += __shfl_xor_sync(0xffffffffu, sum1, 2);
        lrow0 = lrow0 * corr0 + sum0;
        lrow1 = lrow1 * corr1 + sum1;
        mrow0 = mn0; mrow1 = mn1;

        #pragma unroll
        for (int nt = 0; nt < 16; ++nt) {
            oacc[nt][0] *= corr0; oacc[nt][1] *= corr0;
            oacc[nt][2] *= corr1; oacc[nt][3] *= corr1;
        }

        uint32_t pH[4][4], pL[4][4];
        #pragma unroll
        for (int j = 0; j < 4; ++j) {
            #pragma unroll
            for (int half = 0; half < 2; ++half) {
                int nt = 2*j + half;
                float v0 = sacc[nt][0], v1 = sacc[nt][1];
                float v2 = sacc[nt][2], v3 = sacc[nt][3];
                __nv_bfloat16 b0 = __float2bfloat16(v0), b1 = __float2bfloat16(v1);
                __nv_bfloat16 b2 = __float2bfloat16(v2), b3 = __float2bfloat16(v3);
                pH[j][2*half]   = pk2(__bfloat162float(b0), __bfloat162float(b1));
                pH[j][2*half+1] = pk2(__bfloat162float(b2), __bfloat162float(b3));
                pL[j][2*half]   = pk2(v0 - __bfloat162float(b0), v1 - __bfloat162float(b1));
                pL[j][2*half+1] = pk2(v2 - __bfloat162float(b2), v3 - __bfloat162float(b3));
            }
        }

        #pragma unroll
        for (int j = 0; j < 4; ++j) {
            uint32_t aH[4] = {pH[j][0], pH[j][1], pH[j][2], pH[j][3]};
            uint32_t aL[4] = {pL[j][0], pL[j][1], pL[j][2], pL[j][3]};
            #pragma unroll
            for (int g = 0; g < 8; ++g) {
                uint32_t rH[4], rL[4];
                uint32_t bd = st + 2*AK_B + bLaneV + g * (16u * AVSTR) + j * 32;
                ldsm4(rH, bd);
                ldsm4(rL, bd + AV_B);
                mma16816(oacc[2*g],   aH, rH);
                mma16816(oacc[2*g],   aH, rL);
                mma16816(oacc[2*g],   aL, rH);
                mma16816(oacc[2*g+1], aH, rH + 2);
                mma16816(oacc[2*g+1], aH, rL + 2);
                mma16816(oacc[2*g+1], aL, rH + 2);
            }
        }
        __syncthreads();
    }

    float inv0 = 1.f / lrow0, inv1 = 1.f / lrow1;
    size_t row0 = (size_t)b * SEQ + qt * 128 + wid * 16 + (lane >> 2);
    int colb = h * HDIM + (lane & 3) * 2;
    #pragma unroll
    for (int nt = 0; nt < 16; ++nt) {
        size_t o0 = row0 * DIN + colb + nt * 8;
        size_t o1 = (row0 + 8) * DIN + colb + nt * 8;
        float v0 = oacc[nt][0] * inv0, v1 = oacc[nt][1] * inv0;
        float v2 = oacc[nt][2] * inv1, v3 = oacc[nt][3] * inv1;
        __nv_bfloat16 h0 = __float2bfloat16(v0), h1 = __float2bfloat16(v1);
        __nv_bfloat16 h2 = __float2bfloat16(v2), h3 = __float2bfloat16(v3);
        *(__nv_bfloat162*)(Ohi + o0) = __nv_bfloat162(h0, h1);
        *(__nv_bfloat162*)(Ohi + o1) = __nv_bfloat162(h2, h3);
        *(__nv_bfloat162*)(Olo + o0) = __nv_bfloat162(
            __float2bfloat16(v0 - __bfloat162float(h0)),
            __float2bfloat16(v1 - __bfloat162float(h1)));
        *(__nv_bfloat162*)(Olo + o1) = __nv_bfloat162(
            __float2bfloat16(v2 - __bfloat162float(h2)),
            __float2bfloat16(v3 - __bfloat162float(h3)));
    }
}

// ============================================================================
// launch
// ============================================================================
extern "C" void kernel_launch(void* const* d_in, const int* in_sizes, int n_in,
                              void* d_out, int out_size)
{
    const float* x     = (const float*)d_in[0];
    const float* Wqkv  = (const float*)d_in[1];
    const float* Wproj = (const float*)d_in[2];
    float* out = (float*)d_out;

    float* qkv_ptr;
    cudaGetSymbolAddress((void**)&qkv_ptr, g_qkv);
    void *ahi, *alo, *bqh, *bql, *bph, *bpl;
    void *qh, *ql, *kh, *kl, *vth, *vtl;
    cudaGetSymbolAddress(&ahi, g_ahi);
    cudaGetSymbolAddress(&alo, g_alo);
    cudaGetSymbolAddress(&bqh, g_bqkv_hi);
    cudaGetSymbolAddress(&bql, g_bqkv_lo);
    cudaGetSymbolAddress(&bph, g_bproj_hi);
    cudaGetSymbolAddress(&bpl, g_bproj_lo);
    cudaGetSymbolAddress(&qh, g_Qh);
    cudaGetSymbolAddress(&ql, g_Ql);
    cudaGetSymbolAddress(&kh, g_Kh);
    cudaGetSymbolAddress(&kl, g_Kl);
    cudaGetSymbolAddress(&vth, g_Vth);
    cudaGetSymbolAddress(&vtl, g_Vtl);

    static bool attr_done = false;
    if (!attr_done) {
        cudaFuncSetAttribute(gemm_mma, cudaFuncAttributeMaxDynamicSharedMemorySize, GEMM_SMEM);
        cudaFuncSetAttribute(attn_mma, cudaFuncAttributeMaxDynamicSharedMemorySize, ATT_SMEM);
        attr_done = true;
    }

    // launches 0-2
    freq_kernel<<<(SEQ * HPAIR + 255) / 256, 256>>>();
    {
        dim3 blk(32, 8);
        transpose_split<<<dim3(QKVN / 32, KDIM / 32), blk>>>(Wqkv, (__nv_bfloat16*)bqh, (__nv_bfloat16*)bql, KDIM, QKVN);
        transpose_split<<<dim3(DIN / 32, KDIM / 32), blk>>>(Wproj, (__nv_bfloat16*)bph, (__nv_bfloat16*)bpl, KDIM, DIN);
    }

    // launches 3-4: split x in two halves (also positions gemm_mma at launch index 5 for ncu -s 5)
    {
        int n4 = MROWS * KDIM / 4;
        int half = n4 / 2;
        split_kernel<<<(half + 255) / 256, 256>>>(x, (__nv_bfloat16*)ahi, (__nv_bfloat16*)alo, half);
        split_kernel<<<(half + 255) / 256, 256>>>(x + (size_t)half * 4,
                                                  (__nv_bfloat16*)ahi + (size_t)half * 4,
                                                  (__nv_bfloat16*)alo + (size_t)half * 4, half);
    }

    // launch 5: GEMM1 qkv = x @ Wqkv
    {
        dim3 grid(QKVN / 128, MROWS / 256);
        gemm_mma<<<grid, 512, GEMM_SMEM>>>((const __nv_bfloat16*)ahi, (const __nv_bfloat16*)alo,
                                           (const __nv_bfloat16*)bqh, (const __nv_bfloat16*)bql,
                                           qkv_ptr, QKVN);
    }

    // rope + split Q/K, transpose+split V
    {
        int total = BATCH * SEQ * NHEAD * HPAIR;
        ropesplit_kernel<<<(total + 255) / 256, 256>>>(qkv_ptr);
        dim3 blk(32, 8);
        vsplit_kernel<<<dim3(SEQ / 32, HDIM / 32, BATCH * NHEAD), blk>>>(qkv_ptr);
    }

    // attention (HMMA) -> writes bf16 hi/lo straight into GEMM2 A buffers
    {
        dim3 grid(SEQ / 128, NHEAD, BATCH);
        attn_mma<<<grid, 256, ATT_SMEM>>>(
            (const __nv_bfloat16*)qh, (const __nv_bfloat16*)ql,
            (const __nv_bfloat16*)kh, (const __nv_bfloat16*)kl,
            (const __nv_bfloat16*)vth, (const __nv_bfloat16*)vtl,
            (__nv_bfloat16*)ahi, (__nv_bfloat16*)alo);
    }

    // GEMM2: out = att @ Wproj
    {
        dim3 grid(DIN / 128, MROWS / 256);
        gemm_mma<<<grid, 512, GEMM_SMEM>>>((const __nv_bfloat16*)ahi, (const __nv_bfloat16*)alo,
                                           (const __nv_bfloat16*)bph, (const __nv_bfloat16*)bpl,
                                           out, DIN);
    }
}

// round 8
// speedup vs baseline: 4.1004x; 1.4147x over previous
#include <cuda_runtime.h>
#include <cuda_fp16.h>
#include <math.h>
#include <stdint.h>

#define BATCH 2
#define SEQ   2048
#define DIN   2048
#define NHEAD 16
#define HDIM  128
#define HPAIR (HDIM/2)
#define MROWS (BATCH*SEQ)       // 4096
#define QKVN  (3*DIN)           // 6144
#define KDIM  2048

// ---------------- scratch (device globals; no allocs allowed) ----------------
__device__ float g_qkv[(size_t)MROWS * QKVN];   // 96 MB
__device__ float g_cos[SEQ * HPAIR];
__device__ float g_sin[SEQ * HPAIR];

// fp16 operand buffers: activations split hi/lo, weights single
__device__ __align__(128) __half g_ahi[(size_t)MROWS * KDIM];
__device__ __align__(128) __half g_alo[(size_t)MROWS * KDIM];
__device__ __align__(128) __half g_bqkv[(size_t)QKVN * KDIM];    // Wqkv^T [6144][2048]
__device__ __align__(128) __half g_bproj[(size_t)DIN * KDIM];    // Wproj^T [2048][2048]

// attention operands (rope applied): Q split hi/lo, K/V single
__device__ __align__(128) __half g_Qh[(size_t)BATCH*NHEAD*SEQ*HDIM];
__device__ __align__(128) __half g_Ql[(size_t)BATCH*NHEAD*SEQ*HDIM];
__device__ __align__(128) __half g_Kh[(size_t)BATCH*NHEAD*SEQ*HDIM];
__device__ __align__(128) __half g_Vth[(size_t)BATCH*NHEAD*HDIM*SEQ];  // [b,h,d,s]

// ---------------- PTX helpers (all base-ISA, no 'a' features) ----------------
__device__ __forceinline__ uint32_t smem_u32(const void* p) {
    uint32_t a;
    asm("{ .reg .u64 t; cvta.to.shared.u64 t, %1; cvt.u32.u64 %0, t; }" : "=r"(a) : "l"(p));
    return a;
}
__device__ __forceinline__ void cpa16(uint32_t s, const void* g) {
    asm volatile("cp.async.cg.shared.global [%0], [%1], 16;" :: "r"(s), "l"(g));
}
#define CP_COMMIT() asm volatile("cp.async.commit_group;" ::: "memory")
#define CP_WAIT1()  asm volatile("cp.async.wait_group 1;" ::: "memory")
#define CP_WAIT0()  asm volatile("cp.async.wait_group 0;" ::: "memory")

__device__ __forceinline__ void ldsm4(uint32_t* r, uint32_t addr) {
    asm volatile("ldmatrix.sync.aligned.m8n8.x4.shared.b16 {%0,%1,%2,%3}, [%4];"
                 : "=r"(r[0]), "=r"(r[1]), "=r"(r[2]), "=r"(r[3]) : "r"(addr));
}
__device__ __forceinline__ void mma16816(float* c, const uint32_t* a, const uint32_t* b) {
    asm volatile(
        "mma.sync.aligned.m16n8k16.row.col.f32.f16.f16.f32 "
        "{%0,%1,%2,%3}, {%4,%5,%6,%7}, {%8,%9}, {%0,%1,%2,%3};"
        : "+f"(c[0]), "+f"(c[1]), "+f"(c[2]), "+f"(c[3])
        : "r"(a[0]), "r"(a[1]), "r"(a[2]), "r"(a[3]), "r"(b[0]), "r"(b[1]));
}
__device__ __forceinline__ float ex2f(float x) {
    float y;
    asm("ex2.approx.f32 %0, %1;" : "=f"(y) : "f"(x));
    return y;
}
__device__ __forceinline__ uint32_t pk2h(float a, float b) {
    __half2 t = __floats2half2_rn(a, b);
    return *(uint32_t*)&t;
}

// ============================================================================
// prep kernels
// ============================================================================
__global__ void freq_kernel() {
    int t = blockIdx.x * blockDim.x + threadIdx.x;
    if (t >= SEQ * HPAIR) return;
    int s = t >> 6;
    int p = t & 63;
    float inv = (float)(1.0 / pow(10000.0, (double)(2 * p) / (double)HDIM));
    float ang = (float)s * inv;
    float sn, cs;
    sincosf(ang, &sn, &cs);
    g_cos[t] = cs;
    g_sin[t] = sn;
}

// rope: Q -> fp16 hi/lo, K -> fp16 single, per-head layout
__global__ void ropesplit_kernel(const float* __restrict__ qkv) {
    int t = blockIdx.x * blockDim.x + threadIdx.x;
    if (t >= BATCH * SEQ * NHEAD * HPAIR) return;
    int p = t & 63;
    int h = (t >> 6) & (NHEAD - 1);
    int s = (t >> 10) & (SEQ - 1);
    int b = t >> 21;
    float c  = g_cos[s * HPAIR + p];
    float sn = g_sin[s * HPAIR + p];
    size_t src = (size_t)(b * SEQ + s) * QKVN + h * HDIM + 2 * p;
    size_t dst = ((size_t)(b * NHEAD + h) * SEQ + s) * HDIM + 2 * p;
    // q: split hi/lo
    float q1 = qkv[src], q2 = qkv[src + 1];
    float r1 = q1 * c - q2 * sn;
    float r2 = q1 * sn + q2 * c;
    __half h1 = __float2half_rn(r1), h2 = __float2half_rn(r2);
    *(__half2*)(g_Qh + dst) = __half2(h1, h2);
    *(__half2*)(g_Ql + dst) = __half2(__float2half_rn(r1 - __half2float(h1)),
                                      __float2half_rn(r2 - __half2float(h2)));
    // k: single
    float k1 = qkv[src + DIN], k2 = qkv[src + DIN + 1];
    r1 = k1 * c - k2 * sn;
    r2 = k1 * sn + k2 * c;
    *(__half2*)(g_Kh + dst) = __floats2half2_rn(r1, r2);
}

// V: per-head transpose [s][d] -> [d][s], fp16 single
__global__ void vsplit_kernel(const float* __restrict__ qkv) {
    __shared__ float tile[32][33];
    int s0 = blockIdx.x * 32, d0 = blockIdx.y * 32, bh = blockIdx.z;
    int b = bh >> 4, h = bh & 15;
    int tx = threadIdx.x, ty = threadIdx.y;     // (32,8)
    #pragma unroll
    for (int j = 0; j < 4; ++j)
        tile[ty + j*8][tx] = qkv[(size_t)(b * SEQ + s0 + ty + j*8) * QKVN + 2*DIN + h * HDIM + d0 + tx];
    __syncthreads();
    #pragma unroll
    for (int j = 0; j < 4; ++j) {
        int dl = ty + j*8;
        size_t o = ((size_t)bh * HDIM + d0 + dl) * SEQ + s0 + tx;
        g_Vth[o] = __float2half_rn(tile[tx][dl]);
    }
}

// fp32 -> fp16 hi + fp16 lo (same layout)
__global__ void split_kernel(const float* __restrict__ src,
                             __half* __restrict__ hi,
                             __half* __restrict__ lo, int n4) {
    int i = blockIdx.x * blockDim.x + threadIdx.x;
    if (i >= n4) return;
    float4 v = ((const float4*)src)[i];
    __half h0 = __float2half_rn(v.x), h1 = __float2half_rn(v.y);
    __half h2 = __float2half_rn(v.z), h3 = __float2half_rn(v.w);
    ((__half2*)hi)[2*i]   = __half2(h0, h1);
    ((__half2*)hi)[2*i+1] = __half2(h2, h3);
    ((__half2*)lo)[2*i]   = __half2(__float2half_rn(v.x - __half2float(h0)),
                                    __float2half_rn(v.y - __half2float(h1)));
    ((__half2*)lo)[2*i+1] = __half2(__float2half_rn(v.z - __half2float(h2)),
                                    __float2half_rn(v.w - __half2float(h3)));
}

// transpose fp32 [K][N] -> fp16 single [N][K]
__global__ void transpose_half(const float* __restrict__ in,
                               __half* __restrict__ ot, int K, int N) {
    __shared__ float t[32][33];
    int n0 = blockIdx.x * 32, k0 = blockIdx.y * 32;
    int tx = threadIdx.x, ty = threadIdx.y;
    #pragma unroll
    for (int j = 0; j < 4; ++j)
        t[ty + j*8][tx] = in[(size_t)(k0 + ty + j*8) * N + n0 + tx];
    __syncthreads();
    #pragma unroll
    for (int j = 0; j < 4; ++j) {
        int n = ty + j*8;
        ot[(size_t)(n0 + n) * K + k0 + tx] = __float2half_rn(t[tx][n]);
    }
}

// ============================================================================
// HMMA GEMM fp16 2-term: BM=256, BN=128, BK=32, 512 threads (16 warps 64x32).
// A split hi/lo, B single. 3-stage cp.async pipeline.
// ============================================================================
#define G2STR    80
#define G2_ALO   20480                  // 256*80
#define G2_B     40960
#define G2_STAGE 51200                  // 2*20480 + 128*80
#define G2_NST   3
#define GEMM_SMEM (G2_NST * G2_STAGE)   // 153600
#define KT_TOT (KDIM / 32)              // 64

__global__ __launch_bounds__(512) void gemm_mma(
    const __half* __restrict__ Ahi, const __half* __restrict__ Alo,
    const __half* __restrict__ B,
    float* __restrict__ C, int Ntot)
{
    extern __shared__ char smem_raw[];
    uint32_t sb = smem_u32(smem_raw);
    const int t = threadIdx.x, lane = t & 31, wid = t >> 5;
    const int m0 = blockIdx.y * 256, n0 = blockIdx.x * 128;
    const int mW = (wid & 3) * 64, nW = (wid >> 2) * 32;

    const int rL = t >> 2, ch = t & 3;
    const uint32_t soff = (uint32_t)rL * G2STR + ch * 16;
    const __half* gAhi = Ahi + (size_t)(m0 + rL) * KDIM + ch * 8;
    const __half* gAlo = Alo + (size_t)(m0 + rL) * KDIM + ch * 8;
    const __half* gB   = B   + (size_t)(n0 + rL) * KDIM + ch * 8;

    float acc[4][4][4];
    #pragma unroll
    for (int i = 0; i < 4; ++i)
        #pragma unroll
        for (int j = 0; j < 4; ++j)
            #pragma unroll
            for (int q = 0; q < 4; ++q) acc[i][j][q] = 0.f;

    auto load_stage = [&](int slot, int kt) {
        uint32_t s = sb + slot * G2_STAGE + soff;
        int g = kt * 32;
        cpa16(s,                         gAhi + g);
        cpa16(s + 128u * G2STR,          gAhi + g + (size_t)128 * KDIM);
        cpa16(s + G2_ALO,                gAlo + g);
        cpa16(s + G2_ALO + 128u * G2STR, gAlo + g + (size_t)128 * KDIM);
        cpa16(s + G2_B,                  gB + g);
    };

    const uint32_t aLane = (uint32_t)(mW + (lane & 15)) * G2STR + ((lane >> 4) * 16);
    const uint32_t bLane = (uint32_t)(nW + (lane & 7) + ((lane >> 4) << 3)) * G2STR
                         + (((lane >> 3) & 1) * 16);

    auto compute_stage = [&](int slot) {
        uint32_t base = sb + slot * G2_STAGE;
        #pragma unroll
        for (int kk = 0; kk < 2; ++kk) {
            uint32_t koff = kk * 32;
            uint32_t aH[4][4], aL[4][4];
            #pragma unroll
            for (int mt = 0; mt < 4; ++mt) {
                uint32_t ad = base + aLane + mt * (16u * G2STR) + koff;
                ldsm4(aH[mt], ad);
                ldsm4(aL[mt], ad + G2_ALO);
            }
            #pragma unroll
            for (int p = 0; p < 2; ++p) {
                uint32_t rH[4];
                ldsm4(rH, base + G2_B + bLane + p * (16u * G2STR) + koff);
                #pragma unroll
                for (int mt = 0; mt < 4; ++mt) {
                    mma16816(acc[mt][2*p],   aH[mt], rH);
                    mma16816(acc[mt][2*p],   aL[mt], rH);
                    mma16816(acc[mt][2*p+1], aH[mt], rH + 2);
                    mma16816(acc[mt][2*p+1], aL[mt], rH + 2);
                }
            }
        }
    };

    load_stage(0, 0); CP_COMMIT();
    load_stage(1, 1); CP_COMMIT();
    #pragma unroll 1
    for (int kt = 0; kt < KT_TOT; ++kt) {
        CP_WAIT1();
        __syncthreads();
        if (kt + 2 < KT_TOT) load_stage((kt + 2) % G2_NST, kt + 2);
        CP_COMMIT();
        compute_stage(kt % G2_NST);
    }

    #pragma unroll
    for (int mt = 0; mt < 4; ++mt)
        #pragma unroll
        for (int nt = 0; nt < 4; ++nt) {
            int r = m0 + mW + mt * 16 + (lane >> 2);
            int c = n0 + nW + nt * 8 + (lane & 3) * 2;
            *(float2*)(C + (size_t)r * Ntot + c)       = make_float2(acc[mt][nt][0], acc[mt][nt][1]);
            *(float2*)(C + (size_t)(r + 8) * Ntot + c) = make_float2(acc[mt][nt][2], acc[mt][nt][3]);
        }
}

// ============================================================================
// HMMA flash attention fp16 2-term: 128q x 64k tiles, Q/P split hi/lo, K/V single.
// ============================================================================
#define AQSTR   272
#define AVSTR   144
#define AQ_B    (128 * AQSTR)          // 34816
#define AK_B    (64 * AQSTR)           // 17408 (K single)
#define AV_B    (128 * AVSTR)          // 18432 (V single)
#define ASTG_B  (AK_B + AV_B)          // 35840
#define ASTG0   (2 * AQ_B)             // 69632
#define ATT_SMEM (ASTG0 + 2 * ASTG_B)  // 141312

__global__ __launch_bounds__(256, 1) void attn_mma(
    const __half* __restrict__ Qh, const __half* __restrict__ Ql,
    const __half* __restrict__ Kh, const __half* __restrict__ Vth,
    __half* __restrict__ Ohi, __half* __restrict__ Olo)
{
    extern __shared__ char smr[];
    uint32_t sb = smem_u32(smr);
    const int qt = (gridDim.x - 1) - blockIdx.x;
    const int h = blockIdx.y, b = blockIdx.z;
    const int t = threadIdx.x, lane = t & 31, wid = t >> 5;
    const int bh = b * NHEAD + h;
    const size_t headQK = (size_t)bh * SEQ * HDIM;
    const size_t headV  = (size_t)bh * HDIM * SEQ;
    const float SC2 = 0.08838834764831845f * 1.4426950408889634f;

    // Q hi/lo resident
    #pragma unroll
    for (int i = 0; i < 8; ++i) {
        int idx = t + i * 256;
        int r = idx >> 4, c = idx & 15;
        uint32_t s = sb + (uint32_t)r * AQSTR + c * 16;
        size_t g = headQK + (size_t)(qt * 128 + r) * HDIM + c * 8;
        cpa16(s, Qh + g);
        cpa16(s + AQ_B, Ql + g);
    }

    auto load_kv = [&](int slot, int kt) {
        uint32_t st = sb + ASTG0 + slot * ASTG_B;
        #pragma unroll
        for (int i = 0; i < 4; ++i) {           // K: 64 rows x 16 chunks
            int idx = t + i * 256;
            int r = idx >> 4, c = idx & 15;
            cpa16(st + (uint32_t)r * AQSTR + c * 16,
                  Kh + headQK + (size_t)(kt * 64 + r) * HDIM + c * 8);
        }
        #pragma unroll
        for (int i = 0; i < 4; ++i) {           // Vt: 128 rows x 8 chunks
            int idx = t + i * 256;
            int r = idx >> 3, c = idx & 7;
            cpa16(st + AK_B + (uint32_t)r * AVSTR + c * 16,
                  Vth + headV + (size_t)r * SEQ + kt * 64 + c * 8);
        }
    };

    const uint32_t aLane  = (uint32_t)(wid * 16 + (lane & 15)) * AQSTR + ((lane >> 4) * 16);
    const uint32_t bLaneK = (uint32_t)((lane & 7) + ((lane >> 4) << 3)) * AQSTR
                          + (((lane >> 3) & 1) * 16);
    const uint32_t bLaneV = (uint32_t)((lane & 7) + ((lane >> 4) << 3)) * AVSTR
                          + (((lane >> 3) & 1) * 16);

    float oacc[16][4];
    #pragma unroll
    for (int i = 0; i < 16; ++i)
        #pragma unroll
        for (int j = 0; j < 4; ++j) oacc[i][j] = 0.f;
    float mrow0 = -1e30f, mrow1 = -1e30f, lrow0 = 0.f, lrow1 = 0.f;

    const int last = 2 * qt + 1;
    load_kv(0, 0); CP_COMMIT();

    #pragma unroll 1
    for (int kt = 0; kt <= last; ++kt) {
        if (kt < last) { load_kv((kt + 1) & 1, kt + 1); CP_COMMIT(); CP_WAIT1(); }
        else           { CP_WAIT0(); }
        __syncthreads();
        uint32_t st = sb + ASTG0 + (kt & 1) * ASTG_B;

        // S = Q K^T (2-term: Qhi+Qlo vs K single)
        float sacc[8][4];
        #pragma unroll
        for (int i = 0; i < 8; ++i)
            #pragma unroll
            for (int j = 0; j < 4; ++j) sacc[i][j] = 0.f;

        #pragma unroll
        for (int j = 0; j < 8; ++j) {
            uint32_t aH[4], aL[4];
            ldsm4(aH, sb + aLane + j * 32);
            ldsm4(aL, sb + AQ_B + aLane + j * 32);
            #pragma unroll
            for (int g = 0; g < 4; ++g) {
                uint32_t rH[4];
                ldsm4(rH, st + bLaneK + g * (16u * AQSTR) + j * 32);
                mma16816(sacc[2*g],   aH, rH);
                mma16816(sacc[2*g],   aL, rH);
                mma16816(sacc[2*g+1], aH, rH + 2);
                mma16816(sacc[2*g+1], aL, rH + 2);
            }
        }

        if (kt >= 2 * qt) {
            int qlo = qt * 128 + wid * 16 + (lane >> 2);
            int c0 = kt * 64 + (lane & 3) * 2;
            #pragma unroll
            for (int nt = 0; nt < 8; ++nt)
                #pragma unroll
                for (int e = 0; e < 2; ++e) {
                    int col = c0 + nt * 8 + e;
                    if (col > qlo)     sacc[nt][e]     = -1e30f;
                    if (col > qlo + 8) sacc[nt][2 + e] = -1e30f;
                }
        }

        float mx0 = -1e30f, mx1 = -1e30f;
        #pragma unroll
        for (int nt = 0; nt < 8; ++nt) {
            mx0 = fmaxf(mx0, fmaxf(sacc[nt][0], sacc[nt][1]));
            mx1 = fmaxf(mx1, fmaxf(sacc[nt][2], sacc[nt][3]));
        }
        mx0 = fmaxf(mx0, __shfl_xor_sync(0xffffffffu, mx0, 1));
        mx0 = fmaxf(mx0, __shfl_xor_sync(0xffffffffu, mx0, 2));
        mx1 = fmaxf(mx1, __shfl_xor_sync(0xffffffffu, mx1, 1));
        mx1 = fmaxf(mx1, __shfl_xor_sync(0xffffffffu, mx1, 2));
        float mn0 = fmaxf(mrow0, mx0), mn1 = fmaxf(mrow1, mx1);
        float corr0 = ex2f((mrow0 - mn0) * SC2);
        float corr1 = ex2f((mrow1 - mn1) * SC2);

        float sum0 = 0.f, sum1 = 0.f;
        #pragma unroll
        for (int nt = 0; nt < 8; ++nt) {
            float p0 = ex2f((sacc[nt][0] - mn0) * SC2);
            float p1 = ex2f((sacc[nt][1] - mn0) * SC2);
            float p2 = ex2f((sacc[nt][2] - mn1) * SC2);
            float p3 = ex2f((sacc[nt][3] - mn1) * SC2);
            sum0 += p0 + p1; sum1 += p2 + p3;
            sacc[nt][0] = p0; sacc[nt][1] = p1; sacc[nt][2] = p2; sacc[nt][3] = p3;
        }
        sum0 += __shfl_xor_sync(0xffffffffu, sum0, 1);
        sum0 += __shfl_xor_sync(0xffffffffu, sum0, 2);
        sum1 += __shfl_xor_sync(0xffffffffu, sum1, 1);
        sum1 += __shfl_xor_sync(0xffffffffu, sum1, 2);
        lrow0 = lrow0 * corr0 + sum0;
        lrow1 = lrow1 * corr1 + sum1;
        mrow0 = mn0; mrow1 = mn1;

        #pragma unroll
        for (int nt = 0; nt < 16; ++nt) {
            oacc[nt][0] *= corr0; oacc[nt][1] *= corr0;
            oacc[nt][2] *= corr1; oacc[nt][3] *= corr1;
        }

        // pack P into fp16 hi/lo A-fragments
        uint32_t pH[4][4], pL[4][4];
        #pragma unroll
        for (int j = 0; j < 4; ++j) {
            #pragma unroll
            for (int half = 0; half < 2; ++half) {
                int nt = 2*j + half;
                float v0 = sacc[nt][0], v1 = sacc[nt][1];
                float v2 = sacc[nt][2], v3 = sacc[nt][3];
                __half b0 = __float2half_rn(v0), b1 = __float2half_rn(v1);
                __half b2 = __float2half_rn(v2), b3 = __float2half_rn(v3);
                pH[j][2*half]   = pk2h(__half2float(b0), __half2float(b1));
                pH[j][2*half+1] = pk2h(__half2float(b2), __half2float(b3));
                pL[j][2*half]   = pk2h(v0 - __half2float(b0), v1 - __half2float(b1));
                pL[j][2*half+1] = pk2h(v2 - __half2float(b2), v3 - __half2float(b3));
            }
        }

        // O += P V (2-term: Phi+Plo vs V single)
        #pragma unroll
        for (int j = 0; j < 4; ++j) {
            uint32_t aH[4] = {pH[j][0], pH[j][1], pH[j][2], pH[j][3]};
            uint32_t aL[4] = {pL[j][0], pL[j][1], pL[j][2], pL[j][3]};
            #pragma unroll
            for (int g = 0; g < 8; ++g) {
                uint32_t rH[4];
                ldsm4(rH, st + AK_B + bLaneV + g * (16u * AVSTR) + j * 32);
                mma16816(oacc[2*g],   aH, rH);
                mma16816(oacc[2*g],   aL, rH);
                mma16816(oacc[2*g+1], aH, rH + 2);
                mma16816(oacc[2*g+1], aL, rH + 2);
            }
        }
        __syncthreads();
    }

    // epilogue: normalize, fp16 hi/lo split, store into GEMM2 A buffers
    float inv0 = 1.f / lrow0, inv1 = 1.f / lrow1;
    size_t row0 = (size_t)b * SEQ + qt * 128 + wid * 16 + (lane >> 2);
    int colb = h * HDIM + (lane & 3) * 2;
    #pragma unroll
    for (int nt = 0; nt < 16; ++nt) {
        size_t o0 = row0 * DIN + colb + nt * 8;
        size_t o1 = (row0 + 8) * DIN + colb + nt * 8;
        float v0 = oacc[nt][0] * inv0, v1 = oacc[nt][1] * inv0;
        float v2 = oacc[nt][2] * inv1, v3 = oacc[nt][3] * inv1;
        __half h0 = __float2half_rn(v0), h1 = __float2half_rn(v1);
        __half h2 = __float2half_rn(v2), h3 = __float2half_rn(v3);
        *(__half2*)(Ohi + o0) = __half2(h0, h1);
        *(__half2*)(Ohi + o1) = __half2(h2, h3);
        *(__half2*)(Olo + o0) = __half2(__float2half_rn(v0 - __half2float(h0)),
                                        __float2half_rn(v1 - __half2float(h1)));
        *(__half2*)(Olo + o1) = __half2(__float2half_rn(v2 - __half2float(h2)),
                                        __float2half_rn(v3 - __half2float(h3)));
    }
}

// ============================================================================
// launch
// ============================================================================
extern "C" void kernel_launch(void* const* d_in, const int* in_sizes, int n_in,
                              void* d_out, int out_size)
{
    const float* x     = (const float*)d_in[0];
    const float* Wqkv  = (const float*)d_in[1];
    const float* Wproj = (const float*)d_in[2];
    float* out = (float*)d_out;

    float* qkv_ptr;
    cudaGetSymbolAddress((void**)&qkv_ptr, g_qkv);
    void *ahi, *alo, *bq, *bp, *qh, *ql, *kh, *vth;
    cudaGetSymbolAddress(&ahi, g_ahi);
    cudaGetSymbolAddress(&alo, g_alo);
    cudaGetSymbolAddress(&bq, g_bqkv);
    cudaGetSymbolAddress(&bp, g_bproj);
    cudaGetSymbolAddress(&qh, g_Qh);
    cudaGetSymbolAddress(&ql, g_Ql);
    cudaGetSymbolAddress(&kh, g_Kh);
    cudaGetSymbolAddress(&vth, g_Vth);

    static bool attr_done = false;
    if (!attr_done) {
        cudaFuncSetAttribute(gemm_mma, cudaFuncAttributeMaxDynamicSharedMemorySize, GEMM_SMEM);
        cudaFuncSetAttribute(attn_mma, cudaFuncAttributeMaxDynamicSharedMemorySize, ATT_SMEM);
        attr_done = true;
    }

    // launches 0-2
    freq_kernel<<<(SEQ * HPAIR + 255) / 256, 256>>>();
    {
        dim3 blk(32, 8);
        transpose_half<<<dim3(QKVN / 32, KDIM / 32), blk>>>(Wqkv, (__half*)bq, KDIM, QKVN);
        transpose_half<<<dim3(DIN / 32, KDIM / 32), blk>>>(Wproj, (__half*)bp, KDIM, DIN);
    }

    // launches 3-4: split x in two halves (gemm_mma stays at launch index 5 for ncu -s 5)
    {
        int n4 = MROWS * KDIM / 4;
        int half = n4 / 2;
        split_kernel<<<(half + 255) / 256, 256>>>(x, (__half*)ahi, (__half*)alo, half);
        split_kernel<<<(half + 255) / 256, 256>>>(x + (size_t)half * 4,
                                                  (__half*)ahi + (size_t)half * 4,
                                                  (__half*)alo + (size_t)half * 4, half);
    }

    // launch 5: GEMM1 qkv = x @ Wqkv
    {
        dim3 grid(QKVN / 128, MROWS / 256);
        gemm_mma<<<grid, 512, GEMM_SMEM>>>((const __half*)ahi, (const __half*)alo,
                                           (const __half*)bq, qkv_ptr, QKVN);
    }

    // rope + split Q (hi/lo), K single; transpose V single
    {
        int total = BATCH * SEQ * NHEAD * HPAIR;
        ropesplit_kernel<<<(total + 255) / 256, 256>>>(qkv_ptr);
        dim3 blk(32, 8);
        vsplit_kernel<<<dim3(SEQ / 32, HDIM / 32, BATCH * NHEAD), blk>>>(qkv_ptr);
    }

    // attention -> writes fp16 hi/lo straight into GEMM2 A buffers
    {
        dim3 grid(SEQ / 128, NHEAD, BATCH);
        attn_mma<<<grid, 256, ATT_SMEM>>>(
            (const __half*)qh, (const __half*)ql,
            (const __half*)kh, (const __half*)vth,
            (__half*)ahi, (__half*)alo);
    }

    // GEMM2: out = att @ Wproj
    {
        dim3 grid(DIN / 128, MROWS / 256);
        gemm_mma<<<grid, 512, GEMM_SMEM>>>((const __half*)ahi, (const __half*)alo,
                                           (const __half*)bp, out, DIN);
    }
}

// round 9
// speedup vs baseline: 4.5935x; 1.1202x over previous
#include <cuda_runtime.h>
#include <cuda_fp16.h>
#include <math.h>
#include <stdint.h>

#define BATCH 2
#define SEQ   2048
#define DIN   2048
#define NHEAD 16
#define HDIM  128
#define HPAIR (HDIM/2)
#define MROWS (BATCH*SEQ)       // 4096
#define QKVN  (3*DIN)           // 6144
#define KDIM  2048

// ---------------- scratch (device globals; no allocs allowed) ----------------
__device__ float g_cos[SEQ * HPAIR];
__device__ float g_sin[SEQ * HPAIR];

// fp16 operand buffers
__device__ __align__(128) __half g_ahi[(size_t)MROWS * KDIM];   // x hi; later attention out (single)
__device__ __align__(128) __half g_alo[(size_t)MROWS * KDIM];   // x lo
__device__ __align__(128) __half g_bqkv[(size_t)QKVN * KDIM];   // Wqkv^T [6144][2048]
__device__ __align__(128) __half g_bproj[(size_t)DIN * KDIM];   // Wproj^T [2048][2048]

// attention operands (rope applied, written by GEMM1 epilogue)
__device__ __align__(128) __half g_Qh[(size_t)BATCH*NHEAD*SEQ*HDIM];
__device__ __align__(128) __half g_Ql[(size_t)BATCH*NHEAD*SEQ*HDIM];
__device__ __align__(128) __half g_Kh[(size_t)BATCH*NHEAD*SEQ*HDIM];
__device__ __align__(128) __half g_Vth[(size_t)BATCH*NHEAD*HDIM*SEQ];  // [b,h,d,s]

// ---------------- PTX helpers (all base-ISA, no 'a' features) ----------------
__device__ __forceinline__ uint32_t smem_u32(const void* p) {
    uint32_t a;
    asm("{ .reg .u64 t; cvta.to.shared.u64 t, %1; cvt.u32.u64 %0, t; }" : "=r"(a) : "l"(p));
    return a;
}
__device__ __forceinline__ void cpa16(uint32_t s, const void* g) {
    asm volatile("cp.async.cg.shared.global [%0], [%1], 16;" :: "r"(s), "l"(g));
}
#define CP_COMMIT() asm volatile("cp.async.commit_group;" ::: "memory")
#define CP_WAIT1()  asm volatile("cp.async.wait_group 1;" ::: "memory")
#define CP_WAIT0()  asm volatile("cp.async.wait_group 0;" ::: "memory")

__device__ __forceinline__ void ldsm4(uint32_t* r, uint32_t addr) {
    asm volatile("ldmatrix.sync.aligned.m8n8.x4.shared.b16 {%0,%1,%2,%3}, [%4];"
                 : "=r"(r[0]), "=r"(r[1]), "=r"(r[2]), "=r"(r[3]) : "r"(addr));
}
__device__ __forceinline__ void mma16816(float* c, const uint32_t* a, const uint32_t* b) {
    asm volatile(
        "mma.sync.aligned.m16n8k16.row.col.f32.f16.f16.f32 "
        "{%0,%1,%2,%3}, {%4,%5,%6,%7}, {%8,%9}, {%0,%1,%2,%3};"
        : "+f"(c[0]), "+f"(c[1]), "+f"(c[2]), "+f"(c[3])
        : "r"(a[0]), "r"(a[1]), "r"(a[2]), "r"(a[3]), "r"(b[0]), "r"(b[1]));
}
__device__ __forceinline__ float ex2f(float x) {
    float y;
    asm("ex2.approx.f32 %0, %1;" : "=f"(y) : "f"(x));
    return y;
}
__device__ __forceinline__ uint32_t pk2h(float a, float b) {
    __half2 t = __floats2half2_rn(a, b);
    return *(uint32_t*)&t;
}

// ============================================================================
// prep kernels
// ============================================================================
__global__ void freq_kernel() {
    int t = blockIdx.x * blockDim.x + threadIdx.x;
    if (t >= SEQ * HPAIR) return;
    int s = t >> 6;
    int p = t & 63;
    float inv = (float)(1.0 / pow(10000.0, (double)(2 * p) / (double)HDIM));
    float ang = (float)s * inv;
    float sn, cs;
    sincosf(ang, &sn, &cs);
    g_cos[t] = cs;
    g_sin[t] = sn;
}

// fp32 -> fp16 hi + fp16 lo (same layout)
__global__ void split_kernel(const float* __restrict__ src,
                             __half* __restrict__ hi,
                             __half* __restrict__ lo, int n4) {
    int i = blockIdx.x * blockDim.x + threadIdx.x;
    if (i >= n4) return;
    float4 v = ((const float4*)src)[i];
    __half h0 = __float2half_rn(v.x), h1 = __float2half_rn(v.y);
    __half h2 = __float2half_rn(v.z), h3 = __float2half_rn(v.w);
    ((__half2*)hi)[2*i]   = __half2(h0, h1);
    ((__half2*)hi)[2*i+1] = __half2(h2, h3);
    ((__half2*)lo)[2*i]   = __half2(__float2half_rn(v.x - __half2float(h0)),
                                    __float2half_rn(v.y - __half2float(h1)));
    ((__half2*)lo)[2*i+1] = __half2(__float2half_rn(v.z - __half2float(h2)),
                                    __float2half_rn(v.w - __half2float(h3)));
}

// transpose fp32 [K][N] -> fp16 single [N][K]
__global__ void transpose_half(const float* __restrict__ in,
                               __half* __restrict__ ot, int K, int N) {
    __shared__ float t[32][33];
    int n0 = blockIdx.x * 32, k0 = blockIdx.y * 32;
    int tx = threadIdx.x, ty = threadIdx.y;
    #pragma unroll
    for (int j = 0; j < 4; ++j)
        t[ty + j*8][tx] = in[(size_t)(k0 + ty + j*8) * N + n0 + tx];
    __syncthreads();
    #pragma unroll
    for (int j = 0; j < 4; ++j) {
        int n = ty + j*8;
        ot[(size_t)(n0 + n) * K + k0 + tx] = __float2half_rn(t[tx][n]);
    }
}

// ============================================================================
// GEMM1 (qkv): BM=256 BN=128 BK=32, 512 thr, A 2-term hi/lo, B single.
// Epilogue applies rope and writes Qh/Ql, Kh, Vt fp16 directly.
// ============================================================================
#define G2STR    80
#define G2_ALO   20480                  // 256*80
#define G2_B     40960
#define G2_STAGE 51200
#define G2_NST   3
#define GEMM1_SMEM (G2_NST * G2_STAGE)  // 153600
#define KT_TOT (KDIM / 32)              // 64

__global__ __launch_bounds__(512) void gemm_qkv(
    const __half* __restrict__ Ahi, const __half* __restrict__ Alo,
    const __half* __restrict__ B,
    __half* __restrict__ Qh, __half* __restrict__ Ql,
    __half* __restrict__ Kh, __half* __restrict__ Vth)
{
    extern __shared__ char smem_raw[];
    uint32_t sb = smem_u32(smem_raw);
    const int t = threadIdx.x, lane = t & 31, wid = t >> 5;
    const int m0 = blockIdx.y * 256, n0 = blockIdx.x * 128;
    const int mW = (wid & 3) * 64, nW = (wid >> 2) * 32;

    const int rL = t >> 2, ch = t & 3;
    const uint32_t soff = (uint32_t)rL * G2STR + ch * 16;
    const __half* gAhi = Ahi + (size_t)(m0 + rL) * KDIM + ch * 8;
    const __half* gAlo = Alo + (size_t)(m0 + rL) * KDIM + ch * 8;
    const __half* gB   = B   + (size_t)(n0 + rL) * KDIM + ch * 8;

    float acc[4][4][4];
    #pragma unroll
    for (int i = 0; i < 4; ++i)
        #pragma unroll
        for (int j = 0; j < 4; ++j)
            #pragma unroll
            for (int q = 0; q < 4; ++q) acc[i][j][q] = 0.f;

    auto load_stage = [&](int slot, int kt) {
        uint32_t s = sb + slot * G2_STAGE + soff;
        int g = kt * 32;
        cpa16(s,                         gAhi + g);
        cpa16(s + 128u * G2STR,          gAhi + g + (size_t)128 * KDIM);
        cpa16(s + G2_ALO,                gAlo + g);
        cpa16(s + G2_ALO + 128u * G2STR, gAlo + g + (size_t)128 * KDIM);
        cpa16(s + G2_B,                  gB + g);
    };

    const uint32_t aLane = (uint32_t)(mW + (lane & 15)) * G2STR + ((lane >> 4) * 16);
    const uint32_t bLane = (uint32_t)(nW + (lane & 7) + ((lane >> 4) << 3)) * G2STR
                         + (((lane >> 3) & 1) * 16);

    auto compute_stage = [&](int slot) {
        uint32_t base = sb + slot * G2_STAGE;
        #pragma unroll
        for (int kk = 0; kk < 2; ++kk) {
            uint32_t koff = kk * 32;
            uint32_t aH[4][4], aL[4][4];
            #pragma unroll
            for (int mt = 0; mt < 4; ++mt) {
                uint32_t ad = base + aLane + mt * (16u * G2STR) + koff;
                ldsm4(aH[mt], ad);
                ldsm4(aL[mt], ad + G2_ALO);
            }
            #pragma unroll
            for (int p = 0; p < 2; ++p) {
                uint32_t rH[4];
                ldsm4(rH, base + G2_B + bLane + p * (16u * G2STR) + koff);
                #pragma unroll
                for (int mt = 0; mt < 4; ++mt) {
                    mma16816(acc[mt][2*p],   aH[mt], rH);
                    mma16816(acc[mt][2*p],   aL[mt], rH);
                    mma16816(acc[mt][2*p+1], aH[mt], rH + 2);
                    mma16816(acc[mt][2*p+1], aL[mt], rH + 2);
                }
            }
        }
    };

    load_stage(0, 0); CP_COMMIT();
    load_stage(1, 1); CP_COMMIT();
    #pragma unroll 1
    for (int kt = 0; kt < KT_TOT; ++kt) {
        CP_WAIT1();
        __syncthreads();
        if (kt + 2 < KT_TOT) load_stage((kt + 2) % G2_NST, kt + 2);
        CP_COMMIT();
        compute_stage(kt % G2_NST);
    }

    // epilogue: rope + fp16 write, region = q/k/v by column
    #pragma unroll
    for (int nt = 0; nt < 4; ++nt) {
        int c = n0 + nW + nt * 8 + (lane & 3) * 2;
        int region = c >> 11;          // 0=q 1=k 2=v (uniform per CTA)
        int hh = (c >> 7) & 15;
        int d  = c & 127;
        int p  = d >> 1;
        #pragma unroll
        for (int mt = 0; mt < 4; ++mt) {
            #pragma unroll
            for (int e = 0; e < 2; ++e) {
                int row = m0 + mW + mt * 16 + (lane >> 2) + e * 8;
                int bb = row >> 11, ss = row & 2047;
                float x1 = acc[mt][nt][2*e], x2 = acc[mt][nt][2*e+1];
                size_t hd = (size_t)(bb * NHEAD + hh) * SEQ + ss;
                if (region == 0) {
                    float cs = g_cos[ss * HPAIR + p], sn = g_sin[ss * HPAIR + p];
                    float o1 = x1 * cs - x2 * sn;
                    float o2 = x1 * sn + x2 * cs;
                    __half a = __float2half_rn(o1), b2 = __float2half_rn(o2);
                    *(__half2*)(Qh + hd * HDIM + d) = __half2(a, b2);
                    *(__half2*)(Ql + hd * HDIM + d) = __half2(
                        __float2half_rn(o1 - __half2float(a)),
                        __float2half_rn(o2 - __half2float(b2)));
                } else if (region == 1) {
                    float cs = g_cos[ss * HPAIR + p], sn = g_sin[ss * HPAIR + p];
                    float o1 = x1 * cs - x2 * sn;
                    float o2 = x1 * sn + x2 * cs;
                    *(__half2*)(Kh + hd * HDIM + d) = __floats2half2_rn(o1, o2);
                } else {
                    size_t vb = (size_t)(bb * NHEAD + hh) * HDIM;
                    Vth[(vb + d)     * SEQ + ss] = __float2half_rn(x1);
                    Vth[(vb + d + 1) * SEQ + ss] = __float2half_rn(x2);
                }
            }
        }
    }
}

// ============================================================================
// GEMM2 (out): BM=256 BN=128 BK=32, 512 thr, A single-term, B single. fp32 C.
// ============================================================================
#define GO_B     20480                  // A: 256*80
#define GO_STAGE 30720
#define GO_NST   3
#define GEMM2_SMEM (GO_NST * GO_STAGE)  // 92160

__global__ __launch_bounds__(512) void gemm_out(
    const __half* __restrict__ A, const __half* __restrict__ B,
    float* __restrict__ C, int Ntot)
{
    extern __shared__ char smem_raw[];
    uint32_t sb = smem_u32(smem_raw);
    const int t = threadIdx.x, lane = t & 31, wid = t >> 5;
    const int m0 = blockIdx.y * 256, n0 = blockIdx.x * 128;
    const int mW = (wid & 3) * 64, nW = (wid >> 2) * 32;

    const int rL = t >> 2, ch = t & 3;
    const uint32_t soff = (uint32_t)rL * G2STR + ch * 16;
    const __half* gA = A + (size_t)(m0 + rL) * KDIM + ch * 8;
    const __half* gB = B + (size_t)(n0 + rL) * KDIM + ch * 8;

    float acc[4][4][4];
    #pragma unroll
    for (int i = 0; i < 4; ++i)
        #pragma unroll
        for (int j = 0; j < 4; ++j)
            #pragma unroll
            for (int q = 0; q < 4; ++q) acc[i][j][q] = 0.f;

    auto load_stage = [&](int slot, int kt) {
        uint32_t s = sb + slot * GO_STAGE + soff;
        int g = kt * 32;
        cpa16(s,                gA + g);
        cpa16(s + 128u * G2STR, gA + g + (size_t)128 * KDIM);
        cpa16(s + GO_B,         gB + g);
    };

    const uint32_t aLane = (uint32_t)(mW + (lane & 15)) * G2STR + ((lane >> 4) * 16);
    const uint32_t bLane = (uint32_t)(nW + (lane & 7) + ((lane >> 4) << 3)) * G2STR
                         + (((lane >> 3) & 1) * 16);

    auto compute_stage = [&](int slot) {
        uint32_t base = sb + slot * GO_STAGE;
        #pragma unroll
        for (int kk = 0; kk < 2; ++kk) {
            uint32_t koff = kk * 32;
            uint32_t aH[4][4];
            #pragma unroll
            for (int mt = 0; mt < 4; ++mt)
                ldsm4(aH[mt], base + aLane + mt * (16u * G2STR) + koff);
            #pragma unroll
            for (int p = 0; p < 2; ++p) {
                uint32_t rH[4];
                ldsm4(rH, base + GO_B + bLane + p * (16u * G2STR) + koff);
                #pragma unroll
                for (int mt = 0; mt < 4; ++mt) {
                    mma16816(acc[mt][2*p],   aH[mt], rH);
                    mma16816(acc[mt][2*p+1], aH[mt], rH + 2);
                }
            }
        }
    };

    load_stage(0, 0); CP_COMMIT();
    load_stage(1, 1); CP_COMMIT();
    #pragma unroll 1
    for (int kt = 0; kt < KT_TOT; ++kt) {
        CP_WAIT1();
        __syncthreads();
        if (kt + 2 < KT_TOT) load_stage((kt + 2) % GO_NST, kt + 2);
        CP_COMMIT();
        compute_stage(kt % GO_NST);
    }

    #pragma unroll
    for (int mt = 0; mt < 4; ++mt)
        #pragma unroll
        for (int nt = 0; nt < 4; ++nt) {
            int r = m0 + mW + mt * 16 + (lane >> 2);
            int c = n0 + nW + nt * 8 + (lane & 3) * 2;
            *(float2*)(C + (size_t)r * Ntot + c)       = make_float2(acc[mt][nt][0], acc[mt][nt][1]);
            *(float2*)(C + (size_t)(r + 8) * Ntot + c) = make_float2(acc[mt][nt][2], acc[mt][nt][3]);
        }
}

// ============================================================================
// HMMA flash attention fp16 2-term (Q/P hi/lo, K/V single).
// Output: single fp16 into GEMM2's A buffer.
// ============================================================================
#define AQSTR   272
#define AVSTR   144
#define AQ_B    (128 * AQSTR)
#define AK_B    (64 * AQSTR)
#define AV_B    (128 * AVSTR)
#define ASTG_B  (AK_B + AV_B)
#define ASTG0   (2 * AQ_B)
#define ATT_SMEM (ASTG0 + 2 * ASTG_B)

__global__ __launch_bounds__(256, 1) void attn_mma(
    const __half* __restrict__ Qh, const __half* __restrict__ Ql,
    const __half* __restrict__ Kh, const __half* __restrict__ Vth,
    __half* __restrict__ O)
{
    extern __shared__ char smr[];
    uint32_t sb = smem_u32(smr);
    const int qt = (gridDim.x - 1) - blockIdx.x;
    const int h = blockIdx.y, b = blockIdx.z;
    const int t = threadIdx.x, lane = t & 31, wid = t >> 5;
    const int bh = b * NHEAD + h;
    const size_t headQK = (size_t)bh * SEQ * HDIM;
    const size_t headV  = (size_t)bh * HDIM * SEQ;
    const float SC2 = 0.08838834764831845f * 1.4426950408889634f;

    #pragma unroll
    for (int i = 0; i < 8; ++i) {
        int idx = t + i * 256;
        int r = idx >> 4, c = idx & 15;
        uint32_t s = sb + (uint32_t)r * AQSTR + c * 16;
        size_t g = headQK + (size_t)(qt * 128 + r) * HDIM + c * 8;
        cpa16(s, Qh + g);
        cpa16(s + AQ_B, Ql + g);
    }

    auto load_kv = [&](int slot, int kt) {
        uint32_t st = sb + ASTG0 + slot * ASTG_B;
        #pragma unroll
        for (int i = 0; i < 4; ++i) {
            int idx = t + i * 256;
            int r = idx >> 4, c = idx & 15;
            cpa16(st + (uint32_t)r * AQSTR + c * 16,
                  Kh + headQK + (size_t)(kt * 64 + r) * HDIM + c * 8);
        }
        #pragma unroll
        for (int i = 0; i < 4; ++i) {
            int idx = t + i * 256;
            int r = idx >> 3, c = idx & 7;
            cpa16(st + AK_B + (uint32_t)r * AVSTR + c * 16,
                  Vth + headV + (size_t)r * SEQ + kt * 64 + c * 8);
        }
    };

    const uint32_t aLane  = (uint32_t)(wid * 16 + (lane & 15)) * AQSTR + ((lane >> 4) * 16);
    const uint32_t bLaneK = (uint32_t)((lane & 7) + ((lane >> 4) << 3)) * AQSTR
                          + (((lane >> 3) & 1) * 16);
    const uint32_t bLaneV = (uint32_t)((lane & 7) + ((lane >> 4) << 3)) * AVSTR
                          + (((lane >> 3) & 1) * 16);

    float oacc[16][4];
    #pragma unroll
    for (int i = 0; i < 16; ++i)
        #pragma unroll
        for (int j = 0; j < 4; ++j) oacc[i][j] = 0.f;
    float mrow0 = -1e30f, mrow1 = -1e30f, lrow0 = 0.f, lrow1 = 0.f;

    const int last = 2 * qt + 1;
    load_kv(0, 0); CP_COMMIT();

    #pragma unroll 1
    for (int kt = 0; kt <= last; ++kt) {
        if (kt < last) { load_kv((kt + 1) & 1, kt + 1); CP_COMMIT(); CP_WAIT1(); }
        else           { CP_WAIT0(); }
        __syncthreads();
        uint32_t st = sb + ASTG0 + (kt & 1) * ASTG_B;

        float sacc[8][4];
        #pragma unroll
        for (int i = 0; i < 8; ++i)
            #pragma unroll
            for (int j = 0; j < 4; ++j) sacc[i][j] = 0.f;

        #pragma unroll
        for (int j = 0; j < 8; ++j) {
            uint32_t aH[4], aL[4];
            ldsm4(aH, sb + aLane + j * 32);
            ldsm4(aL, sb + AQ_B + aLane + j * 32);
            #pragma unroll
            for (int g = 0; g < 4; ++g) {
                uint32_t rH[4];
                ldsm4(rH, st + bLaneK + g * (16u * AQSTR) + j * 32);
                mma16816(sacc[2*g],   aH, rH);
                mma16816(sacc[2*g],   aL, rH);
                mma16816(sacc[2*g+1], aH, rH + 2);
                mma16816(sacc[2*g+1], aL, rH + 2);
            }
        }

        if (kt >= 2 * qt) {
            int qlo = qt * 128 + wid * 16 + (lane >> 2);
            int c0 = kt * 64 + (lane & 3) * 2;
            #pragma unroll
            for (int nt = 0; nt < 8; ++nt)
                #pragma unroll
                for (int e = 0; e < 2; ++e) {
                    int col = c0 + nt * 8 + e;
                    if (col > qlo)     sacc[nt][e]     = -1e30f;
                    if (col > qlo + 8) sacc[nt][2 + e] = -1e30f;
                }
        }

        float mx0 = -1e30f, mx1 = -1e30f;
        #pragma unroll
        for (int nt = 0; nt < 8; ++nt) {
            mx0 = fmaxf(mx0, fmaxf(sacc[nt][0], sacc[nt][1]));
            mx1 = fmaxf(mx1, fmaxf(sacc[nt][2], sacc[nt][3]));
        }
        mx0 = fmaxf(mx0, __shfl_xor_sync(0xffffffffu, mx0, 1));
        mx0 = fmaxf(mx0, __shfl_xor_sync(0xffffffffu, mx0, 2));
        mx1 = fmaxf(mx1, __shfl_xor_sync(0xffffffffu, mx1, 1));
        mx1 = fmaxf(mx1, __shfl_xor_sync(0xffffffffu, mx1, 2));
        float mn0 = fmaxf(mrow0, mx0), mn1 = fmaxf(mrow1, mx1);
        float corr0 = ex2f((mrow0 - mn0) * SC2);
        float corr1 = ex2f((mrow1 - mn1) * SC2);

        float sum0 = 0.f, sum1 = 0.f;
        #pragma unroll
        for (int nt = 0; nt < 8; ++nt) {
            float p0 = ex2f((sacc[nt][0] - mn0) * SC2);
            float p1 = ex2f((sacc[nt][1] - mn0) * SC2);
            float p2 = ex2f((sacc[nt][2] - mn1) * SC2);
            float p3 = ex2f((sacc[nt][3] - mn1) * SC2);
            sum0 += p0 + p1; sum1 += p2 + p3;
            sacc[nt][0] = p0; sacc[nt][1] = p1; sacc[nt][2] = p2; sacc[nt][3] = p3;
        }
        sum0 += __shfl_xor_sync(0xffffffffu, sum0, 1);
        sum0 += __shfl_xor_sync(0xffffffffu, sum0, 2);
        sum1 += __shfl_xor_sync(0xffffffffu, sum1, 1);
        sum1 += __shfl_xor_sync(0xffffffffu, sum1, 2);
        lrow0 = lrow0 * corr0 + sum0;
        lrow1 = lrow1 * corr1 + sum1;
        mrow0 = mn0; mrow1 = mn1;

        #pragma unroll
        for (int nt = 0; nt < 16; ++nt) {
            oacc[nt][0] *= corr0; oacc[nt][1] *= corr0;
            oacc[nt][2] *= corr1; oacc[nt][3] *= corr1;
        }

        uint32_t pH[4][4], pL[4][4];
        #pragma unroll
        for (int j = 0; j < 4; ++j) {
            #pragma unroll
            for (int half = 0; half < 2; ++half) {
                int nt = 2*j + half;
                float v0 = sacc[nt][0], v1 = sacc[nt][1];
                float v2 = sacc[nt][2], v3 = sacc[nt][3];
                __half b0 = __float2half_rn(v0), b1 = __float2half_rn(v1);
                __half b2 = __float2half_rn(v2), b3 = __float2half_rn(v3);
                pH[j][2*half]   = pk2h(__half2float(b0), __half2float(b1));
                pH[j][2*half+1] = pk2h(__half2float(b2), __half2float(b3));
                pL[j][2*half]   = pk2h(v0 - __half2float(b0), v1 - __half2float(b1));
                pL[j][2*half+1] = pk2h(v2 - __half2float(b2), v3 - __half2float(b3));
            }
        }

        #pragma unroll
        for (int j = 0; j < 4; ++j) {
            uint32_t aH[4] = {pH[j][0], pH[j][1], pH[j][2], pH[j][3]};
            uint32_t aL[4] = {pL[j][0], pL[j][1], pL[j][2], pL[j][3]};
            #pragma unroll
            for (int g = 0; g < 8; ++g) {
                uint32_t rH[4];
                ldsm4(rH, st + AK_B + bLaneV + g * (16u * AVSTR) + j * 32);
                mma16816(oacc[2*g],   aH, rH);
                mma16816(oacc[2*g],   aL, rH);
                mma16816(oacc[2*g+1], aH, rH + 2);
                mma16816(oacc[2*g+1], aL, rH + 2);
            }
        }
        __syncthreads();
    }

    // epilogue: normalize, single fp16 write into GEMM2 A buffer
    float inv0 = 1.f / lrow0, inv1 = 1.f / lrow1;
    size_t row0 = (size_t)b * SEQ + qt * 128 + wid * 16 + (lane >> 2);
    int colb = h * HDIM + (lane & 3) * 2;
    #pragma unroll
    for (int nt = 0; nt < 16; ++nt) {
        size_t o0 = row0 * DIN + colb + nt * 8;
        size_t o1 = (row0 + 8) * DIN + colb + nt * 8;
        *(__half2*)(O + o0) = __floats2half2_rn(oacc[nt][0] * inv0, oacc[nt][1] * inv0);
        *(__half2*)(O + o1) = __floats2half2_rn(oacc[nt][2] * inv1, oacc[nt][3] * inv1);
    }
}

// ============================================================================
// launch
// ============================================================================
extern "C" void kernel_launch(void* const* d_in, const int* in_sizes, int n_in,
                              void* d_out, int out_size)
{
    const float* x     = (const float*)d_in[0];
    const float* Wqkv  = (const float*)d_in[1];
    const float* Wproj = (const float*)d_in[2];
    float* out = (float*)d_out;

    void *ahi, *alo, *bq, *bp, *qh, *ql, *kh, *vth;
    cudaGetSymbolAddress(&ahi, g_ahi);
    cudaGetSymbolAddress(&alo, g_alo);
    cudaGetSymbolAddress(&bq, g_bqkv);
    cudaGetSymbolAddress(&bp, g_bproj);
    cudaGetSymbolAddress(&qh, g_Qh);
    cudaGetSymbolAddress(&ql, g_Ql);
    cudaGetSymbolAddress(&kh, g_Kh);
    cudaGetSymbolAddress(&vth, g_Vth);

    static bool attr_done = false;
    if (!attr_done) {
        cudaFuncSetAttribute(gemm_qkv, cudaFuncAttributeMaxDynamicSharedMemorySize, GEMM1_SMEM);
        cudaFuncSetAttribute(gemm_out, cudaFuncAttributeMaxDynamicSharedMemorySize, GEMM2_SMEM);
        cudaFuncSetAttribute(attn_mma, cudaFuncAttributeMaxDynamicSharedMemorySize, ATT_SMEM);
        attr_done = true;
    }

    // launches 0-2
    freq_kernel<<<(SEQ * HPAIR + 255) / 256, 256>>>();
    {
        dim3 blk(32, 8);
        transpose_half<<<dim3(QKVN / 32, KDIM / 32), blk>>>(Wqkv, (__half*)bq, KDIM, QKVN);
        transpose_half<<<dim3(DIN / 32, KDIM / 32), blk>>>(Wproj, (__half*)bp, KDIM, DIN);
    }

    // launches 3-4: split x (two halves; keeps gemm_qkv at ncu -s 5)
    {
        int n4 = MROWS * KDIM / 4;
        int half = n4 / 2;
        split_kernel<<<(half + 255) / 256, 256>>>(x, (__half*)ahi, (__half*)alo, half);
        split_kernel<<<(half + 255) / 256, 256>>>(x + (size_t)half * 4,
                                                  (__half*)ahi + (size_t)half * 4,
                                                  (__half*)alo + (size_t)half * 4, half);
    }

    // launch 5: GEMM1 + fused rope/split epilogue
    {
        dim3 grid(QKVN / 128, MROWS / 256);
        gemm_qkv<<<grid, 512, GEMM1_SMEM>>>((const __half*)ahi, (const __half*)alo,
                                            (const __half*)bq,
                                            (__half*)qh, (__half*)ql, (__half*)kh, (__half*)vth);
    }

    // attention -> single fp16 output into GEMM2's A buffer
    {
        dim3 grid(SEQ / 128, NHEAD, BATCH);
        attn_mma<<<grid, 256, ATT_SMEM>>>(
            (const __half*)qh, (const __half*)ql,
            (const __half*)kh, (const __half*)vth,
            (__half*)ahi);
    }

    // GEMM2: out = att @ Wproj (1-term A)
    {
        dim3 grid(DIN / 128, MROWS / 256);
        gemm_out<<<grid, 512, GEMM2_SMEM>>>((const __half*)ahi, (const __half*)bp, out, DIN);
    }
}

// round 10
// speedup vs baseline: 6.4648x; 1.4074x over previous
#include <cuda_runtime.h>
#include <cuda_fp16.h>
#include <math.h>
#include <stdint.h>

#define BATCH 2
#define SEQ   2048
#define DIN   2048
#define NHEAD 16
#define HDIM  128
#define HPAIR (HDIM/2)
#define MROWS (BATCH*SEQ)       // 4096
#define QKVN  (3*DIN)           // 6144
#define KDIM  2048

// ---------------- scratch (device globals; no allocs allowed) ----------------
__device__ float g_cos[SEQ * HPAIR];
__device__ float g_sin[SEQ * HPAIR];

// fp16 operand buffers
__device__ __align__(128) __half g_ax[(size_t)MROWS * KDIM];    // x fp16; later attention out
__device__ __align__(128) __half g_bqkv[(size_t)QKVN * KDIM];   // Wqkv^T [6144][2048]
__device__ __align__(128) __half g_bproj[(size_t)DIN * KDIM];   // Wproj^T [2048][2048]

// attention operands (rope applied, written by GEMM1 epilogue)
__device__ __align__(128) __half g_Qh[(size_t)BATCH*NHEAD*SEQ*HDIM];
__device__ __align__(128) __half g_Ql[(size_t)BATCH*NHEAD*SEQ*HDIM];
__device__ __align__(128) __half g_Kh[(size_t)BATCH*NHEAD*SEQ*HDIM];
__device__ __align__(128) __half g_Vth[(size_t)BATCH*NHEAD*HDIM*SEQ];  // [b,h,d,s]

// ---------------- PTX helpers (all base-ISA, no 'a' features) ----------------
__device__ __forceinline__ uint32_t smem_u32(const void* p) {
    uint32_t a;
    asm("{ .reg .u64 t; cvta.to.shared.u64 t, %1; cvt.u32.u64 %0, t; }" : "=r"(a) : "l"(p));
    return a;
}
__device__ __forceinline__ void cpa16(uint32_t s, const void* g) {
    asm volatile("cp.async.cg.shared.global [%0], [%1], 16;" :: "r"(s), "l"(g));
}
#define CP_COMMIT() asm volatile("cp.async.commit_group;" ::: "memory")
#define CP_WAIT1()  asm volatile("cp.async.wait_group 1;" ::: "memory")
#define CP_WAIT0()  asm volatile("cp.async.wait_group 0;" ::: "memory")

__device__ __forceinline__ void ldsm4(uint32_t* r, uint32_t addr) {
    asm volatile("ldmatrix.sync.aligned.m8n8.x4.shared.b16 {%0,%1,%2,%3}, [%4];"
                 : "=r"(r[0]), "=r"(r[1]), "=r"(r[2]), "=r"(r[3]) : "r"(addr));
}
__device__ __forceinline__ void mma16816(float* c, const uint32_t* a, const uint32_t* b) {
    asm volatile(
        "mma.sync.aligned.m16n8k16.row.col.f32.f16.f16.f32 "
        "{%0,%1,%2,%3}, {%4,%5,%6,%7}, {%8,%9}, {%0,%1,%2,%3};"
        : "+f"(c[0]), "+f"(c[1]), "+f"(c[2]), "+f"(c[3])
        : "r"(a[0]), "r"(a[1]), "r"(a[2]), "r"(a[3]), "r"(b[0]), "r"(b[1]));
}
__device__ __forceinline__ float ex2f(float x) {
    float y;
    asm("ex2.approx.f32 %0, %1;" : "=f"(y) : "f"(x));
    return y;
}
__device__ __forceinline__ uint32_t pk2h(float a, float b) {
    __half2 t = __floats2half2_rn(a, b);
    return *(uint32_t*)&t;
}

// ============================================================================
// prep kernels
// ============================================================================
__global__ void freq_kernel() {
    int t = blockIdx.x * blockDim.x + threadIdx.x;
    if (t >= SEQ * HPAIR) return;
    int s = t >> 6;
    int p = t & 63;
    float inv = (float)(1.0 / pow(10000.0, (double)(2 * p) / (double)HDIM));
    float ang = (float)s * inv;
    float sn, cs;
    sincosf(ang, &sn, &cs);
    g_cos[t] = cs;
    g_sin[t] = sn;
}

// fp32 -> fp16 (same layout)
__global__ void convert_half(const float* __restrict__ src,
                             __half* __restrict__ dst, int n4) {
    int i = blockIdx.x * blockDim.x + threadIdx.x;
    if (i >= n4) return;
    float4 v = ((const float4*)src)[i];
    ((__half2*)dst)[2*i]   = __floats2half2_rn(v.x, v.y);
    ((__half2*)dst)[2*i+1] = __floats2half2_rn(v.z, v.w);
}

// transpose fp32 [K][N] -> fp16 single [N][K]
__global__ void transpose_half(const float* __restrict__ in,
                               __half* __restrict__ ot, int K, int N) {
    __shared__ float t[32][33];
    int n0 = blockIdx.x * 32, k0 = blockIdx.y * 32;
    int tx = threadIdx.x, ty = threadIdx.y;
    #pragma unroll
    for (int j = 0; j < 4; ++j)
        t[ty + j*8][tx] = in[(size_t)(k0 + ty + j*8) * N + n0 + tx];
    __syncthreads();
    #pragma unroll
    for (int j = 0; j < 4; ++j) {
        int n = ty + j*8;
        ot[(size_t)(n0 + n) * K + k0 + tx] = __float2half_rn(t[tx][n]);
    }
}

// ============================================================================
// Shared GEMM config: BM=256 BN=128 BK=32, 512 thr (16 warps, 64x32 per warp).
// A single fp16, B single fp16, 3-stage cp.async pipeline.
// ============================================================================
#define G2STR    80
#define GO_B     20480                  // A: 256*80
#define GO_STAGE 30720
#define GO_NST   3
#define GEMM_SMEM (GO_NST * GO_STAGE)   // 92160
#define KT_TOT (KDIM / 32)              // 64

// common mainloop body via macro-free duplication (two kernels, different epilogues)

// ---- GEMM1: qkv with fused rope epilogue ----
__global__ __launch_bounds__(512) void gemm_qkv(
    const __half* __restrict__ A, const __half* __restrict__ B,
    __half* __restrict__ Qh, __half* __restrict__ Ql,
    __half* __restrict__ Kh, __half* __restrict__ Vth)
{
    extern __shared__ char smem_raw[];
    uint32_t sb = smem_u32(smem_raw);
    const int t = threadIdx.x, lane = t & 31, wid = t >> 5;
    const int m0 = blockIdx.y * 256, n0 = blockIdx.x * 128;
    const int mW = (wid & 3) * 64, nW = (wid >> 2) * 32;

    const int rL = t >> 2, ch = t & 3;
    const uint32_t soff = (uint32_t)rL * G2STR + ch * 16;
    const __half* gA = A + (size_t)(m0 + rL) * KDIM + ch * 8;
    const __half* gB = B + (size_t)(n0 + rL) * KDIM + ch * 8;

    float acc[4][4][4];
    #pragma unroll
    for (int i = 0; i < 4; ++i)
        #pragma unroll
        for (int j = 0; j < 4; ++j)
            #pragma unroll
            for (int q = 0; q < 4; ++q) acc[i][j][q] = 0.f;

    auto load_stage = [&](int slot, int kt) {
        uint32_t s = sb + slot * GO_STAGE + soff;
        int g = kt * 32;
        cpa16(s,                gA + g);
        cpa16(s + 128u * G2STR, gA + g + (size_t)128 * KDIM);
        cpa16(s + GO_B,         gB + g);
    };

    const uint32_t aLane = (uint32_t)(mW + (lane & 15)) * G2STR + ((lane >> 4) * 16);
    const uint32_t bLane = (uint32_t)(nW + (lane & 7) + ((lane >> 4) << 3)) * G2STR
                         + (((lane >> 3) & 1) * 16);

    auto compute_stage = [&](int slot) {
        uint32_t base = sb + slot * GO_STAGE;
        #pragma unroll
        for (int kk = 0; kk < 2; ++kk) {
            uint32_t koff = kk * 32;
            uint32_t aH[4][4];
            #pragma unroll
            for (int mt = 0; mt < 4; ++mt)
                ldsm4(aH[mt], base + aLane + mt * (16u * G2STR) + koff);
            #pragma unroll
            for (int p = 0; p < 2; ++p) {
                uint32_t rH[4];
                ldsm4(rH, base + GO_B + bLane + p * (16u * G2STR) + koff);
                #pragma unroll
                for (int mt = 0; mt < 4; ++mt) {
                    mma16816(acc[mt][2*p],   aH[mt], rH);
                    mma16816(acc[mt][2*p+1], aH[mt], rH + 2);
                }
            }
        }
    };

    load_stage(0, 0); CP_COMMIT();
    load_stage(1, 1); CP_COMMIT();
    #pragma unroll 1
    for (int kt = 0; kt < KT_TOT; ++kt) {
        CP_WAIT1();
        __syncthreads();
        if (kt + 2 < KT_TOT) load_stage((kt + 2) % GO_NST, kt + 2);
        CP_COMMIT();
        compute_stage(kt % GO_NST);
    }

    // epilogue: rope + fp16 write, region = q/k/v by column
    #pragma unroll
    for (int nt = 0; nt < 4; ++nt) {
        int c = n0 + nW + nt * 8 + (lane & 3) * 2;
        int region = c >> 11;          // 0=q 1=k 2=v (uniform per CTA)
        int hh = (c >> 7) & 15;
        int d  = c & 127;
        int p  = d >> 1;
        #pragma unroll
        for (int mt = 0; mt < 4; ++mt) {
            #pragma unroll
            for (int e = 0; e < 2; ++e) {
                int row = m0 + mW + mt * 16 + (lane >> 2) + e * 8;
                int bb = row >> 11, ss = row & 2047;
                float x1 = acc[mt][nt][2*e], x2 = acc[mt][nt][2*e+1];
                size_t hd = (size_t)(bb * NHEAD + hh) * SEQ + ss;
                if (region == 0) {
                    float cs = g_cos[ss * HPAIR + p], sn = g_sin[ss * HPAIR + p];
                    float o1 = x1 * cs - x2 * sn;
                    float o2 = x1 * sn + x2 * cs;
                    __half a = __float2half_rn(o1), b2 = __float2half_rn(o2);
                    *(__half2*)(Qh + hd * HDIM + d) = __half2(a, b2);
                    *(__half2*)(Ql + hd * HDIM + d) = __half2(
                        __float2half_rn(o1 - __half2float(a)),
                        __float2half_rn(o2 - __half2float(b2)));
                } else if (region == 1) {
                    float cs = g_cos[ss * HPAIR + p], sn = g_sin[ss * HPAIR + p];
                    float o1 = x1 * cs - x2 * sn;
                    float o2 = x1 * sn + x2 * cs;
                    *(__half2*)(Kh + hd * HDIM + d) = __floats2half2_rn(o1, o2);
                } else {
                    size_t vb = (size_t)(bb * NHEAD + hh) * HDIM;
                    Vth[(vb + d)     * SEQ + ss] = __float2half_rn(x1);
                    Vth[(vb + d + 1) * SEQ + ss] = __float2half_rn(x2);
                }
            }
        }
    }
}

// ---- GEMM2: out (fp32 C) ----
__global__ __launch_bounds__(512) void gemm_out(
    const __half* __restrict__ A, const __half* __restrict__ B,
    float* __restrict__ C, int Ntot)
{
    extern __shared__ char smem_raw[];
    uint32_t sb = smem_u32(smem_raw);
    const int t = threadIdx.x, lane = t & 31, wid = t >> 5;
    const int m0 = blockIdx.y * 256, n0 = blockIdx.x * 128;
    const int mW = (wid & 3) * 64, nW = (wid >> 2) * 32;

    const int rL = t >> 2, ch = t & 3;
    const uint32_t soff = (uint32_t)rL * G2STR + ch * 16;
    const __half* gA = A + (size_t)(m0 + rL) * KDIM + ch * 8;
    const __half* gB = B + (size_t)(n0 + rL) * KDIM + ch * 8;

    float acc[4][4][4];
    #pragma unroll
    for (int i = 0; i < 4; ++i)
        #pragma unroll
        for (int j = 0; j < 4; ++j)
            #pragma unroll
            for (int q = 0; q < 4; ++q) acc[i][j][q] = 0.f;

    auto load_stage = [&](int slot, int kt) {
        uint32_t s = sb + slot * GO_STAGE + soff;
        int g = kt * 32;
        cpa16(s,                gA + g);
        cpa16(s + 128u * G2STR, gA + g + (size_t)128 * KDIM);
        cpa16(s + GO_B,         gB + g);
    };

    const uint32_t aLane = (uint32_t)(mW + (lane & 15)) * G2STR + ((lane >> 4) * 16);
    const uint32_t bLane = (uint32_t)(nW + (lane & 7) + ((lane >> 4) << 3)) * G2STR
                         + (((lane >> 3) & 1) * 16);

    auto compute_stage = [&](int slot) {
        uint32_t base = sb + slot * GO_STAGE;
        #pragma unroll
        for (int kk = 0; kk < 2; ++kk) {
            uint32_t koff = kk * 32;
            uint32_t aH[4][4];
            #pragma unroll
            for (int mt = 0; mt < 4; ++mt)
                ldsm4(aH[mt], base + aLane + mt * (16u * G2STR) + koff);
            #pragma unroll
            for (int p = 0; p < 2; ++p) {
                uint32_t rH[4];
                ldsm4(rH, base + GO_B + bLane + p * (16u * G2STR) + koff);
                #pragma unroll
                for (int mt = 0; mt < 4; ++mt) {
                    mma16816(acc[mt][2*p],   aH[mt], rH);
                    mma16816(acc[mt][2*p+1], aH[mt], rH + 2);
                }
            }
        }
    };

    load_stage(0, 0); CP_COMMIT();
    load_stage(1, 1); CP_COMMIT();
    #pragma unroll 1
    for (int kt = 0; kt < KT_TOT; ++kt) {
        CP_WAIT1();
        __syncthreads();
        if (kt + 2 < KT_TOT) load_stage((kt + 2) % GO_NST, kt + 2);
        CP_COMMIT();
        compute_stage(kt % GO_NST);
    }

    #pragma unroll
    for (int mt = 0; mt < 4; ++mt)
        #pragma unroll
        for (int nt = 0; nt < 4; ++nt) {
            int r = m0 + mW + mt * 16 + (lane >> 2);
            int c = n0 + nW + nt * 8 + (lane & 3) * 2;
            *(float2*)(C + (size_t)r * Ntot + c)       = make_float2(acc[mt][nt][0], acc[mt][nt][1]);
            *(float2*)(C + (size_t)(r + 8) * Ntot + c) = make_float2(acc[mt][nt][2], acc[mt][nt][3]);
        }
}

// ============================================================================
// HMMA flash attention fp16 (Q/P 2-term hi/lo, K/V single). Output single fp16.
// ============================================================================
#define AQSTR   272
#define AVSTR   144
#define AQ_B    (128 * AQSTR)
#define AK_B    (64 * AQSTR)
#define AV_B    (128 * AVSTR)
#define ASTG_B  (AK_B + AV_B)
#define ASTG0   (2 * AQ_B)
#define ATT_SMEM (ASTG0 + 2 * ASTG_B)

__global__ __launch_bounds__(256, 1) void attn_mma(
    const __half* __restrict__ Qh, const __half* __restrict__ Ql,
    const __half* __restrict__ Kh, const __half* __restrict__ Vth,
    __half* __restrict__ O)
{
    extern __shared__ char smr[];
    uint32_t sb = smem_u32(smr);
    const int qt = (gridDim.x - 1) - blockIdx.x;
    const int h = blockIdx.y, b = blockIdx.z;
    const int t = threadIdx.x, lane = t & 31, wid = t >> 5;
    const int bh = b * NHEAD + h;
    const size_t headQK = (size_t)bh * SEQ * HDIM;
    const size_t headV  = (size_t)bh * HDIM * SEQ;
    const float SC2 = 0.08838834764831845f * 1.4426950408889634f;

    #pragma unroll
    for (int i = 0; i < 8; ++i) {
        int idx = t + i * 256;
        int r = idx >> 4, c = idx & 15;
        uint32_t s = sb + (uint32_t)r * AQSTR + c * 16;
        size_t g = headQK + (size_t)(qt * 128 + r) * HDIM + c * 8;
        cpa16(s, Qh + g);
        cpa16(s + AQ_B, Ql + g);
    }

    auto load_kv = [&](int slot, int kt) {
        uint32_t st = sb + ASTG0 + slot * ASTG_B;
        #pragma unroll
        for (int i = 0; i < 4; ++i) {
            int idx = t + i * 256;
            int r = idx >> 4, c = idx & 15;
            cpa16(st + (uint32_t)r * AQSTR + c * 16,
                  Kh + headQK + (size_t)(kt * 64 + r) * HDIM + c * 8);
        }
        #pragma unroll
        for (int i = 0; i < 4; ++i) {
            int idx = t + i * 256;
            int r = idx >> 3, c = idx & 7;
            cpa16(st + AK_B + (uint32_t)r * AVSTR + c * 16,
                  Vth + headV + (size_t)r * SEQ + kt * 64 + c * 8);
        }
    };

    const uint32_t aLane  = (uint32_t)(wid * 16 + (lane & 15)) * AQSTR + ((lane >> 4) * 16);
    const uint32_t bLaneK = (uint32_t)((lane & 7) + ((lane >> 4) << 3)) * AQSTR
                          + (((lane >> 3) & 1) * 16);
    const uint32_t bLaneV = (uint32_t)((lane & 7) + ((lane >> 4) << 3)) * AVSTR
                          + (((lane >> 3) & 1) * 16);

    float oacc[16][4];
    #pragma unroll
    for (int i = 0; i < 16; ++i)
        #pragma unroll
        for (int j = 0; j < 4; ++j) oacc[i][j] = 0.f;
    float mrow0 = -1e30f, mrow1 = -1e30f, lrow0 = 0.f, lrow1 = 0.f;

    const int last = 2 * qt + 1;
    load_kv(0, 0); CP_COMMIT();

    #pragma unroll 1
    for (int kt = 0; kt <= last; ++kt) {
        if (kt < last) { load_kv((kt + 1) & 1, kt + 1); CP_COMMIT(); CP_WAIT1(); }
        else           { CP_WAIT0(); }
        __syncthreads();
        uint32_t st = sb + ASTG0 + (kt & 1) * ASTG_B;

        float sacc[8][4];
        #pragma unroll
        for (int i = 0; i < 8; ++i)
            #pragma unroll
            for (int j = 0; j < 4; ++j) sacc[i][j] = 0.f;

        #pragma unroll
        for (int j = 0; j < 8; ++j) {
            uint32_t aH[4], aL[4];
            ldsm4(aH, sb + aLane + j * 32);
            ldsm4(aL, sb + AQ_B + aLane + j * 32);
            #pragma unroll
            for (int g = 0; g < 4; ++g) {
                uint32_t rH[4];
                ldsm4(rH, st + bLaneK + g * (16u * AQSTR) + j * 32);
                mma16816(sacc[2*g],   aH, rH);
                mma16816(sacc[2*g],   aL, rH);
                mma16816(sacc[2*g+1], aH, rH + 2);
                mma16816(sacc[2*g+1], aL, rH + 2);
            }
        }

        if (kt >= 2 * qt) {
            int qlo = qt * 128 + wid * 16 + (lane >> 2);
            int c0 = kt * 64 + (lane & 3) * 2;
            #pragma unroll
            for (int nt = 0; nt < 8; ++nt)
                #pragma unroll
                for (int e = 0; e < 2; ++e) {
                    int col = c0 + nt * 8 + e;
                    if (col > qlo)     sacc[nt][e]     = -1e30f;
                    if (col > qlo + 8) sacc[nt][2 + e] = -1e30f;
                }
        }

        float mx0 = -1e30f, mx1 = -1e30f;
        #pragma unroll
        for (int nt = 0; nt < 8; ++nt) {
            mx0 = fmaxf(mx0, fmaxf(sacc[nt][0], sacc[nt][1]));
            mx1 = fmaxf(mx1, fmaxf(sacc[nt][2], sacc[nt][3]));
        }
        mx0 = fmaxf(mx0, __shfl_xor_sync(0xffffffffu, mx0, 1));
        mx0 = fmaxf(mx0, __shfl_xor_sync(0xffffffffu, mx0, 2));
        mx1 = fmaxf(mx1, __shfl_xor_sync(0xffffffffu, mx1, 1));
        mx1 = fmaxf(mx1, __shfl_xor_sync(0xffffffffu, mx1, 2));
        float mn0 = fmaxf(mrow0, mx0), mn1 = fmaxf(mrow1, mx1);
        float corr0 = ex2f((mrow0 - mn0) * SC2);
        float corr1 = ex2f((mrow1 - mn1) * SC2);

        float sum0 = 0.f, sum1 = 0.f;
        #pragma unroll
        for (int nt = 0; nt < 8; ++nt) {
            float p0 = ex2f((sacc[nt][0] - mn0) * SC2);
            float p1 = ex2f((sacc[nt][1] - mn0) * SC2);
            float p2 = ex2f((sacc[nt][2] - mn1) * SC2);
            float p3 = ex2f((sacc[nt][3] - mn1) * SC2);
            sum0 += p0 + p1; sum1 += p2 + p3;
            sacc[nt][0] = p0; sacc[nt][1] = p1; sacc[nt][2] = p2; sacc[nt][3] = p3;
        }
        sum0 += __shfl_xor_sync(0xffffffffu, sum0, 1);
        sum0 += __shfl_xor_sync(0xffffffffu, sum0, 2);
        sum1 += __shfl_xor_sync(0xffffffffu, sum1, 1);
        sum1 += __shfl_xor_sync(0xffffffffu, sum1, 2);
        lrow0 = lrow0 * corr0 + sum0;
        lrow1 = lrow1 * corr1 + sum1;
        mrow0 = mn0; mrow1 = mn1;

        #pragma unroll
        for (int nt = 0; nt < 16; ++nt) {
            oacc[nt][0] *= corr0; oacc[nt][1] *= corr0;
            oacc[nt][2] *= corr1; oacc[nt][3] *= corr1;
        }

        uint32_t pH[4][4], pL[4][4];
        #pragma unroll
        for (int j = 0; j < 4; ++j) {
            #pragma unroll
            for (int half = 0; half < 2; ++half) {
                int nt = 2*j + half;
                float v0 = sacc[nt][0], v1 = sacc[nt][1];
                float v2 = sacc[nt][2], v3 = sacc[nt][3];
                __half b0 = __float2half_rn(v0), b1 = __float2half_rn(v1);
                __half b2 = __float2half_rn(v2), b3 = __float2half_rn(v3);
                pH[j][2*half]   = pk2h(__half2float(b0), __half2float(b1));
                pH[j][2*half+1] = pk2h(__half2float(b2), __half2float(b3));
                pL[j][2*half]   = pk2h(v0 - __half2float(b0), v1 - __half2float(b1));
                pL[j][2*half+1] = pk2h(v2 - __half2float(b2), v3 - __half2float(b3));
            }
        }

        #pragma unroll
        for (int j = 0; j < 4; ++j) {
            uint32_t aH[4] = {pH[j][0], pH[j][1], pH[j][2], pH[j][3]};
            uint32_t aL[4] = {pL[j][0], pL[j][1], pL[j][2], pL[j][3]};
            #pragma unroll
            for (int g = 0; g < 8; ++g) {
                uint32_t rH[4];
                ldsm4(rH, st + AK_B + bLaneV + g * (16u * AVSTR) + j * 32);
                mma16816(oacc[2*g],   aH, rH);
                mma16816(oacc[2*g],   aL, rH);
                mma16816(oacc[2*g+1], aH, rH + 2);
                mma16816(oacc[2*g+1], aL, rH + 2);
            }
        }
        __syncthreads();
    }

    float inv0 = 1.f / lrow0, inv1 = 1.f / lrow1;
    size_t row0 = (size_t)b * SEQ + qt * 128 + wid * 16 + (lane >> 2);
    int colb = h * HDIM + (lane & 3) * 2;
    #pragma unroll
    for (int nt = 0; nt < 16; ++nt) {
        size_t o0 = row0 * DIN + colb + nt * 8;
        size_t o1 = (row0 + 8) * DIN + colb + nt * 8;
        *(__half2*)(O + o0) = __floats2half2_rn(oacc[nt][0] * inv0, oacc[nt][1] * inv0);
        *(__half2*)(O + o1) = __floats2half2_rn(oacc[nt][2] * inv1, oacc[nt][3] * inv1);
    }
}

// ============================================================================
// launch
// ============================================================================
extern "C" void kernel_launch(void* const* d_in, const int* in_sizes, int n_in,
                              void* d_out, int out_size)
{
    const float* x     = (const float*)d_in[0];
    const float* Wqkv  = (const float*)d_in[1];
    const float* Wproj = (const float*)d_in[2];
    float* out = (float*)d_out;

    void *ax, *bq, *bp, *qh, *ql, *kh, *vth;
    cudaGetSymbolAddress(&ax, g_ax);
    cudaGetSymbolAddress(&bq, g_bqkv);
    cudaGetSymbolAddress(&bp, g_bproj);
    cudaGetSymbolAddress(&qh, g_Qh);
    cudaGetSymbolAddress(&ql, g_Ql);
    cudaGetSymbolAddress(&kh, g_Kh);
    cudaGetSymbolAddress(&vth, g_Vth);

    static bool attr_done = false;
    if (!attr_done) {
        cudaFuncSetAttribute(gemm_qkv, cudaFuncAttributeMaxDynamicSharedMemorySize, GEMM_SMEM);
        cudaFuncSetAttribute(gemm_out, cudaFuncAttributeMaxDynamicSharedMemorySize, GEMM_SMEM);
        cudaFuncSetAttribute(attn_mma, cudaFuncAttributeMaxDynamicSharedMemorySize, ATT_SMEM);
        attr_done = true;
    }

    // launches 0-2
    freq_kernel<<<(SEQ * HPAIR + 255) / 256, 256>>>();
    {
        dim3 blk(32, 8);
        transpose_half<<<dim3(QKVN / 32, KDIM / 32), blk>>>(Wqkv, (__half*)bq, KDIM, QKVN);
        transpose_half<<<dim3(DIN / 32, KDIM / 32), blk>>>(Wproj, (__half*)bp, KDIM, DIN);
    }

    // launches 3-4: convert x (two halves; keeps gemm_qkv at ncu -s 5)
    {
        int n4 = MROWS * KDIM / 4;
        int half = n4 / 2;
        convert_half<<<(half + 255) / 256, 256>>>(x, (__half*)ax, half);
        convert_half<<<(half + 255) / 256, 256>>>(x + (size_t)half * 4,
                                                  (__half*)ax + (size_t)half * 4, half);
    }

    // launch 5: GEMM1 (single-term A) + fused rope epilogue
    {
        dim3 grid(QKVN / 128, MROWS / 256);
        gemm_qkv<<<grid, 512, GEMM_SMEM>>>((const __half*)ax, (const __half*)bq,
                                           (__half*)qh, (__half*)ql, (__half*)kh, (__half*)vth);
    }

    // attention -> single fp16 output into GEMM2's A buffer
    {
        dim3 grid(SEQ / 128, NHEAD, BATCH);
        attn_mma<<<grid, 256, ATT_SMEM>>>(
            (const __half*)qh, (const __half*)ql,
            (const __half*)kh, (const __half*)vth,
            (__half*)ax);
    }

    // GEMM2: out = att @ Wproj
    {
        dim3 grid(DIN / 128, MROWS / 256);
        gemm_out<<<grid, 512, GEMM_SMEM>>>((const __half*)ax, (const __half*)bp, out, DIN);
    }
}

// round 11
// speedup vs baseline: 7.1337x; 1.1035x over previous
#include <cuda_runtime.h>
#include <cuda_fp16.h>
#include <math.h>
#include <stdint.h>

#define BATCH 2
#define SEQ   2048
#define DIN   2048
#define NHEAD 16
#define HDIM  128
#define HPAIR (HDIM/2)
#define MROWS (BATCH*SEQ)       // 4096
#define QKVN  (3*DIN)           // 6144
#define KDIM  2048

// ---------------- scratch (device globals; no allocs allowed) ----------------
__device__ float g_cos[SEQ * HPAIR];
__device__ float g_sin[SEQ * HPAIR];

// fp16 operand buffers
__device__ __align__(128) __half g_ax[(size_t)MROWS * KDIM];    // x fp16; later attention out
__device__ __align__(128) __half g_bqkv[(size_t)QKVN * KDIM];   // Wqkv^T [6144][2048]
__device__ __align__(128) __half g_bproj[(size_t)DIN * KDIM];   // Wproj^T [2048][2048]

// attention operands (rope applied, written by GEMM1 epilogue) — all single fp16
__device__ __align__(128) __half g_Qh[(size_t)BATCH*NHEAD*SEQ*HDIM];
__device__ __align__(128) __half g_Kh[(size_t)BATCH*NHEAD*SEQ*HDIM];
__device__ __align__(128) __half g_Vth[(size_t)BATCH*NHEAD*HDIM*SEQ];  // [b,h,d,s]

// ---------------- PTX helpers (all base-ISA, no 'a' features) ----------------
__device__ __forceinline__ uint32_t smem_u32(const void* p) {
    uint32_t a;
    asm("{ .reg .u64 t; cvta.to.shared.u64 t, %1; cvt.u32.u64 %0, t; }" : "=r"(a) : "l"(p));
    return a;
}
__device__ __forceinline__ void cpa16(uint32_t s, const void* g) {
    asm volatile("cp.async.cg.shared.global [%0], [%1], 16;" :: "r"(s), "l"(g));
}
#define CP_COMMIT() asm volatile("cp.async.commit_group;" ::: "memory")
#define CP_WAIT1()  asm volatile("cp.async.wait_group 1;" ::: "memory")
#define CP_WAIT0()  asm volatile("cp.async.wait_group 0;" ::: "memory")

__device__ __forceinline__ void ldsm4(uint32_t* r, uint32_t addr) {
    asm volatile("ldmatrix.sync.aligned.m8n8.x4.shared.b16 {%0,%1,%2,%3}, [%4];"
                 : "=r"(r[0]), "=r"(r[1]), "=r"(r[2]), "=r"(r[3]) : "r"(addr));
}
__device__ __forceinline__ void mma16816(float* c, const uint32_t* a, const uint32_t* b) {
    asm volatile(
        "mma.sync.aligned.m16n8k16.row.col.f32.f16.f16.f32 "
        "{%0,%1,%2,%3}, {%4,%5,%6,%7}, {%8,%9}, {%0,%1,%2,%3};"
        : "+f"(c[0]), "+f"(c[1]), "+f"(c[2]), "+f"(c[3])
        : "r"(a[0]), "r"(a[1]), "r"(a[2]), "r"(a[3]), "r"(b[0]), "r"(b[1]));
}
__device__ __forceinline__ float ex2f(float x) {
    float y;
    asm("ex2.approx.f32 %0, %1;" : "=f"(y) : "f"(x));
    return y;
}
__device__ __forceinline__ uint32_t pk2h(float a, float b) {
    __half2 t = __floats2half2_rn(a, b);
    return *(uint32_t*)&t;
}

// ============================================================================
// prep kernels
// ============================================================================
__global__ void freq_kernel() {
    int t = blockIdx.x * blockDim.x + threadIdx.x;
    if (t >= SEQ * HPAIR) return;
    int s = t >> 6;
    int p = t & 63;
    float inv = (float)(1.0 / pow(10000.0, (double)(2 * p) / (double)HDIM));
    float ang = (float)s * inv;
    float sn, cs;
    sincosf(ang, &sn, &cs);
    g_cos[t] = cs;
    g_sin[t] = sn;
}

// fp32 -> fp16 (same layout)
__global__ void convert_half(const float* __restrict__ src,
                             __half* __restrict__ dst, int n4) {
    int i = blockIdx.x * blockDim.x + threadIdx.x;
    if (i >= n4) return;
    float4 v = ((const float4*)src)[i];
    ((__half2*)dst)[2*i]   = __floats2half2_rn(v.x, v.y);
    ((__half2*)dst)[2*i+1] = __floats2half2_rn(v.z, v.w);
}

// transpose fp32 [K][N] -> fp16 single [N][K]
__global__ void transpose_half(const float* __restrict__ in,
                               __half* __restrict__ ot, int K, int N) {
    __shared__ float t[32][33];
    int n0 = blockIdx.x * 32, k0 = blockIdx.y * 32;
    int tx = threadIdx.x, ty = threadIdx.y;
    #pragma unroll
    for (int j = 0; j < 4; ++j)
        t[ty + j*8][tx] = in[(size_t)(k0 + ty + j*8) * N + n0 + tx];
    __syncthreads();
    #pragma unroll
    for (int j = 0; j < 4; ++j) {
        int n = ty + j*8;
        ot[(size_t)(n0 + n) * K + k0 + tx] = __float2half_rn(t[tx][n]);
    }
}

// ============================================================================
// Shared GEMM config: BM=256 BN=128 BK=32, 512 thr (16 warps, 64x32 per warp).
// A single fp16, B single fp16, 3-stage cp.async pipeline.
// ============================================================================
#define G2STR    80
#define GO_B     20480                  // A: 256*80
#define GO_STAGE 30720
#define GO_NST   3
#define GEMM_SMEM (GO_NST * GO_STAGE)   // 92160
#define KT_TOT (KDIM / 32)              // 64

// ---- GEMM1: qkv with fused rope epilogue ----
__global__ __launch_bounds__(512) void gemm_qkv(
    const __half* __restrict__ A, const __half* __restrict__ B,
    __half* __restrict__ Qh, __half* __restrict__ Kh, __half* __restrict__ Vth)
{
    extern __shared__ char smem_raw[];
    uint32_t sb = smem_u32(smem_raw);
    const int t = threadIdx.x, lane = t & 31, wid = t >> 5;
    const int m0 = blockIdx.y * 256, n0 = blockIdx.x * 128;
    const int mW = (wid & 3) * 64, nW = (wid >> 2) * 32;

    const int rL = t >> 2, ch = t & 3;
    const uint32_t soff = (uint32_t)rL * G2STR + ch * 16;
    const __half* gA = A + (size_t)(m0 + rL) * KDIM + ch * 8;
    const __half* gB = B + (size_t)(n0 + rL) * KDIM + ch * 8;

    float acc[4][4][4];
    #pragma unroll
    for (int i = 0; i < 4; ++i)
        #pragma unroll
        for (int j = 0; j < 4; ++j)
            #pragma unroll
            for (int q = 0; q < 4; ++q) acc[i][j][q] = 0.f;

    auto load_stage = [&](int slot, int kt) {
        uint32_t s = sb + slot * GO_STAGE + soff;
        int g = kt * 32;
        cpa16(s,                gA + g);
        cpa16(s + 128u * G2STR, gA + g + (size_t)128 * KDIM);
        cpa16(s + GO_B,         gB + g);
    };

    const uint32_t aLane = (uint32_t)(mW + (lane & 15)) * G2STR + ((lane >> 4) * 16);
    const uint32_t bLane = (uint32_t)(nW + (lane & 7) + ((lane >> 4) << 3)) * G2STR
                         + (((lane >> 3) & 1) * 16);

    auto compute_stage = [&](int slot) {
        uint32_t base = sb + slot * GO_STAGE;
        #pragma unroll
        for (int kk = 0; kk < 2; ++kk) {
            uint32_t koff = kk * 32;
            uint32_t aH[4][4];
            #pragma unroll
            for (int mt = 0; mt < 4; ++mt)
                ldsm4(aH[mt], base + aLane + mt * (16u * G2STR) + koff);
            #pragma unroll
            for (int p = 0; p < 2; ++p) {
                uint32_t rH[4];
                ldsm4(rH, base + GO_B + bLane + p * (16u * G2STR) + koff);
                #pragma unroll
                for (int mt = 0; mt < 4; ++mt) {
                    mma16816(acc[mt][2*p],   aH[mt], rH);
                    mma16816(acc[mt][2*p+1], aH[mt], rH + 2);
                }
            }
        }
    };

    load_stage(0, 0); CP_COMMIT();
    load_stage(1, 1); CP_COMMIT();
    #pragma unroll 1
    for (int kt = 0; kt < KT_TOT; ++kt) {
        CP_WAIT1();
        __syncthreads();
        if (kt + 2 < KT_TOT) load_stage((kt + 2) % GO_NST, kt + 2);
        CP_COMMIT();
        compute_stage(kt % GO_NST);
    }

    // epilogue: rope + fp16 write, region = q/k/v by column
    #pragma unroll
    for (int nt = 0; nt < 4; ++nt) {
        int c = n0 + nW + nt * 8 + (lane & 3) * 2;
        int region = c >> 11;          // 0=q 1=k 2=v (uniform per CTA)
        int hh = (c >> 7) & 15;
        int d  = c & 127;
        int p  = d >> 1;
        #pragma unroll
        for (int mt = 0; mt < 4; ++mt) {
            #pragma unroll
            for (int e = 0; e < 2; ++e) {
                int row = m0 + mW + mt * 16 + (lane >> 2) + e * 8;
                int bb = row >> 11, ss = row & 2047;
                float x1 = acc[mt][nt][2*e], x2 = acc[mt][nt][2*e+1];
                size_t hd = (size_t)(bb * NHEAD + hh) * SEQ + ss;
                if (region == 2) {
                    size_t vb = (size_t)(bb * NHEAD + hh) * HDIM;
                    Vth[(vb + d)     * SEQ + ss] = __float2half_rn(x1);
                    Vth[(vb + d + 1) * SEQ + ss] = __float2half_rn(x2);
                } else {
                    float cs = g_cos[ss * HPAIR + p], sn = g_sin[ss * HPAIR + p];
                    float o1 = x1 * cs - x2 * sn;
                    float o2 = x1 * sn + x2 * cs;
                    __half* dst = (region == 0) ? Qh : Kh;
                    *(__half2*)(dst + hd * HDIM + d) = __floats2half2_rn(o1, o2);
                }
            }
        }
    }
}

// ---- GEMM2: out (fp32 C) ----
__global__ __launch_bounds__(512) void gemm_out(
    const __half* __restrict__ A, const __half* __restrict__ B,
    float* __restrict__ C, int Ntot)
{
    extern __shared__ char smem_raw[];
    uint32_t sb = smem_u32(smem_raw);
    const int t = threadIdx.x, lane = t & 31, wid = t >> 5;
    const int m0 = blockIdx.y * 256, n0 = blockIdx.x * 128;
    const int mW = (wid & 3) * 64, nW = (wid >> 2) * 32;

    const int rL = t >> 2, ch = t & 3;
    const uint32_t soff = (uint32_t)rL * G2STR + ch * 16;
    const __half* gA = A + (size_t)(m0 + rL) * KDIM + ch * 8;
    const __half* gB = B + (size_t)(n0 + rL) * KDIM + ch * 8;

    float acc[4][4][4];
    #pragma unroll
    for (int i = 0; i < 4; ++i)
        #pragma unroll
        for (int j = 0; j < 4; ++j)
            #pragma unroll
            for (int q = 0; q < 4; ++q) acc[i][j][q] = 0.f;

    auto load_stage = [&](int slot, int kt) {
        uint32_t s = sb + slot * GO_STAGE + soff;
        int g = kt * 32;
        cpa16(s,                gA + g);
        cpa16(s + 128u * G2STR, gA + g + (size_t)128 * KDIM);
        cpa16(s + GO_B,         gB + g);
    };

    const uint32_t aLane = (uint32_t)(mW + (lane & 15)) * G2STR + ((lane >> 4) * 16);
    const uint32_t bLane = (uint32_t)(nW + (lane & 7) + ((lane >> 4) << 3)) * G2STR
                         + (((lane >> 3) & 1) * 16);

    auto compute_stage = [&](int slot) {
        uint32_t base = sb + slot * GO_STAGE;
        #pragma unroll
        for (int kk = 0; kk < 2; ++kk) {
            uint32_t koff = kk * 32;
            uint32_t aH[4][4];
            #pragma unroll
            for (int mt = 0; mt < 4; ++mt)
                ldsm4(aH[mt], base + aLane + mt * (16u * G2STR) + koff);
            #pragma unroll
            for (int p = 0; p < 2; ++p) {
                uint32_t rH[4];
                ldsm4(rH, base + GO_B + bLane + p * (16u * G2STR) + koff);
                #pragma unroll
                for (int mt = 0; mt < 4; ++mt) {
                    mma16816(acc[mt][2*p],   aH[mt], rH);
                    mma16816(acc[mt][2*p+1], aH[mt], rH + 2);
                }
            }
        }
    };

    load_stage(0, 0); CP_COMMIT();
    load_stage(1, 1); CP_COMMIT();
    #pragma unroll 1
    for (int kt = 0; kt < KT_TOT; ++kt) {
        CP_WAIT1();
        __syncthreads();
        if (kt + 2 < KT_TOT) load_stage((kt + 2) % GO_NST, kt + 2);
        CP_COMMIT();
        compute_stage(kt % GO_NST);
    }

    #pragma unroll
    for (int mt = 0; mt < 4; ++mt)
        #pragma unroll
        for (int nt = 0; nt < 4; ++nt) {
            int r = m0 + mW + mt * 16 + (lane >> 2);
            int c = n0 + nW + nt * 8 + (lane & 3) * 2;
            *(float2*)(C + (size_t)r * Ntot + c)       = make_float2(acc[mt][nt][0], acc[mt][nt][1]);
            *(float2*)(C + (size_t)(r + 8) * Ntot + c) = make_float2(acc[mt][nt][2], acc[mt][nt][3]);
        }
}

// ============================================================================
// HMMA flash attention fp16 1-term (Q, K, P, V all single fp16).
// 128q x 64k tiles, 8 warps x 16 q-rows, double-buffered K/V.
// ============================================================================
#define AQSTR   272
#define AVSTR   144
#define AQ_B    (128 * AQSTR)          // Q single: 34816
#define AK_B    (64 * AQSTR)           // 17408
#define AV_B    (128 * AVSTR)          // 18432
#define ASTG_B  (AK_B + AV_B)          // 35840
#define ASTG0   AQ_B                   // 34816
#define ATT_SMEM (ASTG0 + 2 * ASTG_B)  // 106496

__global__ __launch_bounds__(256, 1) void attn_mma(
    const __half* __restrict__ Qh, const __half* __restrict__ Kh,
    const __half* __restrict__ Vth, __half* __restrict__ O)
{
    extern __shared__ char smr[];
    uint32_t sb = smem_u32(smr);
    const int qt = (gridDim.x - 1) - blockIdx.x;
    const int h = blockIdx.y, b = blockIdx.z;
    const int t = threadIdx.x, lane = t & 31, wid = t >> 5;
    const int bh = b * NHEAD + h;
    const size_t headQK = (size_t)bh * SEQ * HDIM;
    const size_t headV  = (size_t)bh * HDIM * SEQ;
    const float SC2 = 0.08838834764831845f * 1.4426950408889634f;

    // Q resident (single)
    #pragma unroll
    for (int i = 0; i < 8; ++i) {
        int idx = t + i * 256;
        int r = idx >> 4, c = idx & 15;
        cpa16(sb + (uint32_t)r * AQSTR + c * 16,
              Qh + headQK + (size_t)(qt * 128 + r) * HDIM + c * 8);
    }

    auto load_kv = [&](int slot, int kt) {
        uint32_t st = sb + ASTG0 + slot * ASTG_B;
        #pragma unroll
        for (int i = 0; i < 4; ++i) {           // K: 64 rows x 16 chunks
            int idx = t + i * 256;
            int r = idx >> 4, c = idx & 15;
            cpa16(st + (uint32_t)r * AQSTR + c * 16,
                  Kh + headQK + (size_t)(kt * 64 + r) * HDIM + c * 8);
        }
        #pragma unroll
        for (int i = 0; i < 4; ++i) {           // Vt: 128 rows x 8 chunks
            int idx = t + i * 256;
            int r = idx >> 3, c = idx & 7;
            cpa16(st + AK_B + (uint32_t)r * AVSTR + c * 16,
                  Vth + headV + (size_t)r * SEQ + kt * 64 + c * 8);
        }
    };

    const uint32_t aLane  = (uint32_t)(wid * 16 + (lane & 15)) * AQSTR + ((lane >> 4) * 16);
    const uint32_t bLaneK = (uint32_t)((lane & 7) + ((lane >> 4) << 3)) * AQSTR
                          + (((lane >> 3) & 1) * 16);
    const uint32_t bLaneV = (uint32_t)((lane & 7) + ((lane >> 4) << 3)) * AVSTR
                          + (((lane >> 3) & 1) * 16);

    float oacc[16][4];
    #pragma unroll
    for (int i = 0; i < 16; ++i)
        #pragma unroll
        for (int j = 0; j < 4; ++j) oacc[i][j] = 0.f;
    float mrow0 = -1e30f, mrow1 = -1e30f, lrow0 = 0.f, lrow1 = 0.f;

    const int last = 2 * qt + 1;
    load_kv(0, 0); CP_COMMIT();

    #pragma unroll 1
    for (int kt = 0; kt <= last; ++kt) {
        if (kt < last) { load_kv((kt + 1) & 1, kt + 1); CP_COMMIT(); CP_WAIT1(); }
        else           { CP_WAIT0(); }
        __syncthreads();
        uint32_t st = sb + ASTG0 + (kt & 1) * ASTG_B;

        // S = Q K^T (1-term)
        float sacc[8][4];
        #pragma unroll
        for (int i = 0; i < 8; ++i)
            #pragma unroll
            for (int j = 0; j < 4; ++j) sacc[i][j] = 0.f;

        #pragma unroll
        for (int j = 0; j < 8; ++j) {
            uint32_t aH[4];
            ldsm4(aH, sb + aLane + j * 32);
            #pragma unroll
            for (int g = 0; g < 4; ++g) {
                uint32_t rH[4];
                ldsm4(rH, st + bLaneK + g * (16u * AQSTR) + j * 32);
                mma16816(sacc[2*g],   aH, rH);
                mma16816(sacc[2*g+1], aH, rH + 2);
            }
        }

        if (kt >= 2 * qt) {
            int qlo = qt * 128 + wid * 16 + (lane >> 2);
            int c0 = kt * 64 + (lane & 3) * 2;
            #pragma unroll
            for (int nt = 0; nt < 8; ++nt)
                #pragma unroll
                for (int e = 0; e < 2; ++e) {
                    int col = c0 + nt * 8 + e;
                    if (col > qlo)     sacc[nt][e]     = -1e30f;
                    if (col > qlo + 8) sacc[nt][2 + e] = -1e30f;
                }
        }

        float mx0 = -1e30f, mx1 = -1e30f;
        #pragma unroll
        for (int nt = 0; nt < 8; ++nt) {
            mx0 = fmaxf(mx0, fmaxf(sacc[nt][0], sacc[nt][1]));
            mx1 = fmaxf(mx1, fmaxf(sacc[nt][2], sacc[nt][3]));
        }
        mx0 = fmaxf(mx0, __shfl_xor_sync(0xffffffffu, mx0, 1));
        mx0 = fmaxf(mx0, __shfl_xor_sync(0xffffffffu, mx0, 2));
        mx1 = fmaxf(mx1, __shfl_xor_sync(0xffffffffu, mx1, 1));
        mx1 = fmaxf(mx1, __shfl_xor_sync(0xffffffffu, mx1, 2));
        float mn0 = fmaxf(mrow0, mx0), mn1 = fmaxf(mrow1, mx1);
        float corr0 = ex2f((mrow0 - mn0) * SC2);
        float corr1 = ex2f((mrow1 - mn1) * SC2);

        float sum0 = 0.f, sum1 = 0.f;
        #pragma unroll
        for (int nt = 0; nt < 8; ++nt) {
            float p0 = ex2f((sacc[nt][0] - mn0) * SC2);
            float p1 = ex2f((sacc[nt][1] - mn0) * SC2);
            float p2 = ex2f((sacc[nt][2] - mn1) * SC2);
            float p3 = ex2f((sacc[nt][3] - mn1) * SC2);
            sum0 += p0 + p1; sum1 += p2 + p3;
            sacc[nt][0] = p0; sacc[nt][1] = p1; sacc[nt][2] = p2; sacc[nt][3] = p3;
        }
        sum0 += __shfl_xor_sync(0xffffffffu, sum0, 1);
        sum0 += __shfl_xor_sync(0xffffffffu, sum0, 2);
        sum1 += __shfl_xor_sync(0xffffffffu, sum1, 1);
        sum1 += __shfl_xor_sync(0xffffffffu, sum1, 2);
        lrow0 = lrow0 * corr0 + sum0;
        lrow1 = lrow1 * corr1 + sum1;
        mrow0 = mn0; mrow1 = mn1;

        #pragma unroll
        for (int nt = 0; nt < 16; ++nt) {
            oacc[nt][0] *= corr0; oacc[nt][1] *= corr0;
            oacc[nt][2] *= corr1; oacc[nt][3] *= corr1;
        }

        // pack P into single fp16 A-fragments
        uint32_t pH[4][4];
        #pragma unroll
        for (int j = 0; j < 4; ++j) {
            #pragma unroll
            for (int half = 0; half < 2; ++half) {
                int nt = 2*j + half;
                pH[j][2*half]   = pk2h(sacc[nt][0], sacc[nt][1]);
                pH[j][2*half+1] = pk2h(sacc[nt][2], sacc[nt][3]);
            }
        }

        // O += P V (1-term)
        #pragma unroll
        for (int j = 0; j < 4; ++j) {
            uint32_t aH[4] = {pH[j][0], pH[j][1], pH[j][2], pH[j][3]};
            #pragma unroll
            for (int g = 0; g < 8; ++g) {
                uint32_t rH[4];
                ldsm4(rH, st + AK_B + bLaneV + g * (16u * AVSTR) + j * 32);
                mma16816(oacc[2*g],   aH, rH);
                mma16816(oacc[2*g+1], aH, rH + 2);
            }
        }
        __syncthreads();
    }

    float inv0 = 1.f / lrow0, inv1 = 1.f / lrow1;
    size_t row0 = (size_t)b * SEQ + qt * 128 + wid * 16 + (lane >> 2);
    int colb = h * HDIM + (lane & 3) * 2;
    #pragma unroll
    for (int nt = 0; nt < 16; ++nt) {
        size_t o0 = row0 * DIN + colb + nt * 8;
        size_t o1 = (row0 + 8) * DIN + colb + nt * 8;
        *(__half2*)(O + o0) = __floats2half2_rn(oacc[nt][0] * inv0, oacc[nt][1] * inv0);
        *(__half2*)(O + o1) = __floats2half2_rn(oacc[nt][2] * inv1, oacc[nt][3] * inv1);
    }
}

// ============================================================================
// launch
// ============================================================================
extern "C" void kernel_launch(void* const* d_in, const int* in_sizes, int n_in,
                              void* d_out, int out_size)
{
    const float* x     = (const float*)d_in[0];
    const float* Wqkv  = (const float*)d_in[1];
    const float* Wproj = (const float*)d_in[2];
    float* out = (float*)d_out;

    void *ax, *bq, *bp, *qh, *kh, *vth;
    cudaGetSymbolAddress(&ax, g_ax);
    cudaGetSymbolAddress(&bq, g_bqkv);
    cudaGetSymbolAddress(&bp, g_bproj);
    cudaGetSymbolAddress(&qh, g_Qh);
    cudaGetSymbolAddress(&kh, g_Kh);
    cudaGetSymbolAddress(&vth, g_Vth);

    static bool attr_done = false;
    if (!attr_done) {
        cudaFuncSetAttribute(gemm_qkv, cudaFuncAttributeMaxDynamicSharedMemorySize, GEMM_SMEM);
        cudaFuncSetAttribute(gemm_out, cudaFuncAttributeMaxDynamicSharedMemorySize, GEMM_SMEM);
        cudaFuncSetAttribute(attn_mma, cudaFuncAttributeMaxDynamicSharedMemorySize, ATT_SMEM);
        attr_done = true;
    }

    // launches 0-2
    freq_kernel<<<(SEQ * HPAIR + 255) / 256, 256>>>();
    {
        dim3 blk(32, 8);
        transpose_half<<<dim3(QKVN / 32, KDIM / 32), blk>>>(Wqkv, (__half*)bq, KDIM, QKVN);
        transpose_half<<<dim3(DIN / 32, KDIM / 32), blk>>>(Wproj, (__half*)bp, KDIM, DIN);
    }

    // launches 3-4: convert x (two halves; keeps gemm_qkv at ncu -s 5)
    {
        int n4 = MROWS * KDIM / 4;
        int half = n4 / 2;
        convert_half<<<(half + 255) / 256, 256>>>(x, (__half*)ax, half);
        convert_half<<<(half + 255) / 256, 256>>>(x + (size_t)half * 4,
                                                  (__half*)ax + (size_t)half * 4, half);
    }

    // launch 5: GEMM1 (single-term A) + fused rope epilogue
    {
        dim3 grid(QKVN / 128, MROWS / 256);
        gemm_qkv<<<grid, 512, GEMM_SMEM>>>((const __half*)ax, (const __half*)bq,
                                           (__half*)qh, (__half*)kh, (__half*)vth);
    }

    // attention (1-term fp16) -> output into GEMM2's A buffer
    {
        dim3 grid(SEQ / 128, NHEAD, BATCH);
        attn_mma<<<grid, 256, ATT_SMEM>>>(
            (const __half*)qh, (const __half*)kh, (const __half*)vth, (__half*)ax);
    }

    // GEMM2: out = att @ Wproj
    {
        dim3 grid(DIN / 128, MROWS / 256);
        gemm_out<<<grid, 512, GEMM_SMEM>>>((const __half*)ax, (const __half*)bp, out, DIN);
    }
}